// round 2
// baseline (speedup 1.0000x reference)
#include <cuda_runtime.h>
#include <cstdint>
#include <math.h>

// ---------------- problem constants ----------------
#define Bb 2
#define Rr 4096
#define Ss 48
#define Cc 32
#define Hh 256
#define NRAY   (Bb*Rr)        // 8192
#define NSAMP  (NRAY*Ss)      // 393216

#define RAY_START 2.25f
#define STEPF 0.0223404255319148936f  // (3.3-2.25)/47

// output layout (flatten+concat of return tuple)
#define OUT_RGB   0
#define OUT_DEPTH 262144
#define OUT_WT    270336
#define OUT_XYZ   278528

// ---------------- scratch (static device memory; no allocs) ----------------
__device__ float g_planes[(size_t)Bb*3*Hh*Hh*64];   // [b][p][y][x][c64] front(0..31)|back(32..63)
__device__ float g_depth_c[NSAMP];
__device__ float g_depth_f[NSAMP];
__device__ float g_col_c[(size_t)NSAMP*32];
__device__ float g_col_f[(size_t)NSAMP*32];
__device__ float g_sig_c[NSAMP];
__device__ float g_sig_f[NSAMP];
__device__ float g_wc[NRAY*47];
__device__ int   g_dmin_bits;
__device__ int   g_dmax_bits;

// ---------------- math helpers ----------------
__device__ __forceinline__ float softplusf(float x) {
    return fmaxf(x, 0.0f) + log1pf(expf(-fabsf(x)));
}
__device__ __forceinline__ float sigmoidf(float x) {
    return 1.0f / (1.0f + expf(-x));
}

// ---------------- Threefry-2x32 (JAX, partitionable variant) ----------------
__device__ __forceinline__ uint32_t rotl32(uint32_t x, int r) {
    return (x << r) | (x >> (32 - r));
}
__device__ __forceinline__ void tf2x32(uint32_t k0, uint32_t k1,
                                       uint32_t x0, uint32_t x1,
                                       uint32_t& o0, uint32_t& o1) {
    uint32_t ks2 = k0 ^ k1 ^ 0x1BD11BDAu;
    x0 += k0; x1 += k1;
#define TFR(r) { x0 += x1; x1 = rotl32(x1, r); x1 ^= x0; }
    TFR(13) TFR(15) TFR(26) TFR(6)  x0 += k1;  x1 += ks2 + 1u;
    TFR(17) TFR(29) TFR(16) TFR(24) x0 += ks2; x1 += k0 + 2u;
    TFR(13) TFR(15) TFR(26) TFR(6)  x0 += k0;  x1 += k1 + 3u;
    TFR(17) TFR(29) TFR(16) TFR(24) x0 += k1;  x1 += ks2 + 4u;
    TFR(13) TFR(15) TFR(26) TFR(6)  x0 += ks2; x1 += k0 + 5u;
#undef TFR
    o0 = x0; o1 = x1;
}
// derived key i from master key(42): cipher((0,42),(0,i)) -> both words
__device__ __forceinline__ void derive_key(uint32_t idx, uint32_t& ka, uint32_t& kb) {
    tf2x32(0u, 42u, 0u, idx, ka, kb);
}
// uniform[0,1): bits = o0^o1 of cipher(key,(0,i)); (bits>>9)|0x3f800000 - 1
__device__ __forceinline__ float tf_uniform(uint32_t ka, uint32_t kb, uint32_t i) {
    uint32_t o0, o1;
    tf2x32(ka, kb, 0u, i, o0, o1);
    uint32_t bits = o0 ^ o1;
    float f = __uint_as_float((bits >> 9) | 0x3f800000u) - 1.0f;
    return fmaxf(f, 0.0f);
}

// ---------------- kernel 0: init min/max scalars ----------------
__global__ void k_init() {
    g_dmin_bits = 0x7f800000;   // +inf
    g_dmax_bits = 0x00000000;   // 0 (depths > 0)
}

// ---------------- kernel 1: plane transpose to channel-last ----------------
__global__ void k_transpose(const float* __restrict__ front, const float* __restrict__ back) {
    __shared__ float tile[32][33];
    int z  = blockIdx.z;          // 0..11 : (b*3+p)*2 + src
    int src = z & 1;
    int bp  = z >> 1;             // b*3+p in 0..5
    int y   = blockIdx.y;
    int x0  = blockIdx.x * 32;
    int tx = threadIdx.x, ty = threadIdx.y;
    const float* in = src ? back : front;
    int off = src ? 32 : 0;
#pragma unroll
    for (int i = 0; i < 4; i++) {
        int c = ty + i * 8;
        tile[c][tx] = in[((size_t)(bp * 32 + c) * 65536) + (size_t)y * 256 + x0 + tx];
    }
    __syncthreads();
#pragma unroll
    for (int i = 0; i < 4; i++) {
        int xx = ty + i * 8;
        g_planes[(((size_t)bp * 65536) + (size_t)y * 256 + x0 + xx) * 64 + off + tx] = tile[tx][xx];
    }
}

// ---------------- kernel 2: coarse stratified depths ----------------
__global__ void k_depth_coarse() {
    int i = blockIdx.x * blockDim.x + threadIdx.x;
    if (i >= NSAMP) return;
    uint32_t ka, kb; derive_key(0u, ka, kb);     // k1 = split(key)[0]
    float u = tf_uniform(ka, kb, (uint32_t)i);
    int s = i % Ss;
    float d0 = RAY_START + (float)s * STEPF;
    g_depth_c[i] = d0 + u * STEPF;
}

// ---------------- kernel 3: global depth min/max ----------------
__global__ void k_minmax() {
    int ray = blockIdx.x * blockDim.x + threadIdx.x;   // 8192 threads exactly
    float dmin = g_depth_c[ray * Ss];
    float dmax = g_depth_c[ray * Ss + Ss - 1];
#pragma unroll
    for (int off = 16; off; off >>= 1) {
        dmin = fminf(dmin, __shfl_xor_sync(0xffffffffu, dmin, off));
        dmax = fmaxf(dmax, __shfl_xor_sync(0xffffffffu, dmax, off));
    }
    if ((threadIdx.x & 31) == 0) {
        atomicMin(&g_dmin_bits, __float_as_int(dmin));
        atomicMax(&g_dmax_bits, __float_as_int(dmax));
    }
}

// ---------------- kernel 4: model (plane sample + MLP), warp per sample ----------------
__global__ void __launch_bounds__(128) k_model(
    const float* __restrict__ ro, const float* __restrict__ rd,
    const float* __restrict__ weight,
    const float* __restrict__ w1, const float* __restrict__ b1,
    const float* __restrict__ w2, const float* __restrict__ b2,
    int fine_pass)
{
    __shared__ __align__(16) float w1s[96 * 64];
    __shared__ __align__(16) float w2s[64 * 33];
    __shared__ __align__(16) float b1s[64];
    __shared__ __align__(16) float b2s[36];
    __shared__ __align__(16) float wsig[96];
    __shared__ __align__(16) float xs[4][96];
    __shared__ __align__(16) float hs[4][64];

    int tid = threadIdx.x;
    for (int i = tid; i < 96 * 64; i += 128) w1s[i] = w1[i];
    for (int i = tid; i < 64 * 33; i += 128) w2s[i] = w2[i];
    if (tid < 64) b1s[tid] = b1[tid];
    if (tid < 33) b2s[tid] = b2[tid];
    if (tid < 96) wsig[tid] = sigmoidf(weight[tid]);
    __syncthreads();

    const float* depths = fine_pass ? g_depth_f : g_depth_c;
    float* cols = fine_pass ? g_col_f : g_col_c;
    float* sigs = fine_pass ? g_sig_f : g_sig_c;

    int lane = tid & 31, wrp = tid >> 5;
    int warpG = blockIdx.x * 4 + wrp;
    int nWarps = gridDim.x * 4;

    for (int smp = warpG; smp < NSAMP; smp += nWarps) {
        int ray = smp / Ss;
        int b = ray >> 12;
        float ox = ro[ray * 3 + 0], oy = ro[ray * 3 + 1], oz = ro[ray * 3 + 2];
        float dx = rd[ray * 3 + 0], dy = rd[ray * 3 + 1], dz = rd[ray * 3 + 2];
        float d = depths[smp];
        float cx = 2.0f * fmaf(d, dx, ox);
        float cy = 2.0f * fmaf(d, dy, oy);
        float cz = 2.0f * fmaf(d, dz, oz);
        // plane projections: p0 (cx,cy), p1 (cx,cz), p2 (cz,cx)
        float gxs[3] = {cx, cx, cz};
        float gys[3] = {cy, cz, cx};
#pragma unroll
        for (int p = 0; p < 3; p++) {
            float x = (gxs[p] + 1.0f) * 128.0f - 0.5f;
            float y = (gys[p] + 1.0f) * 128.0f - 0.5f;
            float x0f = floorf(x), y0f = floorf(y);
            int x0 = (int)x0f, y0 = (int)y0f;
            float wx = x - x0f, wy = y - y0f;
            float accF = 0.0f, accB = 0.0f;
            const float* base = g_planes + (size_t)(b * 3 + p) * 65536 * 64;
#pragma unroll
            for (int t = 0; t < 4; t++) {
                int ix = x0 + (t & 1), iy = y0 + (t >> 1);
                if (ix >= 0 && ix < 256 && iy >= 0 && iy < 256) {
                    float wt = ((t & 1) ? wx : 1.0f - wx) * ((t >> 1) ? wy : 1.0f - wy);
                    const float* pp = base + ((size_t)iy * 256 + ix) * 64;
                    accF = fmaf(wt, pp[lane], accF);
                    accB = fmaf(wt, pp[lane + 32], accB);
                }
            }
            float wk = wsig[p * 32 + lane];
            xs[wrp][p * 32 + lane] = wk * accF + (1.0f - wk) * accB;
        }
        __syncwarp();
        // layer1: 96 -> 64
        float h0 = b1s[lane], h1 = b1s[lane + 32];
        const float4* x4 = reinterpret_cast<const float4*>(xs[wrp]);
#pragma unroll
        for (int k4 = 0; k4 < 24; k4++) {
            float4 v = x4[k4];
            int k = k4 * 4;
            h0 = fmaf(v.x, w1s[(k + 0) * 64 + lane], h0); h1 = fmaf(v.x, w1s[(k + 0) * 64 + 32 + lane], h1);
            h0 = fmaf(v.y, w1s[(k + 1) * 64 + lane], h0); h1 = fmaf(v.y, w1s[(k + 1) * 64 + 32 + lane], h1);
            h0 = fmaf(v.z, w1s[(k + 2) * 64 + lane], h0); h1 = fmaf(v.z, w1s[(k + 2) * 64 + 32 + lane], h1);
            h0 = fmaf(v.w, w1s[(k + 3) * 64 + lane], h0); h1 = fmaf(v.w, w1s[(k + 3) * 64 + 32 + lane], h1);
        }
        h0 = softplusf(h0); h1 = softplusf(h1);
        hs[wrp][lane] = h0; hs[wrp][lane + 32] = h1;
        __syncwarp();
        // layer2: 64 -> 33 (lane j computes o[j+1]; sigma o[0] redundantly on all lanes)
        float orgb = b2s[lane + 1];
        float osig = b2s[0];
        const float4* h4 = reinterpret_cast<const float4*>(hs[wrp]);
#pragma unroll
        for (int k4 = 0; k4 < 16; k4++) {
            float4 v = h4[k4];
            int k = k4 * 4;
            orgb = fmaf(v.x, w2s[(k + 0) * 33 + lane + 1], orgb); osig = fmaf(v.x, w2s[(k + 0) * 33], osig);
            orgb = fmaf(v.y, w2s[(k + 1) * 33 + lane + 1], orgb); osig = fmaf(v.y, w2s[(k + 1) * 33], osig);
            orgb = fmaf(v.z, w2s[(k + 2) * 33 + lane + 1], orgb); osig = fmaf(v.z, w2s[(k + 2) * 33], osig);
            orgb = fmaf(v.w, w2s[(k + 3) * 33 + lane + 1], orgb); osig = fmaf(v.w, w2s[(k + 3) * 33], osig);
        }
        cols[(size_t)smp * 32 + lane] = sigmoidf(orgb) * 1.002f - 0.001f;
        if (lane == 0) sigs[smp] = osig;
        __syncwarp();
    }
}

// ---------------- kernel 5: coarse ray-march weights ----------------
__global__ void k_coarse_weights() {
    int ray = blockIdx.x * blockDim.x + threadIdx.x;
    if (ray >= NRAY) return;
    float T = 1.0f;
    float zp = g_depth_c[ray * Ss];
    float sp = g_sig_c[ray * Ss];
    for (int s = 1; s < Ss; s++) {
        float z = g_depth_c[ray * Ss + s];
        float sg = g_sig_c[ray * Ss + s];
        float dens = softplusf(0.5f * (sp + sg) - 1.0f);
        float alpha = 1.0f - expf(-dens * (z - zp));
        g_wc[ray * 47 + s - 1] = alpha * T;
        T *= (1.0f - alpha + 1e-10f);
        zp = z; sp = sg;
    }
}

// ---------------- kernel 6: importance sampling (fine depths) ----------------
__global__ void k_fine_depths() {
    int ray = blockIdx.x * blockDim.x + threadIdx.x;
    if (ray >= NRAY) return;
    float z[48], w[47];
    for (int i = 0; i < 48; i++) z[i] = g_depth_c[ray * Ss + i];
    for (int i = 0; i < 47; i++) w[i] = g_wc[ray * 47 + i];
    float zm[47];
    for (int i = 0; i < 47; i++) zm[i] = 0.5f * (z[i] + z[i + 1]);
    float wa[47];
    for (int i = 0; i < 47; i++) {
        float wmi  = (i == 0)  ? w[0]  : fmaxf(w[i - 1], w[i]);
        float wmi1 = (i == 46) ? w[46] : fmaxf(w[i], w[i + 1]);
        wa[i] = 0.5f * (wmi + wmi1) + 0.01f;
    }
    float ws[45];
    float sum = 0.0f;
    for (int j = 0; j < 45; j++) { ws[j] = wa[j + 1] + 1e-5f; sum += ws[j]; }
    float cdf[46];
    cdf[0] = 0.0f;
    for (int j = 0; j < 45; j++) cdf[j + 1] = cdf[j] + ws[j] / sum;

    uint32_t ka, kb; derive_key(1u, ka, kb);   // k2 = split(key)[1]
    for (int j = 0; j < 48; j++) {
        float u = tf_uniform(ka, kb, (uint32_t)(ray * 48 + j));
        int ind = 0;
        for (int k = 0; k < 46; k++) ind += (cdf[k] <= u) ? 1 : 0;  // searchsorted right
        int below = ind - 1; if (below < 0) below = 0;
        int above = ind;     if (above > 45) above = 45;
        float c0 = cdf[below], c1 = cdf[above];
        float b0 = zm[below],  b1v = zm[above];
        float denom = c1 - c0;
        if (denom < 1e-5f) denom = 1.0f;
        g_depth_f[ray * 48 + j] = b0 + (u - c0) / denom * (b1v - b0);
    }
}

// ---------------- kernel 7: unify + final march, warp per ray ----------------
__global__ void __launch_bounds__(256) k_final(
    const float* __restrict__ ro, const float* __restrict__ rd,
    float* __restrict__ out)
{
    __shared__ __align__(16) float sd[8][96];
    __shared__ __align__(16) float ssg[8][96];
    __shared__ __align__(16) int   sidx[8][96];
    int lane = threadIdx.x & 31, wrp = threadIdx.x >> 5;
    int ray = blockIdx.x * 8 + wrp;

    for (int i = lane; i < 48; i += 32) {
        sd[wrp][i]       = g_depth_c[ray * 48 + i];
        sd[wrp][48 + i]  = g_depth_f[ray * 48 + i];
        ssg[wrp][i]      = g_sig_c[ray * 48 + i];
        ssg[wrp][48 + i] = g_sig_f[ray * 48 + i];
    }
    __syncwarp();
    // stable rank sort (matches stable argsort of [coarse, fine])
#pragma unroll
    for (int t = 0; t < 3; t++) {
        int e = lane + t * 32;
        float de = sd[wrp][e];
        int rank = 0;
        for (int j = 0; j < 96; j++) {
            float dj = sd[wrp][j];
            rank += (dj < de || (dj == de && j < e)) ? 1 : 0;
        }
        sidx[wrp][rank] = e;
    }
    __syncwarp();

    float T = 1.0f, accW = 0.0f, accWD = 0.0f, accC = 0.0f;
    int i0 = sidx[wrp][0];
    float dp = sd[wrp][i0], sp = ssg[wrp][i0];
    const float* cb0 = (i0 < 48) ? g_col_c : g_col_f;
    float cp = cb0[((size_t)ray * 48 + (i0 < 48 ? i0 : i0 - 48)) * 32 + lane];

    for (int s = 1; s < 96; s++) {
        int i = sidx[wrp][s];
        float dc = sd[wrp][i], sc = ssg[wrp][i];
        const float* cb = (i < 48) ? g_col_c : g_col_f;
        float cc = cb[((size_t)ray * 48 + (i < 48 ? i : i - 48)) * 32 + lane];
        float delta = dc - dp;
        float dens = softplusf(0.5f * (sc + sp) - 1.0f);
        float alpha = 1.0f - expf(-dens * delta);
        float wgt = alpha * T;
        T *= (1.0f - alpha + 1e-10f);
        accC  += wgt * 0.5f * (cc + cp);
        accW  += wgt;
        accWD += wgt * 0.5f * (dc + dp);
        dp = dc; sp = sc; cp = cc;
    }

    out[OUT_RGB + (size_t)ray * 32 + lane] = accC * 2.0f - 1.0f;
    if (lane == 0) {
        float wt = accW;
        float dep = accWD / wt;
        if (isnan(dep)) dep = __int_as_float(0x7f800000);
        float dmin = __int_as_float(g_dmin_bits);
        float dmax = __int_as_float(g_dmax_bits);
        dep = fminf(fmaxf(dep, dmin), dmax);
        out[OUT_DEPTH + ray] = dep;
        out[OUT_WT + ray] = wt;
    }
    if (lane < 3) {
        float o_ = ro[ray * 3 + lane], d_ = rd[ray * 3 + lane];
        out[OUT_XYZ + (size_t)ray * 3 + lane] = 2.0f * (o_ * accW + d_ * accWD) - 1.0f;
    }
}

// ---------------- launcher ----------------
extern "C" void kernel_launch(void* const* d_in, const int* in_sizes, int n_in,
                              void* d_out, int out_size) {
    const float* front  = (const float*)d_in[0];
    const float* back   = (const float*)d_in[1];
    const float* ro     = (const float*)d_in[2];
    const float* rd     = (const float*)d_in[3];
    const float* weight = (const float*)d_in[4];
    const float* w1     = (const float*)d_in[5];
    const float* b1     = (const float*)d_in[6];
    const float* w2     = (const float*)d_in[7];
    const float* b2     = (const float*)d_in[8];
    float* out = (float*)d_out;

    k_init<<<1, 1>>>();
    k_transpose<<<dim3(8, 256, 12), dim3(32, 8)>>>(front, back);
    k_depth_coarse<<<(NSAMP + 255) / 256, 256>>>();
    k_minmax<<<NRAY / 256, 256>>>();
    k_model<<<2368, 128>>>(ro, rd, weight, w1, b1, w2, b2, 0);
    k_coarse_weights<<<NRAY / 256, 256>>>();
    k_fine_depths<<<NRAY / 256, 256>>>();
    k_model<<<2368, 128>>>(ro, rd, weight, w1, b1, w2, b2, 1);
    k_final<<<NRAY / 8, 256>>>(ro, rd, out);
    (void)in_sizes; (void)n_in; (void)out_size;
}

// round 3
// speedup vs baseline: 1.4938x; 1.4938x over previous
#include <cuda_runtime.h>
#include <cstdint>
#include <math.h>

// ---------------- problem constants ----------------
#define Bb 2
#define Rr 4096
#define Ss 48
#define NRAY   (Bb*Rr)        // 8192
#define NSAMP  (NRAY*Ss)      // 393216
#define NGROUP (NSAMP/8)      // 49152 (8 samples per warp-group; 8 | 48 so one ray per group)

#define RAY_START 2.25f
#define STEPF 0.0223404255319148936f  // (3.3-2.25)/47

// output layout (flatten+concat of return tuple)
#define OUT_RGB   0
#define OUT_DEPTH 262144
#define OUT_WT    270336
#define OUT_XYZ   278528

// ---------------- scratch (static device memory; no allocs) ----------------
// planes: [b][p][y][x][c*2 + {front,back}]  (float2 per channel)
__device__ float g_planes[(size_t)Bb*3*256*256*64];
__device__ float g_depth_c[NSAMP];
__device__ float g_depth_f[NSAMP];
__device__ float g_col_c[(size_t)NSAMP*32];
__device__ float g_col_f[(size_t)NSAMP*32];
__device__ float g_sig_c[NSAMP];
__device__ float g_sig_f[NSAMP];
__device__ float g_wc[NRAY*47];
__device__ int   g_dmin_bits;
__device__ int   g_dmax_bits;

// ---------------- math helpers ----------------
__device__ __forceinline__ float softplusf(float x) {
    return fmaxf(x, 0.0f) + log1pf(expf(-fabsf(x)));
}
__device__ __forceinline__ float sigmoidf(float x) {
    return 1.0f / (1.0f + expf(-x));
}

// ---------------- Threefry-2x32 (JAX, partitionable variant) ----------------
__device__ __forceinline__ uint32_t rotl32(uint32_t x, int r) {
    return (x << r) | (x >> (32 - r));
}
__device__ __forceinline__ void tf2x32(uint32_t k0, uint32_t k1,
                                       uint32_t x0, uint32_t x1,
                                       uint32_t& o0, uint32_t& o1) {
    uint32_t ks2 = k0 ^ k1 ^ 0x1BD11BDAu;
    x0 += k0; x1 += k1;
#define TFR(r) { x0 += x1; x1 = rotl32(x1, r); x1 ^= x0; }
    TFR(13) TFR(15) TFR(26) TFR(6)  x0 += k1;  x1 += ks2 + 1u;
    TFR(17) TFR(29) TFR(16) TFR(24) x0 += ks2; x1 += k0 + 2u;
    TFR(13) TFR(15) TFR(26) TFR(6)  x0 += k0;  x1 += k1 + 3u;
    TFR(17) TFR(29) TFR(16) TFR(24) x0 += k1;  x1 += ks2 + 4u;
    TFR(13) TFR(15) TFR(26) TFR(6)  x0 += ks2; x1 += k0 + 5u;
#undef TFR
    o0 = x0; o1 = x1;
}
__device__ __forceinline__ void derive_key(uint32_t idx, uint32_t& ka, uint32_t& kb) {
    tf2x32(0u, 42u, 0u, idx, ka, kb);
}
__device__ __forceinline__ float tf_uniform(uint32_t ka, uint32_t kb, uint32_t i) {
    uint32_t o0, o1;
    tf2x32(ka, kb, 0u, i, o0, o1);
    uint32_t bits = o0 ^ o1;
    float f = __uint_as_float((bits >> 9) | 0x3f800000u) - 1.0f;
    return fmaxf(f, 0.0f);
}

// ---------------- kernel 0: init min/max scalars ----------------
__global__ void k_init() {
    g_dmin_bits = 0x7f800000;
    g_dmax_bits = 0x00000000;
}

// ---------------- kernel 1: plane transpose to channel-last (front/back interleaved) ----------------
__global__ void k_transpose(const float* __restrict__ front, const float* __restrict__ back) {
    __shared__ float tile[32][33];
    int z  = blockIdx.z;          // 0..11 : (b*3+p)*2 + src
    int src = z & 1;
    int bp  = z >> 1;             // b*3+p in 0..5
    int y   = blockIdx.y;
    int x0  = blockIdx.x * 32;
    int tx = threadIdx.x, ty = threadIdx.y;
    const float* in = src ? back : front;
#pragma unroll
    for (int i = 0; i < 4; i++) {
        int c = ty + i * 8;
        tile[c][tx] = in[((size_t)(bp * 32 + c) * 65536) + (size_t)y * 256 + x0 + tx];
    }
    __syncthreads();
#pragma unroll
    for (int i = 0; i < 4; i++) {
        int xx = ty + i * 8;
        g_planes[(((size_t)bp * 65536) + (size_t)y * 256 + x0 + xx) * 64 + tx * 2 + src] = tile[tx][xx];
    }
}

// ---------------- kernel 2: coarse stratified depths ----------------
__global__ void k_depth_coarse() {
    int i = blockIdx.x * blockDim.x + threadIdx.x;
    if (i >= NSAMP) return;
    uint32_t ka, kb; derive_key(0u, ka, kb);
    float u = tf_uniform(ka, kb, (uint32_t)i);
    int s = i % Ss;
    float d0 = RAY_START + (float)s * STEPF;
    g_depth_c[i] = d0 + u * STEPF;
}

// ---------------- kernel 3: global depth min/max ----------------
__global__ void k_minmax() {
    int ray = blockIdx.x * blockDim.x + threadIdx.x;
    float dmin = g_depth_c[ray * Ss];
    float dmax = g_depth_c[ray * Ss + Ss - 1];
#pragma unroll
    for (int off = 16; off; off >>= 1) {
        dmin = fminf(dmin, __shfl_xor_sync(0xffffffffu, dmin, off));
        dmax = fmaxf(dmax, __shfl_xor_sync(0xffffffffu, dmax, off));
    }
    if ((threadIdx.x & 31) == 0) {
        atomicMin(&g_dmin_bits, __float_as_int(dmin));
        atomicMax(&g_dmax_bits, __float_as_int(dmax));
    }
}

// ---------------- kernel 4: model, warp per 8-sample group ----------------
// dynamic smem layout (floats):
//   [0)        w1s : 96*64   = 6144
//   [6144)     w2s : 64*33   = 2112
//   [8256)     xs  : 8 warps * 8 samp * 96  = 6144
//   [14400)    hs  : 8 warps * 8 samp * 68  = 4352   (row pad 68 avoids bank conflicts)
//   [18752)    b1s : 64
//   [18816)    b2s : 48 (33 used)
//   [18864)    wsig: 96
// total 18960 floats = 75840 bytes
#define SM_W1   0
#define SM_W2   6144
#define SM_XS   8256
#define SM_HS   14400
#define SM_B1   18752
#define SM_B2   18816
#define SM_WSIG 18864
#define SM_TOTAL_BYTES (18960*4)

extern __shared__ __align__(16) float smem[];

__global__ void __launch_bounds__(256) k_model(
    const float* __restrict__ ro, const float* __restrict__ rd,
    const float* __restrict__ weight,
    const float* __restrict__ w1, const float* __restrict__ b1,
    const float* __restrict__ w2, const float* __restrict__ b2,
    int fine_pass)
{
    float* w1s  = smem + SM_W1;
    float* w2s  = smem + SM_W2;
    float* b1s  = smem + SM_B1;
    float* b2s  = smem + SM_B2;
    float* wsig = smem + SM_WSIG;

    int tid = threadIdx.x;
    for (int i = tid; i < 96 * 64; i += 256) w1s[i] = w1[i];
    for (int i = tid; i < 64 * 33; i += 256) w2s[i] = w2[i];
    if (tid < 64) b1s[tid] = b1[tid];
    if (tid < 33) b2s[tid] = b2[tid];
    if (tid < 96) wsig[tid] = sigmoidf(weight[tid]);
    __syncthreads();

    const float* depths = fine_pass ? g_depth_f : g_depth_c;
    float* cols = fine_pass ? g_col_f : g_col_c;
    float* sigs = fine_pass ? g_sig_f : g_sig_c;

    int lane = tid & 31, wrp = tid >> 5;
    float* xsw = smem + SM_XS + wrp * 768;   // 8 samples x 96
    float* hsw = smem + SM_HS + wrp * 544;   // 8 samples x 68 (64 used)

    int groupG = blockIdx.x * 8 + wrp;
    int nGroups = gridDim.x * 8;

    for (int g = groupG; g < NGROUP; g += nGroups) {
        int smp0 = g * 8;
        int ray = smp0 / Ss;          // whole group lies in one ray (8 | 48)
        int b = ray >> 12;
        float ox = ro[ray * 3 + 0], oy = ro[ray * 3 + 1], oz = ro[ray * 3 + 2];
        float dx = rd[ray * 3 + 0], dy = rd[ray * 3 + 1], dz = rd[ray * 3 + 2];
        const float2* pb = (const float2*)g_planes + (size_t)b * 3 * 65536 * 32;

        // ---- phase A: tri-plane gather, lane = channel ----
#pragma unroll
        for (int s = 0; s < 8; s++) {
            float d = depths[smp0 + s];
            float cx = 2.0f * fmaf(d, dx, ox);
            float cy = 2.0f * fmaf(d, dy, oy);
            float cz = 2.0f * fmaf(d, dz, oz);
            float gxs[3] = {cx, cx, cz};
            float gys[3] = {cy, cz, cx};
#pragma unroll
            for (int p = 0; p < 3; p++) {
                float x = (gxs[p] + 1.0f) * 128.0f - 0.5f;
                float y = (gys[p] + 1.0f) * 128.0f - 0.5f;
                float x0f = floorf(x), y0f = floorf(y);
                int x0 = (int)x0f, y0 = (int)y0f;
                float wx = x - x0f, wy = y - y0f;
                float accF = 0.0f, accB = 0.0f;
                const float2* base = pb + (size_t)p * 65536 * 32;
#pragma unroll
                for (int t = 0; t < 4; t++) {
                    int ix = x0 + (t & 1), iy = y0 + (t >> 1);
                    if (ix >= 0 && ix < 256 && iy >= 0 && iy < 256) {
                        float wt = ((t & 1) ? wx : 1.0f - wx) * ((t >> 1) ? wy : 1.0f - wy);
                        float2 v = base[((size_t)iy * 256 + ix) * 32 + lane];
                        accF = fmaf(wt, v.x, accF);
                        accB = fmaf(wt, v.y, accB);
                    }
                }
                float wk = wsig[p * 32 + lane];
                xsw[s * 96 + p * 32 + lane] = wk * accF + (1.0f - wk) * accB;
            }
        }
        __syncwarp();

        // ---- phase B: layer1 96->64, batched over 8 samples ----
        float h0[8], h1[8];
#pragma unroll
        for (int s = 0; s < 8; s++) { h0[s] = b1s[lane]; h1[s] = b1s[lane + 32]; }
        const float4* xs4 = (const float4*)xsw;  // row stride 24 float4
#pragma unroll 4
        for (int k4 = 0; k4 < 24; k4++) {
            int k = k4 * 4;
            float wA0 = w1s[(k + 0) * 64 + lane], wB0 = w1s[(k + 0) * 64 + 32 + lane];
            float wA1 = w1s[(k + 1) * 64 + lane], wB1 = w1s[(k + 1) * 64 + 32 + lane];
            float wA2 = w1s[(k + 2) * 64 + lane], wB2 = w1s[(k + 2) * 64 + 32 + lane];
            float wA3 = w1s[(k + 3) * 64 + lane], wB3 = w1s[(k + 3) * 64 + 32 + lane];
#pragma unroll
            for (int s = 0; s < 8; s++) {
                float4 xv = xs4[s * 24 + k4];
                h0[s] = fmaf(xv.x, wA0, h0[s]); h1[s] = fmaf(xv.x, wB0, h1[s]);
                h0[s] = fmaf(xv.y, wA1, h0[s]); h1[s] = fmaf(xv.y, wB1, h1[s]);
                h0[s] = fmaf(xv.z, wA2, h0[s]); h1[s] = fmaf(xv.z, wB2, h1[s]);
                h0[s] = fmaf(xv.w, wA3, h0[s]); h1[s] = fmaf(xv.w, wB3, h1[s]);
            }
        }
#pragma unroll
        for (int s = 0; s < 8; s++) {
            hsw[s * 68 + lane]      = softplusf(h0[s]);
            hsw[s * 68 + lane + 32] = softplusf(h1[s]);
        }
        __syncwarp();

        // ---- phase C: layer2 64->33, batched; lane j -> output j+1 ----
        float o[8];
#pragma unroll
        for (int s = 0; s < 8; s++) o[s] = b2s[lane + 1];
#pragma unroll 4
        for (int k4 = 0; k4 < 16; k4++) {
            int k = k4 * 4;
            float w0v = w2s[(k + 0) * 33 + lane + 1];
            float w1v = w2s[(k + 1) * 33 + lane + 1];
            float w2v = w2s[(k + 2) * 33 + lane + 1];
            float w3v = w2s[(k + 3) * 33 + lane + 1];
#pragma unroll
            for (int s = 0; s < 8; s++) {
                float4 hv = *(const float4*)(hsw + s * 68 + k);
                o[s] = fmaf(hv.x, w0v, o[s]);
                o[s] = fmaf(hv.y, w1v, o[s]);
                o[s] = fmaf(hv.z, w2v, o[s]);
                o[s] = fmaf(hv.w, w3v, o[s]);
            }
        }
#pragma unroll
        for (int s = 0; s < 8; s++)
            cols[(size_t)(smp0 + s) * 32 + lane] = sigmoidf(o[s]) * 1.002f - 0.001f;

        // sigma: lanes 0..7 each handle one sample (w2 column 0)
        if (lane < 8) {
            const float* hrow = hsw + lane * 68;
            float acc = b2s[0];
#pragma unroll 8
            for (int k = 0; k < 64; k++) acc = fmaf(hrow[k], w2s[k * 33], acc);
            sigs[smp0 + lane] = acc;
        }
        __syncwarp();
    }
}

// ---------------- kernel 5: coarse ray-march weights ----------------
__global__ void k_coarse_weights() {
    int ray = blockIdx.x * blockDim.x + threadIdx.x;
    if (ray >= NRAY) return;
    float T = 1.0f;
    float zp = g_depth_c[ray * Ss];
    float sp = g_sig_c[ray * Ss];
    for (int s = 1; s < Ss; s++) {
        float z = g_depth_c[ray * Ss + s];
        float sg = g_sig_c[ray * Ss + s];
        float dens = softplusf(0.5f * (sp + sg) - 1.0f);
        float alpha = 1.0f - expf(-dens * (z - zp));
        g_wc[ray * 47 + s - 1] = alpha * T;
        T *= (1.0f - alpha + 1e-10f);
        zp = z; sp = sg;
    }
}

// ---------------- kernel 6: importance sampling (fine depths) ----------------
__global__ void k_fine_depths() {
    int ray = blockIdx.x * blockDim.x + threadIdx.x;
    if (ray >= NRAY) return;
    float z[48], w[47];
    for (int i = 0; i < 48; i++) z[i] = g_depth_c[ray * Ss + i];
    for (int i = 0; i < 47; i++) w[i] = g_wc[ray * 47 + i];
    float zm[47];
    for (int i = 0; i < 47; i++) zm[i] = 0.5f * (z[i] + z[i + 1]);
    float wa[47];
    for (int i = 0; i < 47; i++) {
        float wmi  = (i == 0)  ? w[0]  : fmaxf(w[i - 1], w[i]);
        float wmi1 = (i == 46) ? w[46] : fmaxf(w[i], w[i + 1]);
        wa[i] = 0.5f * (wmi + wmi1) + 0.01f;
    }
    float ws[45];
    float sum = 0.0f;
    for (int j = 0; j < 45; j++) { ws[j] = wa[j + 1] + 1e-5f; sum += ws[j]; }
    float cdf[46];
    cdf[0] = 0.0f;
    for (int j = 0; j < 45; j++) cdf[j + 1] = cdf[j] + ws[j] / sum;

    uint32_t ka, kb; derive_key(1u, ka, kb);
    for (int j = 0; j < 48; j++) {
        float u = tf_uniform(ka, kb, (uint32_t)(ray * 48 + j));
        int ind = 0;
        for (int k = 0; k < 46; k++) ind += (cdf[k] <= u) ? 1 : 0;
        int below = ind - 1; if (below < 0) below = 0;
        int above = ind;     if (above > 45) above = 45;
        float c0 = cdf[below], c1 = cdf[above];
        float b0 = zm[below],  b1v = zm[above];
        float denom = c1 - c0;
        if (denom < 1e-5f) denom = 1.0f;
        g_depth_f[ray * 48 + j] = b0 + (u - c0) / denom * (b1v - b0);
    }
}

// ---------------- kernel 7: unify + final march, warp per ray ----------------
__global__ void __launch_bounds__(256) k_final(
    const float* __restrict__ ro, const float* __restrict__ rd,
    float* __restrict__ out)
{
    __shared__ __align__(16) float sd[8][96];
    __shared__ __align__(16) float ssg[8][96];
    __shared__ __align__(16) int   sidx[8][96];
    int lane = threadIdx.x & 31, wrp = threadIdx.x >> 5;
    int ray = blockIdx.x * 8 + wrp;

    for (int i = lane; i < 48; i += 32) {
        sd[wrp][i]       = g_depth_c[ray * 48 + i];
        sd[wrp][48 + i]  = g_depth_f[ray * 48 + i];
        ssg[wrp][i]      = g_sig_c[ray * 48 + i];
        ssg[wrp][48 + i] = g_sig_f[ray * 48 + i];
    }
    __syncwarp();
#pragma unroll
    for (int t = 0; t < 3; t++) {
        int e = lane + t * 32;
        float de = sd[wrp][e];
        int rank = 0;
        for (int j = 0; j < 96; j++) {
            float dj = sd[wrp][j];
            rank += (dj < de || (dj == de && j < e)) ? 1 : 0;
        }
        sidx[wrp][rank] = e;
    }
    __syncwarp();

    float T = 1.0f, accW = 0.0f, accWD = 0.0f, accC = 0.0f;
    int i0 = sidx[wrp][0];
    float dp = sd[wrp][i0], sp = ssg[wrp][i0];
    const float* cb0 = (i0 < 48) ? g_col_c : g_col_f;
    float cp = cb0[((size_t)ray * 48 + (i0 < 48 ? i0 : i0 - 48)) * 32 + lane];

    for (int s = 1; s < 96; s++) {
        int i = sidx[wrp][s];
        float dc = sd[wrp][i], sc = ssg[wrp][i];
        const float* cb = (i < 48) ? g_col_c : g_col_f;
        float cc = cb[((size_t)ray * 48 + (i < 48 ? i : i - 48)) * 32 + lane];
        float delta = dc - dp;
        float dens = softplusf(0.5f * (sc + sp) - 1.0f);
        float alpha = 1.0f - expf(-dens * delta);
        float wgt = alpha * T;
        T *= (1.0f - alpha + 1e-10f);
        accC  += wgt * 0.5f * (cc + cp);
        accW  += wgt;
        accWD += wgt * 0.5f * (dc + dp);
        dp = dc; sp = sc; cp = cc;
    }

    out[OUT_RGB + (size_t)ray * 32 + lane] = accC * 2.0f - 1.0f;
    if (lane == 0) {
        float wt = accW;
        float dep = accWD / wt;
        if (isnan(dep)) dep = __int_as_float(0x7f800000);
        float dmin = __int_as_float(g_dmin_bits);
        float dmax = __int_as_float(g_dmax_bits);
        dep = fminf(fmaxf(dep, dmin), dmax);
        out[OUT_DEPTH + ray] = dep;
        out[OUT_WT + ray] = wt;
    }
    if (lane < 3) {
        float o_ = ro[ray * 3 + lane], d_ = rd[ray * 3 + lane];
        out[OUT_XYZ + (size_t)ray * 3 + lane] = 2.0f * (o_ * accW + d_ * accWD) - 1.0f;
    }
}

// ---------------- launcher ----------------
extern "C" void kernel_launch(void* const* d_in, const int* in_sizes, int n_in,
                              void* d_out, int out_size) {
    const float* front  = (const float*)d_in[0];
    const float* back   = (const float*)d_in[1];
    const float* ro     = (const float*)d_in[2];
    const float* rd     = (const float*)d_in[3];
    const float* weight = (const float*)d_in[4];
    const float* w1     = (const float*)d_in[5];
    const float* b1     = (const float*)d_in[6];
    const float* w2     = (const float*)d_in[7];
    const float* b2     = (const float*)d_in[8];
    float* out = (float*)d_out;

    cudaFuncSetAttribute(k_model, cudaFuncAttributeMaxDynamicSharedMemorySize, SM_TOTAL_BYTES);

    k_init<<<1, 1>>>();
    k_transpose<<<dim3(8, 256, 12), dim3(32, 8)>>>(front, back);
    k_depth_coarse<<<(NSAMP + 255) / 256, 256>>>();
    k_minmax<<<NRAY / 256, 256>>>();
    k_model<<<444, 256, SM_TOTAL_BYTES>>>(ro, rd, weight, w1, b1, w2, b2, 0);
    k_coarse_weights<<<NRAY / 256, 256>>>();
    k_fine_depths<<<NRAY / 256, 256>>>();
    k_model<<<444, 256, SM_TOTAL_BYTES>>>(ro, rd, weight, w1, b1, w2, b2, 1);
    k_final<<<NRAY / 8, 256>>>(ro, rd, out);
    (void)in_sizes; (void)n_in; (void)out_size;
}

// round 4
// speedup vs baseline: 1.8480x; 1.2371x over previous
#include <cuda_runtime.h>
#include <cstdint>
#include <math.h>

// ---------------- problem constants ----------------
#define Bb 2
#define Rr 4096
#define Ss 48
#define NRAY   (Bb*Rr)        // 8192
#define NSAMP  (NRAY*Ss)      // 393216
#define NGROUP (NSAMP/8)      // 49152

#define RAY_START 2.25f
#define STEPF 0.0223404255319148936f  // (3.3-2.25)/47

// output layout (flatten+concat of return tuple)
#define OUT_RGB   0
#define OUT_DEPTH 262144
#define OUT_WT    270336
#define OUT_XYZ   278528

// ---------------- scratch (static device memory; no allocs) ----------------
// planes: [b][p][y][x][c*2 + {front,back}]  (float2 per channel)
__device__ float g_planes[(size_t)Bb*3*256*256*64];
__device__ float g_depth_c[NSAMP];
__device__ float g_depth_f[NSAMP];
__device__ float g_col_c[(size_t)NSAMP*32];
__device__ float g_col_f[(size_t)NSAMP*32];
__device__ float g_sig_c[NSAMP];
__device__ float g_sig_f[NSAMP];
__device__ float g_wc[NRAY*47];
__device__ int   g_dmin_bits;
__device__ int   g_dmax_bits;

// ---------------- math helpers ----------------
__device__ __forceinline__ float softplusf(float x) {
    return fmaxf(x, 0.0f) + log1pf(expf(-fabsf(x)));
}
__device__ __forceinline__ float sigmoidf(float x) {
    return 1.0f / (1.0f + expf(-x));
}

typedef unsigned long long u64t;
__device__ __forceinline__ u64t ffma2(u64t a, u64t b, u64t c) {
    u64t d;
    asm("fma.rn.f32x2 %0, %1, %2, %3;" : "=l"(d) : "l"(a), "l"(b), "l"(c));
    return d;
}
__device__ __forceinline__ u64t pack2(float lo, float hi) {
    u64t r;
    asm("mov.b64 %0, {%1, %2};" : "=l"(r) : "f"(lo), "f"(hi));
    return r;
}
__device__ __forceinline__ void unpack2(u64t v, float& lo, float& hi) {
    asm("mov.b64 {%0, %1}, %2;" : "=f"(lo), "=f"(hi) : "l"(v));
}

// ---------------- Threefry-2x32 (JAX, partitionable variant) ----------------
__device__ __forceinline__ uint32_t rotl32(uint32_t x, int r) {
    return (x << r) | (x >> (32 - r));
}
__device__ __forceinline__ void tf2x32(uint32_t k0, uint32_t k1,
                                       uint32_t x0, uint32_t x1,
                                       uint32_t& o0, uint32_t& o1) {
    uint32_t ks2 = k0 ^ k1 ^ 0x1BD11BDAu;
    x0 += k0; x1 += k1;
#define TFR(r) { x0 += x1; x1 = rotl32(x1, r); x1 ^= x0; }
    TFR(13) TFR(15) TFR(26) TFR(6)  x0 += k1;  x1 += ks2 + 1u;
    TFR(17) TFR(29) TFR(16) TFR(24) x0 += ks2; x1 += k0 + 2u;
    TFR(13) TFR(15) TFR(26) TFR(6)  x0 += k0;  x1 += k1 + 3u;
    TFR(17) TFR(29) TFR(16) TFR(24) x0 += k1;  x1 += ks2 + 4u;
    TFR(13) TFR(15) TFR(26) TFR(6)  x0 += ks2; x1 += k0 + 5u;
#undef TFR
    o0 = x0; o1 = x1;
}
__device__ __forceinline__ void derive_key(uint32_t idx, uint32_t& ka, uint32_t& kb) {
    tf2x32(0u, 42u, 0u, idx, ka, kb);
}
__device__ __forceinline__ float tf_uniform(uint32_t ka, uint32_t kb, uint32_t i) {
    uint32_t o0, o1;
    tf2x32(ka, kb, 0u, i, o0, o1);
    uint32_t bits = o0 ^ o1;
    float f = __uint_as_float((bits >> 9) | 0x3f800000u) - 1.0f;
    return fmaxf(f, 0.0f);
}

// ---------------- kernel 0: init min/max scalars ----------------
__global__ void k_init() {
    g_dmin_bits = 0x7f800000;
    g_dmax_bits = 0x00000000;
}

// ---------------- kernel 1: plane transpose to channel-last ----------------
__global__ void k_transpose(const float* __restrict__ front, const float* __restrict__ back) {
    __shared__ float tile[32][33];
    int z  = blockIdx.z;
    int src = z & 1;
    int bp  = z >> 1;
    int y   = blockIdx.y;
    int x0  = blockIdx.x * 32;
    int tx = threadIdx.x, ty = threadIdx.y;
    const float* in = src ? back : front;
#pragma unroll
    for (int i = 0; i < 4; i++) {
        int c = ty + i * 8;
        tile[c][tx] = in[((size_t)(bp * 32 + c) * 65536) + (size_t)y * 256 + x0 + tx];
    }
    __syncthreads();
#pragma unroll
    for (int i = 0; i < 4; i++) {
        int xx = ty + i * 8;
        g_planes[(((size_t)bp * 65536) + (size_t)y * 256 + x0 + xx) * 64 + tx * 2 + src] = tile[tx][xx];
    }
}

// ---------------- kernel 2: coarse stratified depths ----------------
__global__ void k_depth_coarse() {
    int i = blockIdx.x * blockDim.x + threadIdx.x;
    if (i >= NSAMP) return;
    uint32_t ka, kb; derive_key(0u, ka, kb);
    float u = tf_uniform(ka, kb, (uint32_t)i);
    int s = i % Ss;
    float d0 = RAY_START + (float)s * STEPF;
    g_depth_c[i] = d0 + u * STEPF;
}

// ---------------- kernel 3: global depth min/max ----------------
__global__ void k_minmax() {
    int ray = blockIdx.x * blockDim.x + threadIdx.x;
    float dmin = g_depth_c[ray * Ss];
    float dmax = g_depth_c[ray * Ss + Ss - 1];
#pragma unroll
    for (int off = 16; off; off >>= 1) {
        dmin = fminf(dmin, __shfl_xor_sync(0xffffffffu, dmin, off));
        dmax = fmaxf(dmax, __shfl_xor_sync(0xffffffffu, dmax, off));
    }
    if ((threadIdx.x & 31) == 0) {
        atomicMin(&g_dmin_bits, __float_as_int(dmin));
        atomicMax(&g_dmax_bits, __float_as_int(dmax));
    }
}

// ---------------- kernel 4: model, warp per 8-sample group, f32x2 MLP ----------------
// dynamic smem layout (floats):
//   [0)      w1s : 96*64 = 6144
//   [6144)   w2s : 64*33 = 2112
//   [8256)   b1s : 64
//   [8320)   b2s : 48 (33 used)
//   [8368)   wsig: 96
//   [8464)   xsT : 8 warps * 96*4 float2 = 6144 floats  (per-warp [k][pair] pairs)
//   [14608)  hT  : 8 warps * 64*4 float2 = 4096 floats  (per-warp [o][pair] pairs)
// total 18704 floats = 74816 bytes
#define SM_W1   0
#define SM_W2   6144
#define SM_B1   8256
#define SM_B2   8320
#define SM_WSIG 8368
#define SM_XST  8464
#define SM_HT   14608
#define SM_TOTAL_BYTES (18704*4)

extern __shared__ __align__(16) float smem[];

// axis prep: scaled coordinate -> weights + clamped indices (grid_sample border zeros)
struct Axis { float w0, w1; int i0, i1; };
__device__ __forceinline__ Axis axis_prep(float g) {
    Axis a;
    float x = (g + 1.0f) * 128.0f - 0.5f;
    float x0f = floorf(x);
    int x0 = (int)x0f;
    float w = x - x0f;
    bool v0 = (x0 >= 0) & (x0 < 256);
    bool v1 = (x0 >= -1) & (x0 < 255);
    a.w0 = v0 ? 1.0f - w : 0.0f;
    a.w1 = v1 ? w : 0.0f;
    a.i0 = min(max(x0, 0), 255);
    a.i1 = min(max(x0 + 1, 0), 255);
    return a;
}

__global__ void __launch_bounds__(256, 2) k_model(
    const float* __restrict__ ro, const float* __restrict__ rd,
    const float* __restrict__ weight,
    const float* __restrict__ w1, const float* __restrict__ b1,
    const float* __restrict__ w2, const float* __restrict__ b2,
    int fine_pass)
{
    float* w1s  = smem + SM_W1;
    float* w2s  = smem + SM_W2;
    float* b1s  = smem + SM_B1;
    float* b2s  = smem + SM_B2;
    float* wsig = smem + SM_WSIG;

    int tid = threadIdx.x;
    for (int i = tid; i < 96 * 64; i += 256) w1s[i] = w1[i];
    for (int i = tid; i < 64 * 33; i += 256) w2s[i] = w2[i];
    if (tid < 64) b1s[tid] = b1[tid];
    if (tid < 33) b2s[tid] = b2[tid];
    if (tid < 96) wsig[tid] = sigmoidf(weight[tid]);
    __syncthreads();

    const float* depths = fine_pass ? g_depth_f : g_depth_c;
    float* cols = fine_pass ? g_col_f : g_col_c;
    float* sigs = fine_pass ? g_sig_f : g_sig_c;

    int lane = tid & 31, wrp = tid >> 5;
    float* xw = smem + SM_XST + wrp * 768;   // per-warp x: [96 k][4 pair] float2
    float* hw = smem + SM_HT  + wrp * 512;   // per-warp h: [64 o][4 pair] float2

    float wk0 = wsig[lane], wk1 = wsig[32 + lane], wk2 = wsig[64 + lane];

    int groupG = blockIdx.x * 8 + wrp;
    int nGroups = gridDim.x * 8;

    for (int g = groupG; g < NGROUP; g += nGroups) {
        int smp0 = g * 8;
        int ray = smp0 / Ss;          // whole group lies in one ray (8 | 48)
        int b = ray >> 12;
        float ox = ro[ray * 3 + 0], oy = ro[ray * 3 + 1], oz = ro[ray * 3 + 2];
        float dx = rd[ray * 3 + 0], dy = rd[ray * 3 + 1], dz = rd[ray * 3 + 2];
        const float2* pb = (const float2*)g_planes + (size_t)b * 3 * 65536 * 32;
        const float2* pb0 = pb;
        const float2* pb1 = pb + (size_t)65536 * 32;
        const float2* pb2 = pb + (size_t)2 * 65536 * 32;

        // ---- phase A: tri-plane gather, lane = channel; xv kept per-plane for pair-packed stores ----
        float xv0[8], xv1[8], xv2[8];
#pragma unroll
        for (int s = 0; s < 8; s++) {
            float d = depths[smp0 + s];
            float cx = 2.0f * fmaf(d, dx, ox);
            float cy = 2.0f * fmaf(d, dy, oy);
            float cz = 2.0f * fmaf(d, dz, oz);
            Axis ax = axis_prep(cx);    // shared by p0.x, p1.x, p2.y
            Axis ay = axis_prep(cy);    // p0.y
            Axis az = axis_prep(cz);    // p1.y, p2.x

            // plane 0: (ax, ay)
            {
                float2 v00 = pb0[(ay.i0 * 256 + ax.i0) * 32 + lane];
                float2 v01 = pb0[(ay.i0 * 256 + ax.i1) * 32 + lane];
                float2 v10 = pb0[(ay.i1 * 256 + ax.i0) * 32 + lane];
                float2 v11 = pb0[(ay.i1 * 256 + ax.i1) * 32 + lane];
                float w00 = ax.w0 * ay.w0, w01 = ax.w1 * ay.w0;
                float w10 = ax.w0 * ay.w1, w11 = ax.w1 * ay.w1;
                float aF = fmaf(w11, v11.x, fmaf(w10, v10.x, fmaf(w01, v01.x, w00 * v00.x)));
                float aB = fmaf(w11, v11.y, fmaf(w10, v10.y, fmaf(w01, v01.y, w00 * v00.y)));
                xv0[s] = wk0 * aF + (1.0f - wk0) * aB;
            }
            // plane 1: (ax, az)
            {
                float2 v00 = pb1[(az.i0 * 256 + ax.i0) * 32 + lane];
                float2 v01 = pb1[(az.i0 * 256 + ax.i1) * 32 + lane];
                float2 v10 = pb1[(az.i1 * 256 + ax.i0) * 32 + lane];
                float2 v11 = pb1[(az.i1 * 256 + ax.i1) * 32 + lane];
                float w00 = ax.w0 * az.w0, w01 = ax.w1 * az.w0;
                float w10 = ax.w0 * az.w1, w11 = ax.w1 * az.w1;
                float aF = fmaf(w11, v11.x, fmaf(w10, v10.x, fmaf(w01, v01.x, w00 * v00.x)));
                float aB = fmaf(w11, v11.y, fmaf(w10, v10.y, fmaf(w01, v01.y, w00 * v00.y)));
                xv1[s] = wk1 * aF + (1.0f - wk1) * aB;
            }
            // plane 2: (az, ax)
            {
                float2 v00 = pb2[(ax.i0 * 256 + az.i0) * 32 + lane];
                float2 v01 = pb2[(ax.i0 * 256 + az.i1) * 32 + lane];
                float2 v10 = pb2[(ax.i1 * 256 + az.i0) * 32 + lane];
                float2 v11 = pb2[(ax.i1 * 256 + az.i1) * 32 + lane];
                float w00 = az.w0 * ax.w0, w01 = az.w1 * ax.w0;
                float w10 = az.w0 * ax.w1, w11 = az.w1 * ax.w1;
                float aF = fmaf(w11, v11.x, fmaf(w10, v10.x, fmaf(w01, v01.x, w00 * v00.x)));
                float aB = fmaf(w11, v11.y, fmaf(w10, v10.y, fmaf(w01, v01.y, w00 * v00.y)));
                xv2[s] = wk2 * aF + (1.0f - wk2) * aB;
            }
        }
        // pair-packed transposed stores: xsT[k][pair]
#pragma unroll
        for (int q = 0; q < 4; q++) {
            *(float2*)(xw + ((0 * 32 + lane) * 4 + q) * 2) = make_float2(xv0[2 * q], xv0[2 * q + 1]);
            *(float2*)(xw + ((1 * 32 + lane) * 4 + q) * 2) = make_float2(xv1[2 * q], xv1[2 * q + 1]);
            *(float2*)(xw + ((2 * 32 + lane) * 4 + q) * 2) = make_float2(xv2[2 * q], xv2[2 * q + 1]);
        }
        __syncwarp();

        // ---- phase B: layer1 96->64, f32x2 over sample pairs ----
        u64t hA[4], hB[4];
        {
            float bA = b1s[lane], bB = b1s[lane + 32];
            u64t bA2 = pack2(bA, bA), bB2 = pack2(bB, bB);
#pragma unroll
            for (int q = 0; q < 4; q++) { hA[q] = bA2; hB[q] = bB2; }
        }
        const ulonglong2* xt = (const ulonglong2*)xw;
#pragma unroll 8
        for (int k = 0; k < 96; k++) {
            float wa = w1s[k * 64 + lane], wb = w1s[k * 64 + 32 + lane];
            u64t wa2 = pack2(wa, wa), wb2 = pack2(wb, wb);
            ulonglong2 x01 = xt[k * 2], x23 = xt[k * 2 + 1];
            hA[0] = ffma2(x01.x, wa2, hA[0]); hB[0] = ffma2(x01.x, wb2, hB[0]);
            hA[1] = ffma2(x01.y, wa2, hA[1]); hB[1] = ffma2(x01.y, wb2, hB[1]);
            hA[2] = ffma2(x23.x, wa2, hA[2]); hB[2] = ffma2(x23.x, wb2, hB[2]);
            hA[3] = ffma2(x23.y, wa2, hA[3]); hB[3] = ffma2(x23.y, wb2, hB[3]);
        }
#pragma unroll
        for (int q = 0; q < 4; q++) {
            float a0, a1, c0, c1;
            unpack2(hA[q], a0, a1);
            unpack2(hB[q], c0, c1);
            *(float2*)(hw + (lane * 4 + q) * 2)        = make_float2(softplusf(a0), softplusf(a1));
            *(float2*)(hw + ((lane + 32) * 4 + q) * 2) = make_float2(softplusf(c0), softplusf(c1));
        }
        __syncwarp();

        // ---- phase C: layer2 64->33, f32x2; lane j -> output j+1 ----
        u64t oa[4];
        {
            float bo = b2s[lane + 1];
            u64t bo2 = pack2(bo, bo);
#pragma unroll
            for (int q = 0; q < 4; q++) oa[q] = bo2;
        }
        const ulonglong2* ht = (const ulonglong2*)hw;
#pragma unroll 8
        for (int k = 0; k < 64; k++) {
            float wv = w2s[k * 33 + lane + 1];
            u64t wv2 = pack2(wv, wv);
            ulonglong2 h01 = ht[k * 2], h23 = ht[k * 2 + 1];
            oa[0] = ffma2(h01.x, wv2, oa[0]);
            oa[1] = ffma2(h01.y, wv2, oa[1]);
            oa[2] = ffma2(h23.x, wv2, oa[2]);
            oa[3] = ffma2(h23.y, wv2, oa[3]);
        }
#pragma unroll
        for (int q = 0; q < 4; q++) {
            float o0, o1;
            unpack2(oa[q], o0, o1);
            cols[(size_t)(smp0 + 2 * q) * 32 + lane]     = sigmoidf(o0) * 1.002f - 0.001f;
            cols[(size_t)(smp0 + 2 * q + 1) * 32 + lane] = sigmoidf(o1) * 1.002f - 0.001f;
        }
        // sigma: lanes 0..7 each handle one sample (w2 column 0); hw float view: h[s][o] = hw[o*8+s]
        if (lane < 8) {
            float acc = b2s[0];
#pragma unroll 8
            for (int k = 0; k < 64; k++) acc = fmaf(hw[k * 8 + lane], w2s[k * 33], acc);
            sigs[smp0 + lane] = acc;
        }
        __syncwarp();
    }
}

// ---------------- kernel 5: coarse ray-march weights ----------------
__global__ void k_coarse_weights() {
    int ray = blockIdx.x * blockDim.x + threadIdx.x;
    if (ray >= NRAY) return;
    float T = 1.0f;
    float zp = g_depth_c[ray * Ss];
    float sp = g_sig_c[ray * Ss];
    for (int s = 1; s < Ss; s++) {
        float z = g_depth_c[ray * Ss + s];
        float sg = g_sig_c[ray * Ss + s];
        float dens = softplusf(0.5f * (sp + sg) - 1.0f);
        float alpha = 1.0f - expf(-dens * (z - zp));
        g_wc[ray * 47 + s - 1] = alpha * T;
        T *= (1.0f - alpha + 1e-10f);
        zp = z; sp = sg;
    }
}

// ---------------- kernel 6: importance sampling (fine depths) ----------------
__global__ void k_fine_depths() {
    int ray = blockIdx.x * blockDim.x + threadIdx.x;
    if (ray >= NRAY) return;
    float z[48], w[47];
    for (int i = 0; i < 48; i++) z[i] = g_depth_c[ray * Ss + i];
    for (int i = 0; i < 47; i++) w[i] = g_wc[ray * 47 + i];
    float zm[47];
    for (int i = 0; i < 47; i++) zm[i] = 0.5f * (z[i] + z[i + 1]);
    float wa[47];
    for (int i = 0; i < 47; i++) {
        float wmi  = (i == 0)  ? w[0]  : fmaxf(w[i - 1], w[i]);
        float wmi1 = (i == 46) ? w[46] : fmaxf(w[i], w[i + 1]);
        wa[i] = 0.5f * (wmi + wmi1) + 0.01f;
    }
    float ws[45];
    float sum = 0.0f;
    for (int j = 0; j < 45; j++) { ws[j] = wa[j + 1] + 1e-5f; sum += ws[j]; }
    float cdf[46];
    cdf[0] = 0.0f;
    for (int j = 0; j < 45; j++) cdf[j + 1] = cdf[j] + ws[j] / sum;

    uint32_t ka, kb; derive_key(1u, ka, kb);
    for (int j = 0; j < 48; j++) {
        float u = tf_uniform(ka, kb, (uint32_t)(ray * 48 + j));
        int ind = 0;
        for (int k = 0; k < 46; k++) ind += (cdf[k] <= u) ? 1 : 0;
        int below = ind - 1; if (below < 0) below = 0;
        int above = ind;     if (above > 45) above = 45;
        float c0 = cdf[below], c1 = cdf[above];
        float b0 = zm[below],  b1v = zm[above];
        float denom = c1 - c0;
        if (denom < 1e-5f) denom = 1.0f;
        g_depth_f[ray * 48 + j] = b0 + (u - c0) / denom * (b1v - b0);
    }
}

// ---------------- kernel 7: unify + final march, warp per ray ----------------
__global__ void __launch_bounds__(256) k_final(
    const float* __restrict__ ro, const float* __restrict__ rd,
    float* __restrict__ out)
{
    __shared__ __align__(16) float sd[8][96];
    __shared__ __align__(16) float ssg[8][96];
    __shared__ __align__(16) int   sidx[8][96];
    int lane = threadIdx.x & 31, wrp = threadIdx.x >> 5;
    int ray = blockIdx.x * 8 + wrp;

    for (int i = lane; i < 48; i += 32) {
        sd[wrp][i]       = g_depth_c[ray * 48 + i];
        sd[wrp][48 + i]  = g_depth_f[ray * 48 + i];
        ssg[wrp][i]      = g_sig_c[ray * 48 + i];
        ssg[wrp][48 + i] = g_sig_f[ray * 48 + i];
    }
    __syncwarp();
#pragma unroll
    for (int t = 0; t < 3; t++) {
        int e = lane + t * 32;
        float de = sd[wrp][e];
        int rank = 0;
        for (int j = 0; j < 96; j++) {
            float dj = sd[wrp][j];
            rank += (dj < de || (dj == de && j < e)) ? 1 : 0;
        }
        sidx[wrp][rank] = e;
    }
    __syncwarp();

    float T = 1.0f, accW = 0.0f, accWD = 0.0f, accC = 0.0f;
    int i0 = sidx[wrp][0];
    float dp = sd[wrp][i0], sp = ssg[wrp][i0];
    const float* cb0 = (i0 < 48) ? g_col_c : g_col_f;
    float cp = cb0[((size_t)ray * 48 + (i0 < 48 ? i0 : i0 - 48)) * 32 + lane];

    for (int s = 1; s < 96; s++) {
        int i = sidx[wrp][s];
        float dc = sd[wrp][i], sc = ssg[wrp][i];
        const float* cb = (i < 48) ? g_col_c : g_col_f;
        float cc = cb[((size_t)ray * 48 + (i < 48 ? i : i - 48)) * 32 + lane];
        float delta = dc - dp;
        float dens = softplusf(0.5f * (sc + sp) - 1.0f);
        float alpha = 1.0f - expf(-dens * delta);
        float wgt = alpha * T;
        T *= (1.0f - alpha + 1e-10f);
        accC  += wgt * 0.5f * (cc + cp);
        accW  += wgt;
        accWD += wgt * 0.5f * (dc + dp);
        dp = dc; sp = sc; cp = cc;
    }

    out[OUT_RGB + (size_t)ray * 32 + lane] = accC * 2.0f - 1.0f;
    if (lane == 0) {
        float wt = accW;
        float dep = accWD / wt;
        if (isnan(dep)) dep = __int_as_float(0x7f800000);
        float dmin = __int_as_float(g_dmin_bits);
        float dmax = __int_as_float(g_dmax_bits);
        dep = fminf(fmaxf(dep, dmin), dmax);
        out[OUT_DEPTH + ray] = dep;
        out[OUT_WT + ray] = wt;
    }
    if (lane < 3) {
        float o_ = ro[ray * 3 + lane], d_ = rd[ray * 3 + lane];
        out[OUT_XYZ + (size_t)ray * 3 + lane] = 2.0f * (o_ * accW + d_ * accWD) - 1.0f;
    }
}

// ---------------- launcher ----------------
extern "C" void kernel_launch(void* const* d_in, const int* in_sizes, int n_in,
                              void* d_out, int out_size) {
    const float* front  = (const float*)d_in[0];
    const float* back   = (const float*)d_in[1];
    const float* ro     = (const float*)d_in[2];
    const float* rd     = (const float*)d_in[3];
    const float* weight = (const float*)d_in[4];
    const float* w1     = (const float*)d_in[5];
    const float* b1     = (const float*)d_in[6];
    const float* w2     = (const float*)d_in[7];
    const float* b2     = (const float*)d_in[8];
    float* out = (float*)d_out;

    cudaFuncSetAttribute(k_model, cudaFuncAttributeMaxDynamicSharedMemorySize, SM_TOTAL_BYTES);

    // order chosen so k_model (coarse) sits in the slot ncu profiles (-s 5 -c 1):
    // init(1), transpose(2), depth_coarse(3), model_c(4), coarse_w(5), fine_d(6),
    // minmax(7), model_f(8), final(9)
    k_init<<<1, 1>>>();
    k_transpose<<<dim3(8, 256, 12), dim3(32, 8)>>>(front, back);
    k_depth_coarse<<<(NSAMP + 255) / 256, 256>>>();
    k_model<<<296, 256, SM_TOTAL_BYTES>>>(ro, rd, weight, w1, b1, w2, b2, 0);
    k_coarse_weights<<<NRAY / 256, 256>>>();
    k_fine_depths<<<NRAY / 256, 256>>>();
    k_minmax<<<NRAY / 256, 256>>>();
    k_model<<<296, 256, SM_TOTAL_BYTES>>>(ro, rd, weight, w1, b1, w2, b2, 1);
    k_final<<<NRAY / 8, 256>>>(ro, rd, out);
    (void)in_sizes; (void)n_in; (void)out_size;
}

// round 6
// speedup vs baseline: 1.9267x; 1.0425x over previous
#include <cuda_runtime.h>
#include <cuda_fp16.h>
#include <cstdint>
#include <math.h>

// ---------------- problem constants ----------------
#define Bb 2
#define Rr 4096
#define Ss 48
#define NRAY   (Bb*Rr)        // 8192
#define NSAMP  (NRAY*Ss)      // 393216
#define NGROUP (NSAMP/8)      // 49152

#define RAY_START 2.25f
#define STEPF 0.0223404255319148936f  // (3.3-2.25)/47

// output layout (flatten+concat of return tuple)
#define OUT_RGB   0
#define OUT_DEPTH 262144
#define OUT_WT    270336
#define OUT_XYZ   278528

// ---------------- scratch (static device memory; no allocs) ----------------
// planes fp16: [b][p][y][x][c] as half2 = (front, back)
__device__ __half g_planes_h[(size_t)Bb*3*256*256*64];
__device__ float g_depth_c[NSAMP];
__device__ float g_depth_f[NSAMP];
__device__ float g_col_c[(size_t)NSAMP*32];
__device__ float g_col_f[(size_t)NSAMP*32];
__device__ float g_sig_c[NSAMP];
__device__ float g_sig_f[NSAMP];
__device__ float g_wc[NRAY*47];
__device__ int   g_dmin_bits;
__device__ int   g_dmax_bits;

// ---------------- math helpers ----------------
__device__ __forceinline__ float softplusf(float x) {
    return fmaxf(x, 0.0f) + log1pf(expf(-fabsf(x)));
}
__device__ __forceinline__ float sigmoidf(float x) {
    return 1.0f / (1.0f + expf(-x));
}

typedef unsigned long long u64t;
__device__ __forceinline__ u64t ffma2(u64t a, u64t b, u64t c) {
    u64t d;
    asm("fma.rn.f32x2 %0, %1, %2, %3;" : "=l"(d) : "l"(a), "l"(b), "l"(c));
    return d;
}
__device__ __forceinline__ u64t pack2(float lo, float hi) {
    u64t r;
    asm("mov.b64 %0, {%1, %2};" : "=l"(r) : "f"(lo), "f"(hi));
    return r;
}
__device__ __forceinline__ void unpack2(u64t v, float& lo, float& hi) {
    asm("mov.b64 {%0, %1}, %2;" : "=f"(lo), "=f"(hi) : "l"(v));
}

// ---------------- Threefry-2x32 (JAX, partitionable variant) ----------------
__device__ __forceinline__ uint32_t rotl32(uint32_t x, int r) {
    return (x << r) | (x >> (32 - r));
}
__device__ __forceinline__ void tf2x32(uint32_t k0, uint32_t k1,
                                       uint32_t x0, uint32_t x1,
                                       uint32_t& o0, uint32_t& o1) {
    uint32_t ks2 = k0 ^ k1 ^ 0x1BD11BDAu;
    x0 += k0; x1 += k1;
#define TFR(r) { x0 += x1; x1 = rotl32(x1, r); x1 ^= x0; }
    TFR(13) TFR(15) TFR(26) TFR(6)  x0 += k1;  x1 += ks2 + 1u;
    TFR(17) TFR(29) TFR(16) TFR(24) x0 += ks2; x1 += k0 + 2u;
    TFR(13) TFR(15) TFR(26) TFR(6)  x0 += k0;  x1 += k1 + 3u;
    TFR(17) TFR(29) TFR(16) TFR(24) x0 += k1;  x1 += ks2 + 4u;
    TFR(13) TFR(15) TFR(26) TFR(6)  x0 += ks2; x1 += k0 + 5u;
#undef TFR
    o0 = x0; o1 = x1;
}
__device__ __forceinline__ void derive_key(uint32_t idx, uint32_t& ka, uint32_t& kb) {
    tf2x32(0u, 42u, 0u, idx, ka, kb);
}
__device__ __forceinline__ float tf_uniform(uint32_t ka, uint32_t kb, uint32_t i) {
    uint32_t o0, o1;
    tf2x32(ka, kb, 0u, i, o0, o1);
    uint32_t bits = o0 ^ o1;
    float f = __uint_as_float((bits >> 9) | 0x3f800000u) - 1.0f;
    return fmaxf(f, 0.0f);
}

// ---------------- kernel 0: init min/max scalars ----------------
__global__ void k_init() {
    g_dmin_bits = 0x7f800000;
    g_dmax_bits = 0x00000000;
}

// ---------------- kernel 1: plane transpose to channel-last fp16 ----------------
__global__ void k_transpose(const float* __restrict__ front, const float* __restrict__ back) {
    __shared__ float tf[32][33];
    __shared__ float tb[32][33];
    int bp = blockIdx.z;          // 0..5 : b*3+p
    int y  = blockIdx.y;
    int x0 = blockIdx.x * 32;
    int tx = threadIdx.x, ty = threadIdx.y;
    __half2* out = (__half2*)g_planes_h;
#pragma unroll
    for (int i = 0; i < 4; i++) {
        int c = ty + i * 8;
        size_t src = ((size_t)(bp * 32 + c) * 65536) + (size_t)y * 256 + x0 + tx;
        tf[c][tx] = front[src];
        tb[c][tx] = back[src];
    }
    __syncthreads();
#pragma unroll
    for (int i = 0; i < 4; i++) {
        int xx = ty + i * 8;
        out[(((size_t)bp * 65536) + (size_t)y * 256 + x0 + xx) * 32 + tx] =
            __floats2half2_rn(tf[tx][xx], tb[tx][xx]);
    }
}

// ---------------- kernel 2: coarse stratified depths ----------------
__global__ void k_depth_coarse() {
    int i = blockIdx.x * blockDim.x + threadIdx.x;
    if (i >= NSAMP) return;
    uint32_t ka, kb; derive_key(0u, ka, kb);
    float u = tf_uniform(ka, kb, (uint32_t)i);
    int s = i % Ss;
    float d0 = RAY_START + (float)s * STEPF;
    g_depth_c[i] = d0 + u * STEPF;
}

// ---------------- kernel 3: global depth min/max ----------------
__global__ void k_minmax() {
    int ray = blockIdx.x * blockDim.x + threadIdx.x;
    float dmin = g_depth_c[ray * Ss];
    float dmax = g_depth_c[ray * Ss + Ss - 1];
#pragma unroll
    for (int off = 16; off; off >>= 1) {
        dmin = fminf(dmin, __shfl_xor_sync(0xffffffffu, dmin, off));
        dmax = fmaxf(dmax, __shfl_xor_sync(0xffffffffu, dmax, off));
    }
    if ((threadIdx.x & 31) == 0) {
        atomicMin(&g_dmin_bits, __float_as_int(dmin));
        atomicMax(&g_dmax_bits, __float_as_int(dmax));
    }
}

// ---------------- kernel 4: model, warp per 8-sample group, f32x2 MLP ----------------
#define SM_W1   0
#define SM_W2   6144
#define SM_B1   8256
#define SM_B2   8320
#define SM_WSIG 8368
#define SM_XST  8464
#define SM_HT   14608
#define SM_TOTAL_BYTES (18704*4)

extern __shared__ __align__(16) float smem[];

// axis prep: scaled coordinate -> weights + clamped indices (grid_sample border zeros)
struct Axis { float w0, w1; int i0, i1; };
__device__ __forceinline__ Axis axis_prep(float g) {
    Axis a;
    float x = (g + 1.0f) * 128.0f - 0.5f;
    float x0f = floorf(x);
    int x0 = (int)x0f;
    float w = x - x0f;
    bool v0 = (x0 >= 0) & (x0 < 256);
    bool v1 = (x0 >= -1) & (x0 < 255);
    a.w0 = v0 ? 1.0f - w : 0.0f;
    a.w1 = v1 ? w : 0.0f;
    a.i0 = min(max(x0, 0), 255);
    a.i1 = min(max(x0 + 1, 0), 255);
    return a;
}

__global__ void __launch_bounds__(256, 2) k_model(
    const float* __restrict__ ro, const float* __restrict__ rd,
    const float* __restrict__ weight,
    const float* __restrict__ w1, const float* __restrict__ b1,
    const float* __restrict__ w2, const float* __restrict__ b2,
    int fine_pass)
{
    float* w1s  = smem + SM_W1;
    float* w2s  = smem + SM_W2;
    float* b1s  = smem + SM_B1;
    float* b2s  = smem + SM_B2;
    float* wsig = smem + SM_WSIG;

    int tid = threadIdx.x;
    for (int i = tid; i < 96 * 64; i += 256) w1s[i] = w1[i];
    for (int i = tid; i < 64 * 33; i += 256) w2s[i] = w2[i];
    if (tid < 64) b1s[tid] = b1[tid];
    if (tid < 33) b2s[tid] = b2[tid];
    if (tid < 96) wsig[tid] = sigmoidf(weight[tid]);
    __syncthreads();

    const float* depths = fine_pass ? g_depth_f : g_depth_c;
    float* cols = fine_pass ? g_col_f : g_col_c;
    float* sigs = fine_pass ? g_sig_f : g_sig_c;

    int lane = tid & 31, wrp = tid >> 5;
    float* xw = smem + SM_XST + wrp * 768;   // per-warp x: [96 k][4 pair] float2
    float* hw = smem + SM_HT  + wrp * 512;   // per-warp h: [64 o][4 pair] float2

    float wk0 = wsig[lane], wk1 = wsig[32 + lane], wk2 = wsig[64 + lane];

    int groupG = blockIdx.x * 8 + wrp;
    int nGroups = gridDim.x * 8;

    for (int g = groupG; g < NGROUP; g += nGroups) {
        int smp0 = g * 8;
        int ray = smp0 / Ss;          // whole group lies in one ray (8 | 48)
        int b = ray >> 12;
        float ox = ro[ray * 3 + 0], oy = ro[ray * 3 + 1], oz = ro[ray * 3 + 2];
        float dx = rd[ray * 3 + 0], dy = rd[ray * 3 + 1], dz = rd[ray * 3 + 2];
        const __half2* pb0 = (const __half2*)g_planes_h + (size_t)b * 3 * 65536 * 32 + (size_t)lane;
        const __half2* pb1 = pb0 + (size_t)65536 * 32;
        const __half2* pb2 = pb1 + (size_t)65536 * 32;

        // ---- phase A: tri-plane gather, lane = channel ----
        float xv0[8], xv1[8], xv2[8];
#pragma unroll
        for (int s = 0; s < 8; s++) {
            float d = depths[smp0 + s];
            float cx = 2.0f * fmaf(d, dx, ox);
            float cy = 2.0f * fmaf(d, dy, oy);
            float cz = 2.0f * fmaf(d, dz, oz);
            Axis ax = axis_prep(cx);    // shared by p0.x, p1.x, p2.y
            Axis ay = axis_prep(cy);    // p0.y
            Axis az = axis_prep(cz);    // p1.y, p2.x

            {   // plane 0: (ax, ay)
                float2 v00 = __half22float2(pb0[(ay.i0 * 256 + ax.i0) * 32]);
                float2 v01 = __half22float2(pb0[(ay.i0 * 256 + ax.i1) * 32]);
                float2 v10 = __half22float2(pb0[(ay.i1 * 256 + ax.i0) * 32]);
                float2 v11 = __half22float2(pb0[(ay.i1 * 256 + ax.i1) * 32]);
                float w00 = ax.w0 * ay.w0, w01 = ax.w1 * ay.w0;
                float w10 = ax.w0 * ay.w1, w11 = ax.w1 * ay.w1;
                float aF = fmaf(w11, v11.x, fmaf(w10, v10.x, fmaf(w01, v01.x, w00 * v00.x)));
                float aB = fmaf(w11, v11.y, fmaf(w10, v10.y, fmaf(w01, v01.y, w00 * v00.y)));
                xv0[s] = wk0 * aF + (1.0f - wk0) * aB;
            }
            {   // plane 1: (ax, az)
                float2 v00 = __half22float2(pb1[(az.i0 * 256 + ax.i0) * 32]);
                float2 v01 = __half22float2(pb1[(az.i0 * 256 + ax.i1) * 32]);
                float2 v10 = __half22float2(pb1[(az.i1 * 256 + ax.i0) * 32]);
                float2 v11 = __half22float2(pb1[(az.i1 * 256 + ax.i1) * 32]);
                float w00 = ax.w0 * az.w0, w01 = ax.w1 * az.w0;
                float w10 = ax.w0 * az.w1, w11 = ax.w1 * az.w1;
                float aF = fmaf(w11, v11.x, fmaf(w10, v10.x, fmaf(w01, v01.x, w00 * v00.x)));
                float aB = fmaf(w11, v11.y, fmaf(w10, v10.y, fmaf(w01, v01.y, w00 * v00.y)));
                xv1[s] = wk1 * aF + (1.0f - wk1) * aB;
            }
            {   // plane 2: (az, ax)
                float2 v00 = __half22float2(pb2[(ax.i0 * 256 + az.i0) * 32]);
                float2 v01 = __half22float2(pb2[(ax.i0 * 256 + az.i1) * 32]);
                float2 v10 = __half22float2(pb2[(ax.i1 * 256 + az.i0) * 32]);
                float2 v11 = __half22float2(pb2[(ax.i1 * 256 + az.i1) * 32]);
                float w00 = az.w0 * ax.w0, w01 = az.w1 * ax.w0;
                float w10 = az.w0 * ax.w1, w11 = az.w1 * ax.w1;
                float aF = fmaf(w11, v11.x, fmaf(w10, v10.x, fmaf(w01, v01.x, w00 * v00.x)));
                float aB = fmaf(w11, v11.y, fmaf(w10, v10.y, fmaf(w01, v01.y, w00 * v00.y)));
                xv2[s] = wk2 * aF + (1.0f - wk2) * aB;
            }
        }
#pragma unroll
        for (int q = 0; q < 4; q++) {
            *(float2*)(xw + ((0 * 32 + lane) * 4 + q) * 2) = make_float2(xv0[2 * q], xv0[2 * q + 1]);
            *(float2*)(xw + ((1 * 32 + lane) * 4 + q) * 2) = make_float2(xv1[2 * q], xv1[2 * q + 1]);
            *(float2*)(xw + ((2 * 32 + lane) * 4 + q) * 2) = make_float2(xv2[2 * q], xv2[2 * q + 1]);
        }
        __syncwarp();

        // ---- phase B: layer1 96->64, f32x2 over sample pairs ----
        u64t hA[4], hB[4];
        {
            float bA = b1s[lane], bB = b1s[lane + 32];
            u64t bA2 = pack2(bA, bA), bB2 = pack2(bB, bB);
#pragma unroll
            for (int q = 0; q < 4; q++) { hA[q] = bA2; hB[q] = bB2; }
        }
        const ulonglong2* xt = (const ulonglong2*)xw;
#pragma unroll 8
        for (int k = 0; k < 96; k++) {
            float wa = w1s[k * 64 + lane], wb = w1s[k * 64 + 32 + lane];
            u64t wa2 = pack2(wa, wa), wb2 = pack2(wb, wb);
            ulonglong2 x01 = xt[k * 2], x23 = xt[k * 2 + 1];
            hA[0] = ffma2(x01.x, wa2, hA[0]); hB[0] = ffma2(x01.x, wb2, hB[0]);
            hA[1] = ffma2(x01.y, wa2, hA[1]); hB[1] = ffma2(x01.y, wb2, hB[1]);
            hA[2] = ffma2(x23.x, wa2, hA[2]); hB[2] = ffma2(x23.x, wb2, hB[2]);
            hA[3] = ffma2(x23.y, wa2, hA[3]); hB[3] = ffma2(x23.y, wb2, hB[3]);
        }
#pragma unroll
        for (int q = 0; q < 4; q++) {
            float a0, a1, c0, c1;
            unpack2(hA[q], a0, a1);
            unpack2(hB[q], c0, c1);
            *(float2*)(hw + (lane * 4 + q) * 2)        = make_float2(softplusf(a0), softplusf(a1));
            *(float2*)(hw + ((lane + 32) * 4 + q) * 2) = make_float2(softplusf(c0), softplusf(c1));
        }
        __syncwarp();

        // ---- phase C: layer2 64->33, f32x2; lane j -> output j+1 ----
        u64t oa[4];
        {
            float bo = b2s[lane + 1];
            u64t bo2 = pack2(bo, bo);
#pragma unroll
            for (int q = 0; q < 4; q++) oa[q] = bo2;
        }
        const ulonglong2* ht = (const ulonglong2*)hw;
#pragma unroll 8
        for (int k = 0; k < 64; k++) {
            float wv = w2s[k * 33 + lane + 1];
            u64t wv2 = pack2(wv, wv);
            ulonglong2 h01 = ht[k * 2], h23 = ht[k * 2 + 1];
            oa[0] = ffma2(h01.x, wv2, oa[0]);
            oa[1] = ffma2(h01.y, wv2, oa[1]);
            oa[2] = ffma2(h23.x, wv2, oa[2]);
            oa[3] = ffma2(h23.y, wv2, oa[3]);
        }
#pragma unroll
        for (int q = 0; q < 4; q++) {
            float o0, o1;
            unpack2(oa[q], o0, o1);
            cols[(size_t)(smp0 + 2 * q) * 32 + lane]     = sigmoidf(o0) * 1.002f - 0.001f;
            cols[(size_t)(smp0 + 2 * q + 1) * 32 + lane] = sigmoidf(o1) * 1.002f - 0.001f;
        }
        // sigma: lanes 0..7 each handle one sample; hw float view: h[o][s] = hw[o*8+s]
        if (lane < 8) {
            float acc = b2s[0];
#pragma unroll 8
            for (int k = 0; k < 64; k++) acc = fmaf(hw[k * 8 + lane], w2s[k * 33], acc);
            sigs[smp0 + lane] = acc;
        }
        __syncwarp();
    }
}

// ---------------- kernel 5: coarse ray-march weights ----------------
__global__ void k_coarse_weights() {
    int ray = blockIdx.x * blockDim.x + threadIdx.x;
    if (ray >= NRAY) return;
    float T = 1.0f;
    float zp = g_depth_c[ray * Ss];
    float sp = g_sig_c[ray * Ss];
    for (int s = 1; s < Ss; s++) {
        float z = g_depth_c[ray * Ss + s];
        float sg = g_sig_c[ray * Ss + s];
        float dens = softplusf(0.5f * (sp + sg) - 1.0f);
        float alpha = 1.0f - expf(-dens * (z - zp));
        g_wc[ray * 47 + s - 1] = alpha * T;
        T *= (1.0f - alpha + 1e-10f);
        zp = z; sp = sg;
    }
}

// ---------------- kernel 6: importance sampling (fine depths), smem-resident ----------------
#define FD_T 64
__global__ void __launch_bounds__(FD_T) k_fine_depths() {
    __shared__ float zm_s[FD_T][49];
    __shared__ float cdf_s[FD_T][47];
    int t = threadIdx.x;
    int ray = blockIdx.x * FD_T + t;
    float* zm  = zm_s[t];
    float* cdf = cdf_s[t];
    const float* zrow = g_depth_c + ray * 48;
    const float* wrow = g_wc + ray * 47;

    float zprev = zrow[0];
    for (int i = 0; i < 47; i++) {
        float z = zrow[i + 1];
        zm[i] = 0.5f * (zprev + z);
        zprev = z;
    }
    // ws[j] = wa[j+1]+1e-5 for j=0..44, wa[i]=0.5*(wmi+wmi1)+0.01
    float sum = 0.0f;
    for (int j = 0; j < 45; j++) {
        int i = j + 1;                    // i in 1..45
        float wim1 = wrow[i - 1], wi = wrow[i], wip1 = wrow[i + 1];
        float wmi  = fmaxf(wim1, wi);
        float wmi1 = fmaxf(wi, wip1);
        float wsj = 0.5f * (wmi + wmi1) + 0.01f + 1e-5f;
        cdf[j + 1] = wsj;                 // stash ws
        sum += wsj;
    }
    cdf[0] = 0.0f;
    float run = 0.0f;
    for (int j = 0; j < 45; j++) {        // identical arithmetic: += ws[j]/sum
        run += cdf[j + 1] / sum;
        cdf[j + 1] = run;
    }

    uint32_t ka, kb; derive_key(1u, ka, kb);
    for (int j = 0; j < 48; j++) {
        float u = tf_uniform(ka, kb, (uint32_t)(ray * 48 + j));
        // ind = #{k in 0..45 : cdf[k] <= u}  (binary search, cdf non-decreasing)
        int pos = 0;
#pragma unroll
        for (int step = 32; step; step >>= 1) {
            int np = pos + step;
            if (np <= 46 && cdf[np - 1] <= u) pos = np;
        }
        int ind = pos;
        int below = ind - 1; if (below < 0) below = 0;
        int above = ind;     if (above > 45) above = 45;
        float c0 = cdf[below], c1 = cdf[above];
        float b0 = zm[below],  b1v = zm[above];
        float denom = c1 - c0;
        if (denom < 1e-5f) denom = 1.0f;
        g_depth_f[ray * 48 + j] = b0 + (u - c0) / denom * (b1v - b0);
    }
}

// ---------------- kernel 7: unify + final march, warp per ray ----------------
__global__ void __launch_bounds__(256) k_final(
    const float* __restrict__ ro, const float* __restrict__ rd,
    float* __restrict__ out)
{
    __shared__ __align__(16) float sd[8][96];
    __shared__ __align__(16) float ssg[8][96];
    __shared__ __align__(16) int   sidx[8][96];
    int lane = threadIdx.x & 31, wrp = threadIdx.x >> 5;
    int ray = blockIdx.x * 8 + wrp;

    for (int i = lane; i < 48; i += 32) {
        sd[wrp][i]       = g_depth_c[ray * 48 + i];
        sd[wrp][48 + i]  = g_depth_f[ray * 48 + i];
        ssg[wrp][i]      = g_sig_c[ray * 48 + i];
        ssg[wrp][48 + i] = g_sig_f[ray * 48 + i];
    }
    __syncwarp();
#pragma unroll
    for (int t = 0; t < 3; t++) {
        int e = lane + t * 32;
        float de = sd[wrp][e];
        int rank = 0;
        for (int j = 0; j < 96; j++) {
            float dj = sd[wrp][j];
            rank += (dj < de || (dj == de && j < e)) ? 1 : 0;
        }
        sidx[wrp][rank] = e;
    }
    __syncwarp();

    float T = 1.0f, accW = 0.0f, accWD = 0.0f, accC = 0.0f;
    int i0 = sidx[wrp][0];
    float dp = sd[wrp][i0], sp = ssg[wrp][i0];
    const float* cb0 = (i0 < 48) ? g_col_c : g_col_f;
    float cp = cb0[((size_t)ray * 48 + (i0 < 48 ? i0 : i0 - 48)) * 32 + lane];

    for (int s = 1; s < 96; s++) {
        int i = sidx[wrp][s];
        float dc = sd[wrp][i], sc = ssg[wrp][i];
        const float* cb = (i < 48) ? g_col_c : g_col_f;
        float cc = cb[((size_t)ray * 48 + (i < 48 ? i : i - 48)) * 32 + lane];
        float delta = dc - dp;
        float dens = softplusf(0.5f * (sc + sp) - 1.0f);
        float alpha = 1.0f - expf(-dens * delta);
        float wgt = alpha * T;
        T *= (1.0f - alpha + 1e-10f);
        accC  += wgt * 0.5f * (cc + cp);
        accW  += wgt;
        accWD += wgt * 0.5f * (dc + dp);
        dp = dc; sp = sc; cp = cc;
    }

    out[OUT_RGB + (size_t)ray * 32 + lane] = accC * 2.0f - 1.0f;
    if (lane == 0) {
        float wt = accW;
        float dep = accWD / wt;
        if (isnan(dep)) dep = __int_as_float(0x7f800000);
        float dmin = __int_as_float(g_dmin_bits);
        float dmax = __int_as_float(g_dmax_bits);
        dep = fminf(fmaxf(dep, dmin), dmax);
        out[OUT_DEPTH + ray] = dep;
        out[OUT_WT + ray] = wt;
    }
    if (lane < 3) {
        float o_ = ro[ray * 3 + lane], d_ = rd[ray * 3 + lane];
        out[OUT_XYZ + (size_t)ray * 3 + lane] = 2.0f * (o_ * accW + d_ * accWD) - 1.0f;
    }
}

// ---------------- launcher ----------------
extern "C" void kernel_launch(void* const* d_in, const int* in_sizes, int n_in,
                              void* d_out, int out_size) {
    const float* front  = (const float*)d_in[0];
    const float* back   = (const float*)d_in[1];
    const float* ro     = (const float*)d_in[2];
    const float* rd     = (const float*)d_in[3];
    const float* weight = (const float*)d_in[4];
    const float* w1     = (const float*)d_in[5];
    const float* b1     = (const float*)d_in[6];
    const float* w2     = (const float*)d_in[7];
    const float* b2     = (const float*)d_in[8];
    float* out = (float*)d_out;

    cudaFuncSetAttribute(k_model, cudaFuncAttributeMaxDynamicSharedMemorySize, SM_TOTAL_BYTES);

    k_init<<<1, 1>>>();
    k_transpose<<<dim3(8, 256, 6), dim3(32, 8)>>>(front, back);
    k_depth_coarse<<<(NSAMP + 255) / 256, 256>>>();
    k_model<<<296, 256, SM_TOTAL_BYTES>>>(ro, rd, weight, w1, b1, w2, b2, 0);
    k_coarse_weights<<<NRAY / 256, 256>>>();
    k_fine_depths<<<NRAY / FD_T, FD_T>>>();
    k_minmax<<<NRAY / 256, 256>>>();
    k_model<<<296, 256, SM_TOTAL_BYTES>>>(ro, rd, weight, w1, b1, w2, b2, 1);
    k_final<<<NRAY / 8, 256>>>(ro, rd, out);
    (void)in_sizes; (void)n_in; (void)out_size;
}

// round 7
// speedup vs baseline: 2.4947x; 1.2948x over previous
#include <cuda_runtime.h>
#include <cuda_fp16.h>
#include <cstdint>
#include <math.h>

// ---------------- problem constants ----------------
#define Bb 2
#define Rr 4096
#define Ss 48
#define NRAY   (Bb*Rr)        // 8192
#define NSAMP  (NRAY*Ss)      // 393216
#define NG16   (NSAMP/16)     // 24576 (16-sample groups; 16 | 48 -> one ray per group)

#define RAY_START 2.25f
#define STEPF 0.0223404255319148936f  // (3.3-2.25)/47

// output layout (flatten+concat of return tuple)
#define OUT_RGB   0
#define OUT_DEPTH 262144
#define OUT_WT    270336
#define OUT_XYZ   278528

// ---------------- scratch (static device memory; no allocs) ----------------
// planes fp16: [b][p][y][x][c] as half2 = (front, back)
__device__ __half g_planes_h[(size_t)Bb*3*256*256*64];
__device__ float g_depth_c[NSAMP];
__device__ float g_depth_f[NSAMP];
__device__ float g_col_c[(size_t)NSAMP*32];
__device__ float g_col_f[(size_t)NSAMP*32];
__device__ float g_sig_c[NSAMP];
__device__ float g_sig_f[NSAMP];
__device__ float g_wc[NRAY*47];
__device__ int   g_dmin_bits;
__device__ int   g_dmax_bits;

// ---------------- math helpers ----------------
__device__ __forceinline__ float softplusf(float x) {
    return fmaxf(x, 0.0f) + log1pf(expf(-fabsf(x)));
}
__device__ __forceinline__ float sigmoidf(float x) {
    return 1.0f / (1.0f + expf(-x));
}
__device__ __forceinline__ uint32_t f2tf32(float x) {
    uint32_t r;
    asm("cvt.rna.tf32.f32 %0, %1;" : "=r"(r) : "f"(x));
    return r;
}
__device__ __forceinline__ void mma_tf32(float& d0, float& d1, float& d2, float& d3,
                                         uint32_t a0, uint32_t a1, uint32_t a2, uint32_t a3,
                                         uint32_t b0, uint32_t b1) {
    asm volatile(
        "mma.sync.aligned.m16n8k8.row.col.f32.tf32.tf32.f32 "
        "{%0,%1,%2,%3}, {%4,%5,%6,%7}, {%8,%9}, {%0,%1,%2,%3};"
        : "+f"(d0), "+f"(d1), "+f"(d2), "+f"(d3)
        : "r"(a0), "r"(a1), "r"(a2), "r"(a3), "r"(b0), "r"(b1));
}

// ---------------- Threefry-2x32 (JAX, partitionable variant) ----------------
__device__ __forceinline__ uint32_t rotl32(uint32_t x, int r) {
    return (x << r) | (x >> (32 - r));
}
__device__ __forceinline__ void tf2x32(uint32_t k0, uint32_t k1,
                                       uint32_t x0, uint32_t x1,
                                       uint32_t& o0, uint32_t& o1) {
    uint32_t ks2 = k0 ^ k1 ^ 0x1BD11BDAu;
    x0 += k0; x1 += k1;
#define TFR(r) { x0 += x1; x1 = rotl32(x1, r); x1 ^= x0; }
    TFR(13) TFR(15) TFR(26) TFR(6)  x0 += k1;  x1 += ks2 + 1u;
    TFR(17) TFR(29) TFR(16) TFR(24) x0 += ks2; x1 += k0 + 2u;
    TFR(13) TFR(15) TFR(26) TFR(6)  x0 += k0;  x1 += k1 + 3u;
    TFR(17) TFR(29) TFR(16) TFR(24) x0 += k1;  x1 += ks2 + 4u;
    TFR(13) TFR(15) TFR(26) TFR(6)  x0 += ks2; x1 += k0 + 5u;
#undef TFR
    o0 = x0; o1 = x1;
}
__device__ __forceinline__ void derive_key(uint32_t idx, uint32_t& ka, uint32_t& kb) {
    tf2x32(0u, 42u, 0u, idx, ka, kb);
}
__device__ __forceinline__ float tf_uniform(uint32_t ka, uint32_t kb, uint32_t i) {
    uint32_t o0, o1;
    tf2x32(ka, kb, 0u, i, o0, o1);
    uint32_t bits = o0 ^ o1;
    float f = __uint_as_float((bits >> 9) | 0x3f800000u) - 1.0f;
    return fmaxf(f, 0.0f);
}

// ---------------- kernel 0: init min/max scalars ----------------
__global__ void k_init() {
    g_dmin_bits = 0x7f800000;
    g_dmax_bits = 0x00000000;
}

// ---------------- kernel 1: plane transpose to channel-last fp16 ----------------
__global__ void k_transpose(const float* __restrict__ front, const float* __restrict__ back) {
    __shared__ float tf[32][33];
    __shared__ float tb[32][33];
    int bp = blockIdx.z;          // 0..5 : b*3+p
    int y  = blockIdx.y;
    int x0 = blockIdx.x * 32;
    int tx = threadIdx.x, ty = threadIdx.y;
    __half2* out = (__half2*)g_planes_h;
#pragma unroll
    for (int i = 0; i < 4; i++) {
        int c = ty + i * 8;
        size_t src = ((size_t)(bp * 32 + c) * 65536) + (size_t)y * 256 + x0 + tx;
        tf[c][tx] = front[src];
        tb[c][tx] = back[src];
    }
    __syncthreads();
#pragma unroll
    for (int i = 0; i < 4; i++) {
        int xx = ty + i * 8;
        out[(((size_t)bp * 65536) + (size_t)y * 256 + x0 + xx) * 32 + tx] =
            __floats2half2_rn(tf[tx][xx], tb[tx][xx]);
    }
}

// ---------------- kernel 2: coarse stratified depths ----------------
__global__ void k_depth_coarse() {
    int i = blockIdx.x * blockDim.x + threadIdx.x;
    if (i >= NSAMP) return;
    uint32_t ka, kb; derive_key(0u, ka, kb);
    float u = tf_uniform(ka, kb, (uint32_t)i);
    int s = i % Ss;
    float d0 = RAY_START + (float)s * STEPF;
    g_depth_c[i] = d0 + u * STEPF;
}

// ---------------- kernel 3: global depth min/max ----------------
__global__ void k_minmax() {
    int ray = blockIdx.x * blockDim.x + threadIdx.x;
    float dmin = g_depth_c[ray * Ss];
    float dmax = g_depth_c[ray * Ss + Ss - 1];
#pragma unroll
    for (int off = 16; off; off >>= 1) {
        dmin = fminf(dmin, __shfl_xor_sync(0xffffffffu, dmin, off));
        dmax = fmaxf(dmax, __shfl_xor_sync(0xffffffffu, dmax, off));
    }
    if ((threadIdx.x & 31) == 0) {
        atomicMin(&g_dmin_bits, __float_as_int(dmin));
        atomicMax(&g_dmax_bits, __float_as_int(dmax));
    }
}

// ---------------- kernel 4: model, warp per 16-sample group, tf32 mma MLP ----------------
// smem layout (float/uint32 units):
//   [0)     w1t : 96 x 72 (tf32, row stride 72)           = 6912
//   [6912)  w2t : 64 x 40 (tf32, stride 40, cols>=33 = 0) = 2560
//   [9472)  b1s : 64
//   [9536)  b2s : 40 (33 used, rest 0)
//   [9576)  wsig: 96
//   [9680)  xb  : 8 warps x 16 x 100 (stride 100)         = 12800
// total 22480 -> 89920 bytes
#define SM_W1T  0
#define SM_W2T  6912
#define SM_B1   9472
#define SM_B2   9536
#define SM_WSIG 9576
#define SM_XB   9680
#define SM_TOTAL_BYTES (22480*4)

extern __shared__ __align__(16) float smem[];

// axis prep: scaled coordinate -> weights + clamped indices (grid_sample border zeros)
struct Axis { float w0, w1; int i0, i1; };
__device__ __forceinline__ Axis axis_prep(float g) {
    Axis a;
    float x = (g + 1.0f) * 128.0f - 0.5f;
    float x0f = floorf(x);
    int x0 = (int)x0f;
    float w = x - x0f;
    bool v0 = (x0 >= 0) & (x0 < 256);
    bool v1 = (x0 >= -1) & (x0 < 255);
    a.w0 = v0 ? 1.0f - w : 0.0f;
    a.w1 = v1 ? w : 0.0f;
    a.i0 = min(max(x0, 0), 255);
    a.i1 = min(max(x0 + 1, 0), 255);
    return a;
}

__global__ void __launch_bounds__(256, 2) k_model(
    const float* __restrict__ ro, const float* __restrict__ rd,
    const float* __restrict__ weight,
    const float* __restrict__ w1, const float* __restrict__ b1,
    const float* __restrict__ w2, const float* __restrict__ b2,
    int fine_pass)
{
    uint32_t* w1t = (uint32_t*)(smem + SM_W1T);
    uint32_t* w2t = (uint32_t*)(smem + SM_W2T);
    float* b1s  = smem + SM_B1;
    float* b2s  = smem + SM_B2;
    float* wsig = smem + SM_WSIG;

    int tid = threadIdx.x;
    for (int i = tid; i < 96 * 64; i += 256) w1t[(i >> 6) * 72 + (i & 63)] = f2tf32(w1[i]);
    for (int i = tid; i < 64 * 40; i += 256) {
        int k = i / 40, n = i % 40;
        w2t[i] = (n < 33) ? f2tf32(w2[k * 33 + n]) : 0u;
    }
    if (tid < 64) b1s[tid] = b1[tid];
    if (tid < 40) b2s[tid] = (tid < 33) ? b2[tid] : 0.0f;
    if (tid < 96) wsig[tid] = sigmoidf(weight[tid]);
    __syncthreads();

    const float* depths = fine_pass ? g_depth_f : g_depth_c;
    float* cols = fine_pass ? g_col_f : g_col_c;
    float* sigs = fine_pass ? g_sig_f : g_sig_c;

    int lane = tid & 31, wrp = tid >> 5;
    int gq = lane >> 2, tq = lane & 3;
    uint32_t* xb  = (uint32_t*)(smem + SM_XB) + wrp * 1600;  // [16 rows][stride 100]
    float*    xbf = (float*)xb;

    float wk0 = wsig[lane], wk1 = wsig[32 + lane], wk2 = wsig[64 + lane];

    int g0 = blockIdx.x * 8 + wrp;
    int nG = gridDim.x * 8;

    for (int g = g0; g < NG16; g += nG) {
        int smp0 = g * 16;
        int ray = g / 3;              // 16*g/48
        int b = ray >> 12;
        float ox = ro[ray * 3 + 0], oy = ro[ray * 3 + 1], oz = ro[ray * 3 + 2];
        float dx = rd[ray * 3 + 0], dy = rd[ray * 3 + 1], dz = rd[ray * 3 + 2];
        const __half2* pb0 = (const __half2*)g_planes_h + (size_t)b * 3 * 65536 * 32 + (size_t)lane;
        const __half2* pb1 = pb0 + (size_t)65536 * 32;
        const __half2* pb2 = pb1 + (size_t)65536 * 32;

        float dval = depths[smp0 + (lane & 15)];

        // ---- phase A: gather 16 samples, lane = channel; tf32 into smem [s][k] ----
#pragma unroll 4
        for (int s = 0; s < 16; s++) {
            float d = __shfl_sync(0xffffffffu, dval, s);
            float cx = 2.0f * fmaf(d, dx, ox);
            float cy = 2.0f * fmaf(d, dy, oy);
            float cz = 2.0f * fmaf(d, dz, oz);
            Axis ax = axis_prep(cx);
            Axis ay = axis_prep(cy);
            Axis az = axis_prep(cz);
            float xv0, xv1, xv2;
            {   // plane 0: (ax, ay)
                float2 v00 = __half22float2(pb0[(ay.i0 * 256 + ax.i0) * 32]);
                float2 v01 = __half22float2(pb0[(ay.i0 * 256 + ax.i1) * 32]);
                float2 v10 = __half22float2(pb0[(ay.i1 * 256 + ax.i0) * 32]);
                float2 v11 = __half22float2(pb0[(ay.i1 * 256 + ax.i1) * 32]);
                float w00 = ax.w0 * ay.w0, w01 = ax.w1 * ay.w0;
                float w10 = ax.w0 * ay.w1, w11 = ax.w1 * ay.w1;
                float aF = fmaf(w11, v11.x, fmaf(w10, v10.x, fmaf(w01, v01.x, w00 * v00.x)));
                float aB = fmaf(w11, v11.y, fmaf(w10, v10.y, fmaf(w01, v01.y, w00 * v00.y)));
                xv0 = wk0 * aF + (1.0f - wk0) * aB;
            }
            {   // plane 1: (ax, az)
                float2 v00 = __half22float2(pb1[(az.i0 * 256 + ax.i0) * 32]);
                float2 v01 = __half22float2(pb1[(az.i0 * 256 + ax.i1) * 32]);
                float2 v10 = __half22float2(pb1[(az.i1 * 256 + ax.i0) * 32]);
                float2 v11 = __half22float2(pb1[(az.i1 * 256 + ax.i1) * 32]);
                float w00 = ax.w0 * az.w0, w01 = ax.w1 * az.w0;
                float w10 = ax.w0 * az.w1, w11 = ax.w1 * az.w1;
                float aF = fmaf(w11, v11.x, fmaf(w10, v10.x, fmaf(w01, v01.x, w00 * v00.x)));
                float aB = fmaf(w11, v11.y, fmaf(w10, v10.y, fmaf(w01, v01.y, w00 * v00.y)));
                xv1 = wk1 * aF + (1.0f - wk1) * aB;
            }
            {   // plane 2: (az, ax)
                float2 v00 = __half22float2(pb2[(ax.i0 * 256 + az.i0) * 32]);
                float2 v01 = __half22float2(pb2[(ax.i0 * 256 + az.i1) * 32]);
                float2 v10 = __half22float2(pb2[(ax.i1 * 256 + az.i0) * 32]);
                float2 v11 = __half22float2(pb2[(ax.i1 * 256 + az.i1) * 32]);
                float w00 = az.w0 * ax.w0, w01 = az.w1 * ax.w0;
                float w10 = az.w0 * ax.w1, w11 = az.w1 * ax.w1;
                float aF = fmaf(w11, v11.x, fmaf(w10, v10.x, fmaf(w01, v01.x, w00 * v00.x)));
                float aB = fmaf(w11, v11.y, fmaf(w10, v10.y, fmaf(w01, v01.y, w00 * v00.y)));
                xv2 = wk2 * aF + (1.0f - wk2) * aB;
            }
            xb[s * 100 + lane]      = f2tf32(xv0);
            xb[s * 100 + 32 + lane] = f2tf32(xv1);
            xb[s * 100 + 64 + lane] = f2tf32(xv2);
        }
        __syncwarp();

        // ---- layer1: [16x96] @ [96x64] via m16n8k8 tf32 ----
        float d1[8][4];
#pragma unroll
        for (int nt = 0; nt < 8; nt++) {
            float bl = b1s[nt * 8 + 2 * tq], bh = b1s[nt * 8 + 2 * tq + 1];
            d1[nt][0] = bl; d1[nt][1] = bh; d1[nt][2] = bl; d1[nt][3] = bh;
        }
#pragma unroll
        for (int kt = 0; kt < 12; kt++) {
            int k0 = kt * 8;
            uint32_t a0 = xb[gq * 100 + k0 + tq];
            uint32_t a1 = xb[(gq + 8) * 100 + k0 + tq];
            uint32_t a2 = xb[gq * 100 + k0 + tq + 4];
            uint32_t a3 = xb[(gq + 8) * 100 + k0 + tq + 4];
#pragma unroll
            for (int nt = 0; nt < 8; nt++) {
                uint32_t bv0 = w1t[(k0 + tq) * 72 + nt * 8 + gq];
                uint32_t bv1 = w1t[(k0 + tq + 4) * 72 + nt * 8 + gq];
                mma_tf32(d1[nt][0], d1[nt][1], d1[nt][2], d1[nt][3], a0, a1, a2, a3, bv0, bv1);
            }
        }
        __syncwarp();
        // softplus -> h (tf32) back into xb
#pragma unroll
        for (int nt = 0; nt < 8; nt++) {
            xb[gq * 100 + nt * 8 + 2 * tq]           = f2tf32(softplusf(d1[nt][0]));
            xb[gq * 100 + nt * 8 + 2 * tq + 1]       = f2tf32(softplusf(d1[nt][1]));
            xb[(gq + 8) * 100 + nt * 8 + 2 * tq]     = f2tf32(softplusf(d1[nt][2]));
            xb[(gq + 8) * 100 + nt * 8 + 2 * tq + 1] = f2tf32(softplusf(d1[nt][3]));
        }
        __syncwarp();

        // ---- layer2: [16x64] @ [64x40] ----
        float d2[5][4];
#pragma unroll
        for (int nt = 0; nt < 5; nt++) {
            float bl = b2s[nt * 8 + 2 * tq], bh = b2s[nt * 8 + 2 * tq + 1];
            d2[nt][0] = bl; d2[nt][1] = bh; d2[nt][2] = bl; d2[nt][3] = bh;
        }
#pragma unroll
        for (int kt = 0; kt < 8; kt++) {
            int k0 = kt * 8;
            uint32_t a0 = xb[gq * 100 + k0 + tq];
            uint32_t a1 = xb[(gq + 8) * 100 + k0 + tq];
            uint32_t a2 = xb[gq * 100 + k0 + tq + 4];
            uint32_t a3 = xb[(gq + 8) * 100 + k0 + tq + 4];
#pragma unroll
            for (int nt = 0; nt < 5; nt++) {
                uint32_t bv0 = w2t[(k0 + tq) * 40 + nt * 8 + gq];
                uint32_t bv1 = w2t[(k0 + tq + 4) * 40 + nt * 8 + gq];
                mma_tf32(d2[nt][0], d2[nt][1], d2[nt][2], d2[nt][3], a0, a1, a2, a3, bv0, bv1);
            }
        }
        __syncwarp();
        // out [16][40] into xb (raw fp32)
#pragma unroll
        for (int nt = 0; nt < 5; nt++) {
            xbf[gq * 100 + nt * 8 + 2 * tq]           = d2[nt][0];
            xbf[gq * 100 + nt * 8 + 2 * tq + 1]       = d2[nt][1];
            xbf[(gq + 8) * 100 + nt * 8 + 2 * tq]     = d2[nt][2];
            xbf[(gq + 8) * 100 + nt * 8 + 2 * tq + 1] = d2[nt][3];
        }
        __syncwarp();

        // rgb (cols 1..32) coalesced; sigma (col 0)
#pragma unroll 4
        for (int s = 0; s < 16; s++) {
            float v = xbf[s * 100 + 1 + lane];
            cols[(size_t)(smp0 + s) * 32 + lane] = sigmoidf(v) * 1.002f - 0.001f;
        }
        if (lane < 16) sigs[smp0 + lane] = xbf[lane * 100];
        __syncwarp();
    }
}

// ---------------- kernel 5: coarse ray-march weights ----------------
__global__ void k_coarse_weights() {
    int ray = blockIdx.x * blockDim.x + threadIdx.x;
    if (ray >= NRAY) return;
    float T = 1.0f;
    float zp = g_depth_c[ray * Ss];
    float sp = g_sig_c[ray * Ss];
    for (int s = 1; s < Ss; s++) {
        float z = g_depth_c[ray * Ss + s];
        float sg = g_sig_c[ray * Ss + s];
        float dens = softplusf(0.5f * (sp + sg) - 1.0f);
        float alpha = 1.0f - expf(-dens * (z - zp));
        g_wc[ray * 47 + s - 1] = alpha * T;
        T *= (1.0f - alpha + 1e-10f);
        zp = z; sp = sg;
    }
}

// ---------------- kernel 6: importance sampling (fine depths), smem-resident ----------------
#define FD_T 64
__global__ void __launch_bounds__(FD_T) k_fine_depths() {
    __shared__ float zm_s[FD_T][49];
    __shared__ float cdf_s[FD_T][47];
    int t = threadIdx.x;
    int ray = blockIdx.x * FD_T + t;
    float* zm  = zm_s[t];
    float* cdf = cdf_s[t];
    const float* zrow = g_depth_c + ray * 48;
    const float* wrow = g_wc + ray * 47;

    float zprev = zrow[0];
    for (int i = 0; i < 47; i++) {
        float z = zrow[i + 1];
        zm[i] = 0.5f * (zprev + z);
        zprev = z;
    }
    float sum = 0.0f;
    for (int j = 0; j < 45; j++) {
        int i = j + 1;
        float wim1 = wrow[i - 1], wi = wrow[i], wip1 = wrow[i + 1];
        float wmi  = fmaxf(wim1, wi);
        float wmi1 = fmaxf(wi, wip1);
        float wsj = 0.5f * (wmi + wmi1) + 0.01f + 1e-5f;
        cdf[j + 1] = wsj;
        sum += wsj;
    }
    cdf[0] = 0.0f;
    float run = 0.0f;
    for (int j = 0; j < 45; j++) {
        run += cdf[j + 1] / sum;
        cdf[j + 1] = run;
    }

    uint32_t ka, kb; derive_key(1u, ka, kb);
    for (int j = 0; j < 48; j++) {
        float u = tf_uniform(ka, kb, (uint32_t)(ray * 48 + j));
        int pos = 0;
#pragma unroll
        for (int step = 32; step; step >>= 1) {
            int np = pos + step;
            if (np <= 46 && cdf[np - 1] <= u) pos = np;
        }
        int ind = pos;
        int below = ind - 1; if (below < 0) below = 0;
        int above = ind;     if (above > 45) above = 45;
        float c0 = cdf[below], c1 = cdf[above];
        float b0 = zm[below],  b1v = zm[above];
        float denom = c1 - c0;
        if (denom < 1e-5f) denom = 1.0f;
        g_depth_f[ray * 48 + j] = b0 + (u - c0) / denom * (b1v - b0);
    }
}

// ---------------- kernel 7: unify + final march, warp per ray ----------------
__global__ void __launch_bounds__(256) k_final(
    const float* __restrict__ ro, const float* __restrict__ rd,
    float* __restrict__ out)
{
    __shared__ __align__(16) float sd[8][96];
    __shared__ __align__(16) float ssg[8][96];
    __shared__ __align__(16) int   sidx[8][96];
    int lane = threadIdx.x & 31, wrp = threadIdx.x >> 5;
    int ray = blockIdx.x * 8 + wrp;

    for (int i = lane; i < 48; i += 32) {
        sd[wrp][i]       = g_depth_c[ray * 48 + i];
        sd[wrp][48 + i]  = g_depth_f[ray * 48 + i];
        ssg[wrp][i]      = g_sig_c[ray * 48 + i];
        ssg[wrp][48 + i] = g_sig_f[ray * 48 + i];
    }
    __syncwarp();
#pragma unroll
    for (int t = 0; t < 3; t++) {
        int e = lane + t * 32;
        float de = sd[wrp][e];
        int rank = 0;
        for (int j = 0; j < 96; j++) {
            float dj = sd[wrp][j];
            rank += (dj < de || (dj == de && j < e)) ? 1 : 0;
        }
        sidx[wrp][rank] = e;
    }
    __syncwarp();

    float T = 1.0f, accW = 0.0f, accWD = 0.0f, accC = 0.0f;
    int i0 = sidx[wrp][0];
    float dp = sd[wrp][i0], sp = ssg[wrp][i0];
    const float* cb0 = (i0 < 48) ? g_col_c : g_col_f;
    float cp = cb0[((size_t)ray * 48 + (i0 < 48 ? i0 : i0 - 48)) * 32 + lane];

    for (int s = 1; s < 96; s++) {
        int i = sidx[wrp][s];
        float dc = sd[wrp][i], sc = ssg[wrp][i];
        const float* cb = (i < 48) ? g_col_c : g_col_f;
        float cc = cb[((size_t)ray * 48 + (i < 48 ? i : i - 48)) * 32 + lane];
        float delta = dc - dp;
        float dens = softplusf(0.5f * (sc + sp) - 1.0f);
        float alpha = 1.0f - expf(-dens * delta);
        float wgt = alpha * T;
        T *= (1.0f - alpha + 1e-10f);
        accC  += wgt * 0.5f * (cc + cp);
        accW  += wgt;
        accWD += wgt * 0.5f * (dc + dp);
        dp = dc; sp = sc; cp = cc;
    }

    out[OUT_RGB + (size_t)ray * 32 + lane] = accC * 2.0f - 1.0f;
    if (lane == 0) {
        float wt = accW;
        float dep = accWD / wt;
        if (isnan(dep)) dep = __int_as_float(0x7f800000);
        float dmin = __int_as_float(g_dmin_bits);
        float dmax = __int_as_float(g_dmax_bits);
        dep = fminf(fmaxf(dep, dmin), dmax);
        out[OUT_DEPTH + ray] = dep;
        out[OUT_WT + ray] = wt;
    }
    if (lane < 3) {
        float o_ = ro[ray * 3 + lane], d_ = rd[ray * 3 + lane];
        out[OUT_XYZ + (size_t)ray * 3 + lane] = 2.0f * (o_ * accW + d_ * accWD) - 1.0f;
    }
}

// ---------------- launcher ----------------
extern "C" void kernel_launch(void* const* d_in, const int* in_sizes, int n_in,
                              void* d_out, int out_size) {
    const float* front  = (const float*)d_in[0];
    const float* back   = (const float*)d_in[1];
    const float* ro     = (const float*)d_in[2];
    const float* rd     = (const float*)d_in[3];
    const float* weight = (const float*)d_in[4];
    const float* w1     = (const float*)d_in[5];
    const float* b1     = (const float*)d_in[6];
    const float* w2     = (const float*)d_in[7];
    const float* b2     = (const float*)d_in[8];
    float* out = (float*)d_out;

    cudaFuncSetAttribute(k_model, cudaFuncAttributeMaxDynamicSharedMemorySize, SM_TOTAL_BYTES);

    k_init<<<1, 1>>>();
    k_transpose<<<dim3(8, 256, 6), dim3(32, 8)>>>(front, back);
    k_depth_coarse<<<(NSAMP + 255) / 256, 256>>>();
    k_model<<<296, 256, SM_TOTAL_BYTES>>>(ro, rd, weight, w1, b1, w2, b2, 0);
    k_coarse_weights<<<NRAY / 256, 256>>>();
    k_fine_depths<<<NRAY / FD_T, FD_T>>>();
    k_minmax<<<NRAY / 256, 256>>>();
    k_model<<<296, 256, SM_TOTAL_BYTES>>>(ro, rd, weight, w1, b1, w2, b2, 1);
    k_final<<<NRAY / 8, 256>>>(ro, rd, out);
    (void)in_sizes; (void)n_in; (void)out_size;
}

// round 8
// speedup vs baseline: 3.3609x; 1.3472x over previous
#include <cuda_runtime.h>
#include <cuda_fp16.h>
#include <cstdint>
#include <math.h>

// ---------------- problem constants ----------------
#define Bb 2
#define Rr 4096
#define Ss 48
#define NRAY   (Bb*Rr)        // 8192
#define NSAMP  (NRAY*Ss)      // 393216
#define NG16   (NSAMP/16)     // 24576

#define RAY_START 2.25f
#define STEPF 0.0223404255319148936f  // (3.3-2.25)/47

#define OUT_RGB   0
#define OUT_DEPTH 262144
#define OUT_WT    270336
#define OUT_XYZ   278528

// ---------------- scratch ----------------
__device__ __half g_planes_h[(size_t)Bb*3*256*256*64];
__device__ float g_depth_c[NSAMP];
__device__ float g_depth_f[NSAMP];
__device__ float g_col_c[(size_t)NSAMP*32];
__device__ float g_col_f[(size_t)NSAMP*32];
__device__ float g_sig_c[NSAMP];
__device__ float g_sig_f[NSAMP];
__device__ int   g_dmin_bits;
__device__ int   g_dmax_bits;

// ---------------- math helpers ----------------
__device__ __forceinline__ float softplusf(float x) {            // precise (ray-march)
    return fmaxf(x, 0.0f) + log1pf(expf(-fabsf(x)));
}
__device__ __forceinline__ float softplus_fast(float x) {        // model epilogue
    return fmaxf(x, 0.0f) + __logf(1.0f + __expf(-fabsf(x)));
}
__device__ __forceinline__ float sigmoid_fast(float x) {
    return __fdividef(1.0f, 1.0f + __expf(-x));
}

__device__ __forceinline__ uint32_t smaddr(const void* p) {
    return (uint32_t)__cvta_generic_to_shared(p);
}
__device__ __forceinline__ void ldsm_x4(uint32_t& r0, uint32_t& r1, uint32_t& r2, uint32_t& r3, uint32_t a) {
    asm volatile("ldmatrix.sync.aligned.m8n8.x4.shared.b16 {%0,%1,%2,%3}, [%4];"
                 : "=r"(r0), "=r"(r1), "=r"(r2), "=r"(r3) : "r"(a));
}
__device__ __forceinline__ void ldsm_x2(uint32_t& r0, uint32_t& r1, uint32_t a) {
    asm volatile("ldmatrix.sync.aligned.m8n8.x2.shared.b16 {%0,%1}, [%2];"
                 : "=r"(r0), "=r"(r1) : "r"(a));
}
__device__ __forceinline__ void mma_f16(float& d0, float& d1, float& d2, float& d3,
                                        uint32_t a0, uint32_t a1, uint32_t a2, uint32_t a3,
                                        uint32_t b0, uint32_t b1) {
    asm volatile(
        "mma.sync.aligned.m16n8k16.row.col.f32.f16.f16.f32 "
        "{%0,%1,%2,%3}, {%4,%5,%6,%7}, {%8,%9}, {%0,%1,%2,%3};"
        : "+f"(d0), "+f"(d1), "+f"(d2), "+f"(d3)
        : "r"(a0), "r"(a1), "r"(a2), "r"(a3), "r"(b0), "r"(b1));
}

// ---------------- Threefry-2x32 (JAX, partitionable variant) ----------------
__device__ __forceinline__ uint32_t rotl32(uint32_t x, int r) {
    return (x << r) | (x >> (32 - r));
}
__device__ __forceinline__ void tf2x32(uint32_t k0, uint32_t k1,
                                       uint32_t x0, uint32_t x1,
                                       uint32_t& o0, uint32_t& o1) {
    uint32_t ks2 = k0 ^ k1 ^ 0x1BD11BDAu;
    x0 += k0; x1 += k1;
#define TFR(r) { x0 += x1; x1 = rotl32(x1, r); x1 ^= x0; }
    TFR(13) TFR(15) TFR(26) TFR(6)  x0 += k1;  x1 += ks2 + 1u;
    TFR(17) TFR(29) TFR(16) TFR(24) x0 += ks2; x1 += k0 + 2u;
    TFR(13) TFR(15) TFR(26) TFR(6)  x0 += k0;  x1 += k1 + 3u;
    TFR(17) TFR(29) TFR(16) TFR(24) x0 += k1;  x1 += ks2 + 4u;
    TFR(13) TFR(15) TFR(26) TFR(6)  x0 += ks2; x1 += k0 + 5u;
#undef TFR
    o0 = x0; o1 = x1;
}
__device__ __forceinline__ void derive_key(uint32_t idx, uint32_t& ka, uint32_t& kb) {
    tf2x32(0u, 42u, 0u, idx, ka, kb);
}
__device__ __forceinline__ float tf_uniform(uint32_t ka, uint32_t kb, uint32_t i) {
    uint32_t o0, o1;
    tf2x32(ka, kb, 0u, i, o0, o1);
    uint32_t bits = o0 ^ o1;
    float f = __uint_as_float((bits >> 9) | 0x3f800000u) - 1.0f;
    return fmaxf(f, 0.0f);
}

// ---------------- kernel 0 ----------------
__global__ void k_init() {
    g_dmin_bits = 0x7f800000;
    g_dmax_bits = 0x00000000;
}

// ---------------- kernel 1: transpose planes to channel-last fp16 ----------------
__global__ void k_transpose(const float* __restrict__ front, const float* __restrict__ back) {
    __shared__ float tf[32][33];
    __shared__ float tb[32][33];
    int bp = blockIdx.z;
    int y  = blockIdx.y;
    int x0 = blockIdx.x * 32;
    int tx = threadIdx.x, ty = threadIdx.y;
    __half2* out = (__half2*)g_planes_h;
#pragma unroll
    for (int i = 0; i < 4; i++) {
        int c = ty + i * 8;
        size_t src = ((size_t)(bp * 32 + c) * 65536) + (size_t)y * 256 + x0 + tx;
        tf[c][tx] = front[src];
        tb[c][tx] = back[src];
    }
    __syncthreads();
#pragma unroll
    for (int i = 0; i < 4; i++) {
        int xx = ty + i * 8;
        out[(((size_t)bp * 65536) + (size_t)y * 256 + x0 + xx) * 32 + tx] =
            __floats2half2_rn(tf[tx][xx], tb[tx][xx]);
    }
}

// ---------------- kernel 2: coarse stratified depths ----------------
__global__ void k_depth_coarse() {
    int i = blockIdx.x * blockDim.x + threadIdx.x;
    if (i >= NSAMP) return;
    uint32_t ka, kb; derive_key(0u, ka, kb);
    float u = tf_uniform(ka, kb, (uint32_t)i);
    int s = i % Ss;
    float d0 = RAY_START + (float)s * STEPF;
    g_depth_c[i] = d0 + u * STEPF;
}

// ---------------- kernel 3: global depth min/max ----------------
__global__ void k_minmax() {
    int ray = blockIdx.x * blockDim.x + threadIdx.x;
    float dmin = g_depth_c[ray * Ss];
    float dmax = g_depth_c[ray * Ss + Ss - 1];
#pragma unroll
    for (int off = 16; off; off >>= 1) {
        dmin = fminf(dmin, __shfl_xor_sync(0xffffffffu, dmin, off));
        dmax = fmaxf(dmax, __shfl_xor_sync(0xffffffffu, dmax, off));
    }
    if ((threadIdx.x & 31) == 0) {
        atomicMin(&g_dmin_bits, __float_as_int(dmin));
        atomicMax(&g_dmax_bits, __float_as_int(dmax));
    }
}

// ---------------- kernel 4: model, warp per 16-sample group, fp16 mma MLP ----------------
// smem float-offsets:
//   w1h : 64 n x 104 k halves  = 3328 floats
//   w2h : 40 n x  72 k halves  = 1440 floats
//   b1s : 64, b2s : 40, wsig : 96
//   xb  : 8 warps x 16 x 104 halves (832 floats/warp)  [also reused as 16x44 float out]
//   hb  : 8 warps x 16 x  72 halves (576 floats/warp)
#define SM_W1H  0
#define SM_W2H  3328
#define SM_B1   4768
#define SM_B2   4832
#define SM_WSIG 4872
#define SM_XB   4968
#define SM_HB   11624
#define SM_TOTAL_BYTES ((11624 + 4608) * 4)

extern __shared__ __align__(16) float smem[];

struct Axis { float w0, w1; int i0, i1; };
__device__ __forceinline__ Axis axis_prep(float g) {
    Axis a;
    float x = (g + 1.0f) * 128.0f - 0.5f;
    float x0f = floorf(x);
    int x0 = (int)x0f;
    float w = x - x0f;
    bool v0 = (x0 >= 0) & (x0 < 256);
    bool v1 = (x0 >= -1) & (x0 < 255);
    a.w0 = v0 ? 1.0f - w : 0.0f;
    a.w1 = v1 ? w : 0.0f;
    a.i0 = min(max(x0, 0), 255);
    a.i1 = min(max(x0 + 1, 0), 255);
    return a;
}

__global__ void __launch_bounds__(256, 3) k_model(
    const float* __restrict__ ro, const float* __restrict__ rd,
    const float* __restrict__ weight,
    const float* __restrict__ w1, const float* __restrict__ b1,
    const float* __restrict__ w2, const float* __restrict__ b2,
    int fine_pass)
{
    __half* w1h = (__half*)(smem + SM_W1H);
    __half* w2h = (__half*)(smem + SM_W2H);
    float* b1s  = smem + SM_B1;
    float* b2s  = smem + SM_B2;
    float* wsig = smem + SM_WSIG;

    int tid = threadIdx.x;
    for (int i = tid; i < 96 * 64; i += 256) {
        int k = i >> 6, n = i & 63;
        w1h[n * 104 + k] = __float2half(w1[i]);
    }
    for (int i = tid; i < 64 * 40; i += 256) {
        int k = i / 40, n = i % 40;
        w2h[n * 72 + k] = (n < 33) ? __float2half(w2[k * 33 + n]) : __half(0.0f);
    }
    if (tid < 64) b1s[tid] = b1[tid];
    if (tid < 40) b2s[tid] = (tid < 33) ? b2[tid] : 0.0f;
    if (tid < 96) wsig[tid] = 1.0f / (1.0f + expf(-weight[tid]));
    __syncthreads();

    const float* depths = fine_pass ? g_depth_f : g_depth_c;
    float* cols = fine_pass ? g_col_f : g_col_c;
    float* sigs = fine_pass ? g_sig_f : g_sig_c;

    int lane = tid & 31, wrp = tid >> 5;
    int tq = lane & 3;
    __half* xh = (__half*)(smem + SM_XB) + wrp * 1664;   // [16][104]
    __half* hh = (__half*)(smem + SM_HB) + wrp * 1152;   // [16][72]
    float*  outf = (float*)xh;                           // reuse as [16][44] float

    // ldmatrix lane base addresses
    uint32_t a_x = smaddr(xh) + (((lane & 15) * 104 + ((lane >> 4) * 8)) * 2);
    uint32_t a_h = smaddr(hh) + (((lane & 15) * 72  + ((lane >> 4) * 8)) * 2);
    uint32_t b_w1 = smaddr(w1h) + (((lane & 7) * 104 + (((lane >> 3) & 1) * 8)) * 2);
    uint32_t b_w2 = smaddr(w2h) + (((lane & 7) * 72  + (((lane >> 3) & 1) * 8)) * 2);

    float wk0 = wsig[lane], wk1 = wsig[32 + lane], wk2 = wsig[64 + lane];

    int g0 = blockIdx.x * 8 + wrp;
    int nG = gridDim.x * 8;

    for (int g = g0; g < NG16; g += nG) {
        int smp0 = g * 16;
        int ray = g / 3;              // 3 groups per ray
        int b = ray >> 12;
        float ox = ro[ray * 3 + 0], oy = ro[ray * 3 + 1], oz = ro[ray * 3 + 2];
        float dx = rd[ray * 3 + 0], dy = rd[ray * 3 + 1], dz = rd[ray * 3 + 2];
        const __half2* pb0 = (const __half2*)g_planes_h + (size_t)b * 3 * 65536 * 32 + (size_t)lane;
        const __half2* pb1 = pb0 + (size_t)65536 * 32;
        const __half2* pb2 = pb1 + (size_t)65536 * 32;

        float dval = depths[smp0 + (lane & 15)];

        // ---- phase A: gather 16 samples, lane = channel ----
#pragma unroll 4
        for (int s = 0; s < 16; s++) {
            float d = __shfl_sync(0xffffffffu, dval, s);
            float cx = 2.0f * fmaf(d, dx, ox);
            float cy = 2.0f * fmaf(d, dy, oy);
            float cz = 2.0f * fmaf(d, dz, oz);
            Axis ax = axis_prep(cx);
            Axis ay = axis_prep(cy);
            Axis az = axis_prep(cz);
            float xv0, xv1, xv2;
            {
                float2 v00 = __half22float2(pb0[(ay.i0 * 256 + ax.i0) * 32]);
                float2 v01 = __half22float2(pb0[(ay.i0 * 256 + ax.i1) * 32]);
                float2 v10 = __half22float2(pb0[(ay.i1 * 256 + ax.i0) * 32]);
                float2 v11 = __half22float2(pb0[(ay.i1 * 256 + ax.i1) * 32]);
                float w00 = ax.w0 * ay.w0, w01 = ax.w1 * ay.w0;
                float w10 = ax.w0 * ay.w1, w11 = ax.w1 * ay.w1;
                float aF = fmaf(w11, v11.x, fmaf(w10, v10.x, fmaf(w01, v01.x, w00 * v00.x)));
                float aB = fmaf(w11, v11.y, fmaf(w10, v10.y, fmaf(w01, v01.y, w00 * v00.y)));
                xv0 = wk0 * aF + (1.0f - wk0) * aB;
            }
            {
                float2 v00 = __half22float2(pb1[(az.i0 * 256 + ax.i0) * 32]);
                float2 v01 = __half22float2(pb1[(az.i0 * 256 + ax.i1) * 32]);
                float2 v10 = __half22float2(pb1[(az.i1 * 256 + ax.i0) * 32]);
                float2 v11 = __half22float2(pb1[(az.i1 * 256 + ax.i1) * 32]);
                float w00 = ax.w0 * az.w0, w01 = ax.w1 * az.w0;
                float w10 = ax.w0 * az.w1, w11 = ax.w1 * az.w1;
                float aF = fmaf(w11, v11.x, fmaf(w10, v10.x, fmaf(w01, v01.x, w00 * v00.x)));
                float aB = fmaf(w11, v11.y, fmaf(w10, v10.y, fmaf(w01, v01.y, w00 * v00.y)));
                xv1 = wk1 * aF + (1.0f - wk1) * aB;
            }
            {
                float2 v00 = __half22float2(pb2[(ax.i0 * 256 + az.i0) * 32]);
                float2 v01 = __half22float2(pb2[(ax.i0 * 256 + az.i1) * 32]);
                float2 v10 = __half22float2(pb2[(ax.i1 * 256 + az.i0) * 32]);
                float2 v11 = __half22float2(pb2[(ax.i1 * 256 + az.i1) * 32]);
                float w00 = az.w0 * ax.w0, w01 = az.w1 * ax.w0;
                float w10 = az.w0 * ax.w1, w11 = az.w1 * ax.w1;
                float aF = fmaf(w11, v11.x, fmaf(w10, v10.x, fmaf(w01, v01.x, w00 * v00.x)));
                float aB = fmaf(w11, v11.y, fmaf(w10, v10.y, fmaf(w01, v01.y, w00 * v00.y)));
                xv2 = wk2 * aF + (1.0f - wk2) * aB;
            }
            xh[s * 104 + lane]      = __float2half(xv0);
            xh[s * 104 + 32 + lane] = __float2half(xv1);
            xh[s * 104 + 64 + lane] = __float2half(xv2);
        }
        __syncwarp();

        // ---- layer1: [16x96] @ [96x64], fp16 mma, n split in halves ----
#pragma unroll
        for (int hn = 0; hn < 2; hn++) {
            float d1[4][4];
#pragma unroll
            for (int nt2 = 0; nt2 < 4; nt2++) {
                int nt = hn * 4 + nt2;
                float bl = b1s[nt * 8 + 2 * tq], bh = b1s[nt * 8 + 2 * tq + 1];
                d1[nt2][0] = bl; d1[nt2][1] = bh; d1[nt2][2] = bl; d1[nt2][3] = bh;
            }
#pragma unroll
            for (int kt = 0; kt < 6; kt++) {
                uint32_t a0, a1, a2, a3;
                ldsm_x4(a0, a1, a2, a3, a_x + kt * 32);
#pragma unroll
                for (int nt2 = 0; nt2 < 4; nt2++) {
                    int nt = hn * 4 + nt2;
                    uint32_t bv0, bv1;
                    ldsm_x2(bv0, bv1, b_w1 + nt * 1664 + kt * 32);
                    mma_f16(d1[nt2][0], d1[nt2][1], d1[nt2][2], d1[nt2][3], a0, a1, a2, a3, bv0, bv1);
                }
            }
            int gq = lane >> 2;
#pragma unroll
            for (int nt2 = 0; nt2 < 4; nt2++) {
                int nt = hn * 4 + nt2;
                *(__half2*)(hh + gq * 72 + nt * 8 + 2 * tq) =
                    __floats2half2_rn(softplus_fast(d1[nt2][0]), softplus_fast(d1[nt2][1]));
                *(__half2*)(hh + (gq + 8) * 72 + nt * 8 + 2 * tq) =
                    __floats2half2_rn(softplus_fast(d1[nt2][2]), softplus_fast(d1[nt2][3]));
            }
        }
        __syncwarp();

        // ---- layer2: [16x64] @ [64x40] ----
        float d2[5][4];
#pragma unroll
        for (int nt = 0; nt < 5; nt++) {
            float bl = b2s[nt * 8 + 2 * tq], bh = b2s[nt * 8 + 2 * tq + 1];
            d2[nt][0] = bl; d2[nt][1] = bh; d2[nt][2] = bl; d2[nt][3] = bh;
        }
#pragma unroll
        for (int kt = 0; kt < 4; kt++) {
            uint32_t a0, a1, a2, a3;
            ldsm_x4(a0, a1, a2, a3, a_h + kt * 32);
#pragma unroll
            for (int nt = 0; nt < 5; nt++) {
                uint32_t bv0, bv1;
                ldsm_x2(bv0, bv1, b_w2 + nt * 1152 + kt * 32);
                mma_f16(d2[nt][0], d2[nt][1], d2[nt][2], d2[nt][3], a0, a1, a2, a3, bv0, bv1);
            }
        }
        __syncwarp();
        {
            int gq = lane >> 2;
#pragma unroll
            for (int nt = 0; nt < 5; nt++) {
                *(float2*)(outf + gq * 44 + nt * 8 + 2 * tq)       = make_float2(d2[nt][0], d2[nt][1]);
                *(float2*)(outf + (gq + 8) * 44 + nt * 8 + 2 * tq) = make_float2(d2[nt][2], d2[nt][3]);
            }
        }
        __syncwarp();

        // rgb (cols 1..32) coalesced; sigma (col 0)
#pragma unroll 4
        for (int s = 0; s < 16; s++) {
            float v = outf[s * 44 + 1 + lane];
            cols[(size_t)(smp0 + s) * 32 + lane] = sigmoid_fast(v) * 1.002f - 0.001f;
        }
        if (lane < 16) sigs[smp0 + lane] = outf[lane * 44];
        __syncwarp();
    }
}

// ---------------- kernel 5: fused coarse weights + importance sampling ----------------
#define FD_T 64
__global__ void __launch_bounds__(FD_T) k_fine() {
    __shared__ float zm_s[FD_T][49];
    __shared__ float cdf_s[FD_T][47];
    __shared__ float w_s[FD_T][49];
    int t = threadIdx.x;
    int ray = blockIdx.x * FD_T + t;
    float* zm  = zm_s[t];
    float* cdf = cdf_s[t];
    float* wrow = w_s[t];
    const float* zrow = g_depth_c + ray * 48;
    const float* srow = g_sig_c + ray * 48;

    // coarse ray-march weights (w[0..46]) + midpoints
    {
        float T = 1.0f;
        float zp = zrow[0];
        float sp = srow[0];
        for (int s = 1; s < 48; s++) {
            float z = zrow[s];
            float sg = srow[s];
            float dens = softplusf(0.5f * (sp + sg) - 1.0f);
            float alpha = 1.0f - expf(-dens * (z - zp));
            wrow[s - 1] = alpha * T;
            zm[s - 1] = 0.5f * (zp + z);
            T *= (1.0f - alpha + 1e-10f);
            zp = z; sp = sg;
        }
    }

    float sum = 0.0f;
    for (int j = 0; j < 45; j++) {
        int i = j + 1;
        float wim1 = wrow[i - 1], wi = wrow[i], wip1 = wrow[i + 1];
        float wmi  = fmaxf(wim1, wi);
        float wmi1 = fmaxf(wi, wip1);
        float wsj = 0.5f * (wmi + wmi1) + 0.01f + 1e-5f;
        cdf[j + 1] = wsj;
        sum += wsj;
    }
    cdf[0] = 0.0f;
    float run = 0.0f;
    for (int j = 0; j < 45; j++) {
        run += cdf[j + 1] / sum;
        cdf[j + 1] = run;
    }

    uint32_t ka, kb; derive_key(1u, ka, kb);
    for (int j = 0; j < 48; j++) {
        float u = tf_uniform(ka, kb, (uint32_t)(ray * 48 + j));
        int pos = 0;
#pragma unroll
        for (int step = 32; step; step >>= 1) {
            int np = pos + step;
            if (np <= 46 && cdf[np - 1] <= u) pos = np;
        }
        int ind = pos;
        int below = ind - 1; if (below < 0) below = 0;
        int above = ind;     if (above > 45) above = 45;
        float c0 = cdf[below], c1 = cdf[above];
        float b0 = zm[below],  b1v = zm[above];
        float denom = c1 - c0;
        if (denom < 1e-5f) denom = 1.0f;
        g_depth_f[ray * 48 + j] = b0 + (u - c0) / denom * (b1v - b0);
    }
}

// ---------------- kernel 6: unify + final march, warp per ray ----------------
__global__ void __launch_bounds__(256) k_final(
    const float* __restrict__ ro, const float* __restrict__ rd,
    float* __restrict__ out)
{
    __shared__ __align__(16) float sd[8][96];
    __shared__ __align__(16) float ssg[8][96];
    __shared__ __align__(16) int   sidx[8][96];
    int lane = threadIdx.x & 31, wrp = threadIdx.x >> 5;
    int ray = blockIdx.x * 8 + wrp;

    for (int i = lane; i < 48; i += 32) {
        sd[wrp][i]       = g_depth_c[ray * 48 + i];
        sd[wrp][48 + i]  = g_depth_f[ray * 48 + i];
        ssg[wrp][i]      = g_sig_c[ray * 48 + i];
        ssg[wrp][48 + i] = g_sig_f[ray * 48 + i];
    }
    __syncwarp();
#pragma unroll
    for (int t = 0; t < 3; t++) {
        int e = lane + t * 32;
        float de = sd[wrp][e];
        int rank = 0;
        for (int j = 0; j < 96; j++) {
            float dj = sd[wrp][j];
            rank += (dj < de || (dj == de && j < e)) ? 1 : 0;
        }
        sidx[wrp][rank] = e;
    }
    __syncwarp();

    float T = 1.0f, accW = 0.0f, accWD = 0.0f, accC = 0.0f;
    int i0 = sidx[wrp][0];
    float dp = sd[wrp][i0], sp = ssg[wrp][i0];
    const float* cb0 = (i0 < 48) ? g_col_c : g_col_f;
    float cp = cb0[((size_t)ray * 48 + (i0 < 48 ? i0 : i0 - 48)) * 32 + lane];

    for (int s = 1; s < 96; s++) {
        int i = sidx[wrp][s];
        float dc = sd[wrp][i], sc = ssg[wrp][i];
        const float* cb = (i < 48) ? g_col_c : g_col_f;
        float cc = cb[((size_t)ray * 48 + (i < 48 ? i : i - 48)) * 32 + lane];
        float delta = dc - dp;
        float dens = softplusf(0.5f * (sc + sp) - 1.0f);
        float alpha = 1.0f - expf(-dens * delta);
        float wgt = alpha * T;
        T *= (1.0f - alpha + 1e-10f);
        accC  += wgt * 0.5f * (cc + cp);
        accW  += wgt;
        accWD += wgt * 0.5f * (dc + dp);
        dp = dc; sp = sc; cp = cc;
    }

    out[OUT_RGB + (size_t)ray * 32 + lane] = accC * 2.0f - 1.0f;
    if (lane == 0) {
        float wt = accW;
        float dep = accWD / wt;
        if (isnan(dep)) dep = __int_as_float(0x7f800000);
        float dmin = __int_as_float(g_dmin_bits);
        float dmax = __int_as_float(g_dmax_bits);
        dep = fminf(fmaxf(dep, dmin), dmax);
        out[OUT_DEPTH + ray] = dep;
        out[OUT_WT + ray] = wt;
    }
    if (lane < 3) {
        float o_ = ro[ray * 3 + lane], d_ = rd[ray * 3 + lane];
        out[OUT_XYZ + (size_t)ray * 3 + lane] = 2.0f * (o_ * accW + d_ * accWD) - 1.0f;
    }
}

// ---------------- launcher ----------------
extern "C" void kernel_launch(void* const* d_in, const int* in_sizes, int n_in,
                              void* d_out, int out_size) {
    const float* front  = (const float*)d_in[0];
    const float* back   = (const float*)d_in[1];
    const float* ro     = (const float*)d_in[2];
    const float* rd     = (const float*)d_in[3];
    const float* weight = (const float*)d_in[4];
    const float* w1     = (const float*)d_in[5];
    const float* b1     = (const float*)d_in[6];
    const float* w2     = (const float*)d_in[7];
    const float* b2     = (const float*)d_in[8];
    float* out = (float*)d_out;

    cudaFuncSetAttribute(k_model, cudaFuncAttributeMaxDynamicSharedMemorySize, SM_TOTAL_BYTES);

    k_init<<<1, 1>>>();
    k_transpose<<<dim3(8, 256, 6), dim3(32, 8)>>>(front, back);
    k_depth_coarse<<<(NSAMP + 255) / 256, 256>>>();
    k_model<<<444, 256, SM_TOTAL_BYTES>>>(ro, rd, weight, w1, b1, w2, b2, 0);
    k_fine<<<NRAY / FD_T, FD_T>>>();
    k_minmax<<<NRAY / 256, 256>>>();
    k_model<<<444, 256, SM_TOTAL_BYTES>>>(ro, rd, weight, w1, b1, w2, b2, 1);
    k_final<<<NRAY / 8, 256>>>(ro, rd, out);
    (void)in_sizes; (void)n_in; (void)out_size;
}

// round 9
// speedup vs baseline: 3.5557x; 1.0580x over previous
#include <cuda_runtime.h>
#include <cuda_fp16.h>
#include <cstdint>
#include <math.h>

// ---------------- problem constants ----------------
#define Bb 2
#define Rr 4096
#define Ss 48
#define NRAY   (Bb*Rr)        // 8192
#define NSAMP  (NRAY*Ss)      // 393216
#define NG16   (NSAMP/16)     // 24576

#define RAY_START 2.25f
#define STEPF 0.0223404255319148936f  // (3.3-2.25)/47

#define OUT_RGB   0
#define OUT_DEPTH 262144
#define OUT_WT    270336
#define OUT_XYZ   278528

// ---------------- scratch ----------------
__device__ __half g_planes_h[(size_t)Bb*3*256*256*64];
__device__ float g_depth_c[NSAMP];
__device__ float g_depth_f[NSAMP];
__device__ float g_col_c[(size_t)NSAMP*32];
__device__ float g_col_f[(size_t)NSAMP*32];
__device__ float g_sig_c[NSAMP];
__device__ float g_sig_f[NSAMP];
__device__ int   g_dmin_bits;
__device__ int   g_dmax_bits;

// ---------------- math helpers ----------------
__device__ __forceinline__ float softplusf(float x) {
    return fmaxf(x, 0.0f) + log1pf(expf(-fabsf(x)));
}
__device__ __forceinline__ float softplus_fast(float x) {
    return fmaxf(x, 0.0f) + __logf(1.0f + __expf(-fabsf(x)));
}
__device__ __forceinline__ float sigmoid_fast(float x) {
    return __fdividef(1.0f, 1.0f + __expf(-x));
}

__device__ __forceinline__ uint32_t smaddr(const void* p) {
    return (uint32_t)__cvta_generic_to_shared(p);
}
__device__ __forceinline__ void ldsm_x4(uint32_t& r0, uint32_t& r1, uint32_t& r2, uint32_t& r3, uint32_t a) {
    asm volatile("ldmatrix.sync.aligned.m8n8.x4.shared.b16 {%0,%1,%2,%3}, [%4];"
                 : "=r"(r0), "=r"(r1), "=r"(r2), "=r"(r3) : "r"(a));
}
__device__ __forceinline__ void ldsm_x2(uint32_t& r0, uint32_t& r1, uint32_t a) {
    asm volatile("ldmatrix.sync.aligned.m8n8.x2.shared.b16 {%0,%1}, [%2];"
                 : "=r"(r0), "=r"(r1) : "r"(a));
}
__device__ __forceinline__ void mma_f16(float& d0, float& d1, float& d2, float& d3,
                                        uint32_t a0, uint32_t a1, uint32_t a2, uint32_t a3,
                                        uint32_t b0, uint32_t b1) {
    asm volatile(
        "mma.sync.aligned.m16n8k16.row.col.f32.f16.f16.f32 "
        "{%0,%1,%2,%3}, {%4,%5,%6,%7}, {%8,%9}, {%0,%1,%2,%3};"
        : "+f"(d0), "+f"(d1), "+f"(d2), "+f"(d3)
        : "r"(a0), "r"(a1), "r"(a2), "r"(a3), "r"(b0), "r"(b1));
}

// ---------------- Threefry-2x32 (JAX, partitionable variant) ----------------
__device__ __forceinline__ uint32_t rotl32(uint32_t x, int r) {
    return (x << r) | (x >> (32 - r));
}
__device__ __forceinline__ void tf2x32(uint32_t k0, uint32_t k1,
                                       uint32_t x0, uint32_t x1,
                                       uint32_t& o0, uint32_t& o1) {
    uint32_t ks2 = k0 ^ k1 ^ 0x1BD11BDAu;
    x0 += k0; x1 += k1;
#define TFR(r) { x0 += x1; x1 = rotl32(x1, r); x1 ^= x0; }
    TFR(13) TFR(15) TFR(26) TFR(6)  x0 += k1;  x1 += ks2 + 1u;
    TFR(17) TFR(29) TFR(16) TFR(24) x0 += ks2; x1 += k0 + 2u;
    TFR(13) TFR(15) TFR(26) TFR(6)  x0 += k0;  x1 += k1 + 3u;
    TFR(17) TFR(29) TFR(16) TFR(24) x0 += k1;  x1 += ks2 + 4u;
    TFR(13) TFR(15) TFR(26) TFR(6)  x0 += ks2; x1 += k0 + 5u;
#undef TFR
    o0 = x0; o1 = x1;
}
__device__ __forceinline__ void derive_key(uint32_t idx, uint32_t& ka, uint32_t& kb) {
    tf2x32(0u, 42u, 0u, idx, ka, kb);
}
__device__ __forceinline__ float tf_uniform(uint32_t ka, uint32_t kb, uint32_t i) {
    uint32_t o0, o1;
    tf2x32(ka, kb, 0u, i, o0, o1);
    uint32_t bits = o0 ^ o1;
    float f = __uint_as_float((bits >> 9) | 0x3f800000u) - 1.0f;
    return fmaxf(f, 0.0f);
}

// ---------------- kernel 0 ----------------
__global__ void k_init() {
    g_dmin_bits = 0x7f800000;
    g_dmax_bits = 0x00000000;
}

// ---------------- kernel 1: transpose planes to channel-last fp16 ----------------
__global__ void k_transpose(const float* __restrict__ front, const float* __restrict__ back) {
    __shared__ float tf[32][33];
    __shared__ float tb[32][33];
    int bp = blockIdx.z;
    int y  = blockIdx.y;
    int x0 = blockIdx.x * 32;
    int tx = threadIdx.x, ty = threadIdx.y;
    __half2* out = (__half2*)g_planes_h;
#pragma unroll
    for (int i = 0; i < 4; i++) {
        int c = ty + i * 8;
        size_t src = ((size_t)(bp * 32 + c) * 65536) + (size_t)y * 256 + x0 + tx;
        tf[c][tx] = front[src];
        tb[c][tx] = back[src];
    }
    __syncthreads();
#pragma unroll
    for (int i = 0; i < 4; i++) {
        int xx = ty + i * 8;
        out[(((size_t)bp * 65536) + (size_t)y * 256 + x0 + xx) * 32 + tx] =
            __floats2half2_rn(tf[tx][xx], tb[tx][xx]);
    }
}

// ---------------- kernel 2: coarse stratified depths ----------------
__global__ void k_depth_coarse() {
    int i = blockIdx.x * blockDim.x + threadIdx.x;
    if (i >= NSAMP) return;
    uint32_t ka, kb; derive_key(0u, ka, kb);
    float u = tf_uniform(ka, kb, (uint32_t)i);
    int s = i % Ss;
    float d0 = RAY_START + (float)s * STEPF;
    g_depth_c[i] = d0 + u * STEPF;
}

// ---------------- kernel 3: model, warp per 16-sample group, fp16 mma MLP ----------------
#define SM_W1H  0
#define SM_W2H  3328
#define SM_B1   4768
#define SM_B2   4832
#define SM_WSIG 4872
#define SM_XB   4968
#define SM_HB   11624
#define SM_TOTAL_BYTES ((11624 + 4608) * 4)

extern __shared__ __align__(16) float smem[];

struct Axis { float w0, w1; int i0, i1; bool ok; };
__device__ __forceinline__ Axis axis_prep(float g) {
    Axis a;
    float x = (g + 1.0f) * 128.0f - 0.5f;
    float x0f = floorf(x);
    int x0 = (int)x0f;
    float w = x - x0f;
    bool v0 = (x0 >= 0) & (x0 < 256);
    bool v1 = (x0 >= -1) & (x0 < 255);
    a.w0 = v0 ? 1.0f - w : 0.0f;
    a.w1 = v1 ? w : 0.0f;
    a.i0 = min(max(x0, 0), 255);
    a.i1 = min(max(x0 + 1, 0), 255);
    a.ok = (x0 >= -1) & (x0 <= 255);   // any tap in-bounds
    return a;
}

__global__ void __launch_bounds__(256, 3) k_model(
    const float* __restrict__ ro, const float* __restrict__ rd,
    const float* __restrict__ weight,
    const float* __restrict__ w1, const float* __restrict__ b1,
    const float* __restrict__ w2, const float* __restrict__ b2,
    int fine_pass)
{
    __half* w1h = (__half*)(smem + SM_W1H);
    __half* w2h = (__half*)(smem + SM_W2H);
    float* b1s  = smem + SM_B1;
    float* b2s  = smem + SM_B2;
    float* wsig = smem + SM_WSIG;

    int tid = threadIdx.x;
    for (int i = tid; i < 96 * 64; i += 256) {
        int k = i >> 6, n = i & 63;
        w1h[n * 104 + k] = __float2half(w1[i]);
    }
    for (int i = tid; i < 64 * 40; i += 256) {
        int k = i / 40, n = i % 40;
        w2h[n * 72 + k] = (n < 33) ? __float2half(w2[k * 33 + n]) : __half(0.0f);
    }
    if (tid < 64) b1s[tid] = b1[tid];
    if (tid < 40) b2s[tid] = (tid < 33) ? b2[tid] : 0.0f;
    if (tid < 96) wsig[tid] = 1.0f / (1.0f + expf(-weight[tid]));
    __syncthreads();

    const float* depths = fine_pass ? g_depth_f : g_depth_c;
    float* cols = fine_pass ? g_col_f : g_col_c;
    float* sigs = fine_pass ? g_sig_f : g_sig_c;

    int lane = tid & 31, wrp = tid >> 5;
    int tq = lane & 3;
    __half* xh = (__half*)(smem + SM_XB) + wrp * 1664;   // [16][104]
    __half* hh = (__half*)(smem + SM_HB) + wrp * 1152;   // [16][72]
    float*  outf = (float*)xh;                           // reuse as [16][44] float

    uint32_t a_x = smaddr(xh) + (((lane & 15) * 104 + ((lane >> 4) * 8)) * 2);
    uint32_t a_h = smaddr(hh) + (((lane & 15) * 72  + ((lane >> 4) * 8)) * 2);
    uint32_t b_w1 = smaddr(w1h) + (((lane & 7) * 104 + (((lane >> 3) & 1) * 8)) * 2);
    uint32_t b_w2 = smaddr(w2h) + (((lane & 7) * 72  + (((lane >> 3) & 1) * 8)) * 2);

    float wk0 = wsig[lane], wk1 = wsig[32 + lane], wk2 = wsig[64 + lane];

    int g0 = blockIdx.x * 8 + wrp;
    int nG = gridDim.x * 8;

    for (int g = g0; g < NG16; g += nG) {
        int smp0 = g * 16;
        int ray = g / 3;
        int b = ray >> 12;
        // pre-doubled ray (2*(o + t*d) == fmaf(t, 2d, 2o), bit-exact: ×2 commutes with rounding)
        float ox = 2.0f * ro[ray * 3 + 0], oy = 2.0f * ro[ray * 3 + 1], oz = 2.0f * ro[ray * 3 + 2];
        float dx = 2.0f * rd[ray * 3 + 0], dy = 2.0f * rd[ray * 3 + 1], dz = 2.0f * rd[ray * 3 + 2];
        const __half2* pb0 = (const __half2*)g_planes_h + (size_t)b * 3 * 65536 * 32 + (size_t)lane;
        const __half2* pb1 = pb0 + (size_t)65536 * 32;
        const __half2* pb2 = pb1 + (size_t)65536 * 32;

        float dval = depths[smp0 + (lane & 15)];

        // ---- phase A: gather 16 samples, lane = channel; OOB skips (warp-uniform) ----
#pragma unroll 4
        for (int s = 0; s < 16; s++) {
            float d = __shfl_sync(0xffffffffu, dval, s);
            float cx = fmaf(d, dx, ox);
            float cy = fmaf(d, dy, oy);
            float cz = fmaf(d, dz, oz);
            float xv0 = 0.0f, xv1 = 0.0f, xv2 = 0.0f;
            Axis ax = axis_prep(cx);            // used by ALL three planes
            if (ax.ok) {
                Axis ay = axis_prep(cy);        // p0 only
                Axis az = axis_prep(cz);        // p1, p2
                if (ay.ok) {   // plane 0: (ax, ay)
                    float2 v00 = __half22float2(pb0[(ay.i0 * 256 + ax.i0) * 32]);
                    float2 v01 = __half22float2(pb0[(ay.i0 * 256 + ax.i1) * 32]);
                    float2 v10 = __half22float2(pb0[(ay.i1 * 256 + ax.i0) * 32]);
                    float2 v11 = __half22float2(pb0[(ay.i1 * 256 + ax.i1) * 32]);
                    float w00 = ax.w0 * ay.w0, w01 = ax.w1 * ay.w0;
                    float w10 = ax.w0 * ay.w1, w11 = ax.w1 * ay.w1;
                    float aF = fmaf(w11, v11.x, fmaf(w10, v10.x, fmaf(w01, v01.x, w00 * v00.x)));
                    float aB = fmaf(w11, v11.y, fmaf(w10, v10.y, fmaf(w01, v01.y, w00 * v00.y)));
                    xv0 = wk0 * aF + (1.0f - wk0) * aB;
                }
                if (az.ok) {
                    {   // plane 1: (ax, az)
                        float2 v00 = __half22float2(pb1[(az.i0 * 256 + ax.i0) * 32]);
                        float2 v01 = __half22float2(pb1[(az.i0 * 256 + ax.i1) * 32]);
                        float2 v10 = __half22float2(pb1[(az.i1 * 256 + ax.i0) * 32]);
                        float2 v11 = __half22float2(pb1[(az.i1 * 256 + ax.i1) * 32]);
                        float w00 = ax.w0 * az.w0, w01 = ax.w1 * az.w0;
                        float w10 = ax.w0 * az.w1, w11 = ax.w1 * az.w1;
                        float aF = fmaf(w11, v11.x, fmaf(w10, v10.x, fmaf(w01, v01.x, w00 * v00.x)));
                        float aB = fmaf(w11, v11.y, fmaf(w10, v10.y, fmaf(w01, v01.y, w00 * v00.y)));
                        xv1 = wk1 * aF + (1.0f - wk1) * aB;
                    }
                    {   // plane 2: (az, ax)
                        float2 v00 = __half22float2(pb2[(ax.i0 * 256 + az.i0) * 32]);
                        float2 v01 = __half22float2(pb2[(ax.i0 * 256 + az.i1) * 32]);
                        float2 v10 = __half22float2(pb2[(ax.i1 * 256 + az.i0) * 32]);
                        float2 v11 = __half22float2(pb2[(ax.i1 * 256 + az.i1) * 32]);
                        float w00 = az.w0 * ax.w0, w01 = az.w1 * ax.w0;
                        float w10 = az.w0 * ax.w1, w11 = az.w1 * ax.w1;
                        float aF = fmaf(w11, v11.x, fmaf(w10, v10.x, fmaf(w01, v01.x, w00 * v00.x)));
                        float aB = fmaf(w11, v11.y, fmaf(w10, v10.y, fmaf(w01, v01.y, w00 * v00.y)));
                        xv2 = wk2 * aF + (1.0f - wk2) * aB;
                    }
                }
            }
            xh[s * 104 + lane]      = __float2half(xv0);
            xh[s * 104 + 32 + lane] = __float2half(xv1);
            xh[s * 104 + 64 + lane] = __float2half(xv2);
        }
        __syncwarp();

        // ---- layer1: [16x96] @ [96x64], fp16 mma, n split in halves ----
#pragma unroll
        for (int hn = 0; hn < 2; hn++) {
            float d1[4][4];
#pragma unroll
            for (int nt2 = 0; nt2 < 4; nt2++) {
                int nt = hn * 4 + nt2;
                float bl = b1s[nt * 8 + 2 * tq], bh = b1s[nt * 8 + 2 * tq + 1];
                d1[nt2][0] = bl; d1[nt2][1] = bh; d1[nt2][2] = bl; d1[nt2][3] = bh;
            }
#pragma unroll
            for (int kt = 0; kt < 6; kt++) {
                uint32_t a0, a1, a2, a3;
                ldsm_x4(a0, a1, a2, a3, a_x + kt * 32);
#pragma unroll
                for (int nt2 = 0; nt2 < 4; nt2++) {
                    int nt = hn * 4 + nt2;
                    uint32_t bv0, bv1;
                    ldsm_x2(bv0, bv1, b_w1 + nt * 1664 + kt * 32);
                    mma_f16(d1[nt2][0], d1[nt2][1], d1[nt2][2], d1[nt2][3], a0, a1, a2, a3, bv0, bv1);
                }
            }
            int gq = lane >> 2;
#pragma unroll
            for (int nt2 = 0; nt2 < 4; nt2++) {
                int nt = hn * 4 + nt2;
                *(__half2*)(hh + gq * 72 + nt * 8 + 2 * tq) =
                    __floats2half2_rn(softplus_fast(d1[nt2][0]), softplus_fast(d1[nt2][1]));
                *(__half2*)(hh + (gq + 8) * 72 + nt * 8 + 2 * tq) =
                    __floats2half2_rn(softplus_fast(d1[nt2][2]), softplus_fast(d1[nt2][3]));
            }
        }
        __syncwarp();

        // ---- layer2: [16x64] @ [64x40] ----
        float d2[5][4];
#pragma unroll
        for (int nt = 0; nt < 5; nt++) {
            float bl = b2s[nt * 8 + 2 * tq], bh = b2s[nt * 8 + 2 * tq + 1];
            d2[nt][0] = bl; d2[nt][1] = bh; d2[nt][2] = bl; d2[nt][3] = bh;
        }
#pragma unroll
        for (int kt = 0; kt < 4; kt++) {
            uint32_t a0, a1, a2, a3;
            ldsm_x4(a0, a1, a2, a3, a_h + kt * 32);
#pragma unroll
            for (int nt = 0; nt < 5; nt++) {
                uint32_t bv0, bv1;
                ldsm_x2(bv0, bv1, b_w2 + nt * 1152 + kt * 32);
                mma_f16(d2[nt][0], d2[nt][1], d2[nt][2], d2[nt][3], a0, a1, a2, a3, bv0, bv1);
            }
        }
        __syncwarp();
        {
            int gq = lane >> 2;
#pragma unroll
            for (int nt = 0; nt < 5; nt++) {
                *(float2*)(outf + gq * 44 + nt * 8 + 2 * tq)       = make_float2(d2[nt][0], d2[nt][1]);
                *(float2*)(outf + (gq + 8) * 44 + nt * 8 + 2 * tq) = make_float2(d2[nt][2], d2[nt][3]);
            }
        }
        __syncwarp();

#pragma unroll 4
        for (int s = 0; s < 16; s++) {
            float v = outf[s * 44 + 1 + lane];
            cols[(size_t)(smp0 + s) * 32 + lane] = sigmoid_fast(v) * 1.002f - 0.001f;
        }
        if (lane < 16) sigs[smp0 + lane] = outf[lane * 44];
        __syncwarp();
    }
}

// ---------------- kernel 4: fused coarse weights + importance sampling + minmax ----------------
#define FD_T 64
__global__ void __launch_bounds__(FD_T) k_fine() {
    __shared__ float zm_s[FD_T][49];
    __shared__ float cdf_s[FD_T][47];
    __shared__ float w_s[FD_T][49];
    int t = threadIdx.x;
    int ray = blockIdx.x * FD_T + t;
    float* zm  = zm_s[t];
    float* cdf = cdf_s[t];
    float* wrow = w_s[t];
    const float* zrow = g_depth_c + ray * 48;
    const float* srow = g_sig_c + ray * 48;

    float z0, z47;
    {
        float T = 1.0f;
        float zp = zrow[0];
        z0 = zp;
        float sp = srow[0];
        for (int s = 1; s < 48; s++) {
            float z = zrow[s];
            float sg = srow[s];
            float dens = softplusf(0.5f * (sp + sg) - 1.0f);
            float alpha = 1.0f - expf(-dens * (z - zp));
            wrow[s - 1] = alpha * T;
            zm[s - 1] = 0.5f * (zp + z);
            T *= (1.0f - alpha + 1e-10f);
            zp = z; sp = sg;
        }
        z47 = zp;
    }

    // global depth min/max (only endpoints matter: depths increase along ray)
    {
        float dmin = z0, dmax = z47;
#pragma unroll
        for (int off = 16; off; off >>= 1) {
            dmin = fminf(dmin, __shfl_xor_sync(0xffffffffu, dmin, off));
            dmax = fmaxf(dmax, __shfl_xor_sync(0xffffffffu, dmax, off));
        }
        if ((t & 31) == 0) {
            atomicMin(&g_dmin_bits, __float_as_int(dmin));
            atomicMax(&g_dmax_bits, __float_as_int(dmax));
        }
    }

    float sum = 0.0f;
    for (int j = 0; j < 45; j++) {
        int i = j + 1;
        float wim1 = wrow[i - 1], wi = wrow[i], wip1 = wrow[i + 1];
        float wmi  = fmaxf(wim1, wi);
        float wmi1 = fmaxf(wi, wip1);
        float wsj = 0.5f * (wmi + wmi1) + 0.01f + 1e-5f;
        cdf[j + 1] = wsj;
        sum += wsj;
    }
    cdf[0] = 0.0f;
    float run = 0.0f;
    for (int j = 0; j < 45; j++) {
        run += cdf[j + 1] / sum;
        cdf[j + 1] = run;
    }

    uint32_t ka, kb; derive_key(1u, ka, kb);
    for (int j = 0; j < 48; j++) {
        float u = tf_uniform(ka, kb, (uint32_t)(ray * 48 + j));
        int pos = 0;
#pragma unroll
        for (int step = 32; step; step >>= 1) {
            int np = pos + step;
            if (np <= 46 && cdf[np - 1] <= u) pos = np;
        }
        int ind = pos;
        int below = ind - 1; if (below < 0) below = 0;
        int above = ind;     if (above > 45) above = 45;
        float c0 = cdf[below], c1 = cdf[above];
        float b0 = zm[below],  b1v = zm[above];
        float denom = c1 - c0;
        if (denom < 1e-5f) denom = 1.0f;
        g_depth_f[ray * 48 + j] = b0 + (u - c0) / denom * (b1v - b0);
    }
}

// ---------------- kernel 5: unify + final march, warp per ray ----------------
__global__ void __launch_bounds__(256) k_final(
    const float* __restrict__ ro, const float* __restrict__ rd,
    float* __restrict__ out)
{
    __shared__ __align__(16) float sd[8][96];
    __shared__ __align__(16) float ssg[8][96];
    __shared__ __align__(16) int   sidx[8][96];
    int lane = threadIdx.x & 31, wrp = threadIdx.x >> 5;
    int ray = blockIdx.x * 8 + wrp;

    for (int i = lane; i < 48; i += 32) {
        sd[wrp][i]       = g_depth_c[ray * 48 + i];
        sd[wrp][48 + i]  = g_depth_f[ray * 48 + i];
        ssg[wrp][i]      = g_sig_c[ray * 48 + i];
        ssg[wrp][48 + i] = g_sig_f[ray * 48 + i];
    }
    __syncwarp();
#pragma unroll
    for (int t = 0; t < 3; t++) {
        int e = lane + t * 32;
        float de = sd[wrp][e];
        int rank = 0;
        for (int j = 0; j < 96; j++) {
            float dj = sd[wrp][j];
            rank += (dj < de || (dj == de && j < e)) ? 1 : 0;
        }
        sidx[wrp][rank] = e;
    }
    __syncwarp();

    float T = 1.0f, accW = 0.0f, accWD = 0.0f, accC = 0.0f;
    int i0 = sidx[wrp][0];
    float dp = sd[wrp][i0], sp = ssg[wrp][i0];
    const float* cb0 = (i0 < 48) ? g_col_c : g_col_f;
    float cp = cb0[((size_t)ray * 48 + (i0 < 48 ? i0 : i0 - 48)) * 32 + lane];

    for (int s = 1; s < 96; s++) {
        int i = sidx[wrp][s];
        float dc = sd[wrp][i], sc = ssg[wrp][i];
        const float* cb = (i < 48) ? g_col_c : g_col_f;
        float cc = cb[((size_t)ray * 48 + (i < 48 ? i : i - 48)) * 32 + lane];
        float delta = dc - dp;
        float dens = softplusf(0.5f * (sc + sp) - 1.0f);
        float alpha = 1.0f - expf(-dens * delta);
        float wgt = alpha * T;
        T *= (1.0f - alpha + 1e-10f);
        accC  += wgt * 0.5f * (cc + cp);
        accW  += wgt;
        accWD += wgt * 0.5f * (dc + dp);
        dp = dc; sp = sc; cp = cc;
    }

    out[OUT_RGB + (size_t)ray * 32 + lane] = accC * 2.0f - 1.0f;
    if (lane == 0) {
        float wt = accW;
        float dep = accWD / wt;
        if (isnan(dep)) dep = __int_as_float(0x7f800000);
        float dmin = __int_as_float(g_dmin_bits);
        float dmax = __int_as_float(g_dmax_bits);
        dep = fminf(fmaxf(dep, dmin), dmax);
        out[OUT_DEPTH + ray] = dep;
        out[OUT_WT + ray] = wt;
    }
    if (lane < 3) {
        float o_ = ro[ray * 3 + lane], d_ = rd[ray * 3 + lane];
        out[OUT_XYZ + (size_t)ray * 3 + lane] = 2.0f * (o_ * accW + d_ * accWD) - 1.0f;
    }
}

// ---------------- launcher ----------------
extern "C" void kernel_launch(void* const* d_in, const int* in_sizes, int n_in,
                              void* d_out, int out_size) {
    const float* front  = (const float*)d_in[0];
    const float* back   = (const float*)d_in[1];
    const float* ro     = (const float*)d_in[2];
    const float* rd     = (const float*)d_in[3];
    const float* weight = (const float*)d_in[4];
    const float* w1     = (const float*)d_in[5];
    const float* b1     = (const float*)d_in[6];
    const float* w2     = (const float*)d_in[7];
    const float* b2     = (const float*)d_in[8];
    float* out = (float*)d_out;

    cudaFuncSetAttribute(k_model, cudaFuncAttributeMaxDynamicSharedMemorySize, SM_TOTAL_BYTES);

    k_init<<<1, 1>>>();
    k_transpose<<<dim3(8, 256, 6), dim3(32, 8)>>>(front, back);
    k_depth_coarse<<<(NSAMP + 255) / 256, 256>>>();
    k_model<<<444, 256, SM_TOTAL_BYTES>>>(ro, rd, weight, w1, b1, w2, b2, 0);
    k_fine<<<NRAY / FD_T, FD_T>>>();
    k_model<<<444, 256, SM_TOTAL_BYTES>>>(ro, rd, weight, w1, b1, w2, b2, 1);
    k_final<<<NRAY / 8, 256>>>(ro, rd, out);
    (void)in_sizes; (void)n_in; (void)out_size;
}

// round 10
// speedup vs baseline: 4.1329x; 1.1623x over previous
#include <cuda_runtime.h>
#include <cuda_fp16.h>
#include <cstdint>
#include <math.h>

// ---------------- problem constants ----------------
#define Bb 2
#define Rr 4096
#define Ss 48
#define NRAY   (Bb*Rr)        // 8192
#define NSAMP  (NRAY*Ss)      // 393216
#define NG16   (NSAMP/16)     // 24576

#define RAY_START 2.25f
#define STEPF 0.0223404255319148936f  // (3.3-2.25)/47

#define OUT_RGB   0
#define OUT_DEPTH 262144
#define OUT_WT    270336
#define OUT_XYZ   278528

// ---------------- scratch ----------------
__device__ __half g_planes_h[(size_t)Bb*3*256*256*64];
__device__ float g_depth_c[NSAMP];
__device__ float g_depth_f[NSAMP];
__device__ float g_col_c[(size_t)NSAMP*32];
__device__ float g_col_f[(size_t)NSAMP*32];
__device__ float g_sig_c[NSAMP];
__device__ float g_sig_f[NSAMP];
__device__ int   g_dmin_bits;
__device__ int   g_dmax_bits;

// ---------------- math helpers ----------------
__device__ __forceinline__ float softplusf(float x) {
    return fmaxf(x, 0.0f) + log1pf(expf(-fabsf(x)));
}
__device__ __forceinline__ float softplus_fast(float x) {
    return fmaxf(x, 0.0f) + __logf(1.0f + __expf(-fabsf(x)));
}
__device__ __forceinline__ float sigmoid_fast(float x) {
    return __fdividef(1.0f, 1.0f + __expf(-x));
}

__device__ __forceinline__ uint32_t smaddr(const void* p) {
    return (uint32_t)__cvta_generic_to_shared(p);
}
__device__ __forceinline__ void ldsm_x4(uint32_t& r0, uint32_t& r1, uint32_t& r2, uint32_t& r3, uint32_t a) {
    asm volatile("ldmatrix.sync.aligned.m8n8.x4.shared.b16 {%0,%1,%2,%3}, [%4];"
                 : "=r"(r0), "=r"(r1), "=r"(r2), "=r"(r3) : "r"(a));
}
__device__ __forceinline__ void ldsm_x2(uint32_t& r0, uint32_t& r1, uint32_t a) {
    asm volatile("ldmatrix.sync.aligned.m8n8.x2.shared.b16 {%0,%1}, [%2];"
                 : "=r"(r0), "=r"(r1) : "r"(a));
}
__device__ __forceinline__ void mma_f16(float& d0, float& d1, float& d2, float& d3,
                                        uint32_t a0, uint32_t a1, uint32_t a2, uint32_t a3,
                                        uint32_t b0, uint32_t b1) {
    asm volatile(
        "mma.sync.aligned.m16n8k16.row.col.f32.f16.f16.f32 "
        "{%0,%1,%2,%3}, {%4,%5,%6,%7}, {%8,%9}, {%0,%1,%2,%3};"
        : "+f"(d0), "+f"(d1), "+f"(d2), "+f"(d3)
        : "r"(a0), "r"(a1), "r"(a2), "r"(a3), "r"(b0), "r"(b1));
}

// ---------------- Threefry-2x32 (JAX, partitionable variant) ----------------
__device__ __forceinline__ uint32_t rotl32(uint32_t x, int r) {
    return (x << r) | (x >> (32 - r));
}
__device__ __forceinline__ void tf2x32(uint32_t k0, uint32_t k1,
                                       uint32_t x0, uint32_t x1,
                                       uint32_t& o0, uint32_t& o1) {
    uint32_t ks2 = k0 ^ k1 ^ 0x1BD11BDAu;
    x0 += k0; x1 += k1;
#define TFR(r) { x0 += x1; x1 = rotl32(x1, r); x1 ^= x0; }
    TFR(13) TFR(15) TFR(26) TFR(6)  x0 += k1;  x1 += ks2 + 1u;
    TFR(17) TFR(29) TFR(16) TFR(24) x0 += ks2; x1 += k0 + 2u;
    TFR(13) TFR(15) TFR(26) TFR(6)  x0 += k0;  x1 += k1 + 3u;
    TFR(17) TFR(29) TFR(16) TFR(24) x0 += k1;  x1 += ks2 + 4u;
    TFR(13) TFR(15) TFR(26) TFR(6)  x0 += ks2; x1 += k0 + 5u;
#undef TFR
    o0 = x0; o1 = x1;
}
__device__ __forceinline__ void derive_key(uint32_t idx, uint32_t& ka, uint32_t& kb) {
    tf2x32(0u, 42u, 0u, idx, ka, kb);
}
__device__ __forceinline__ float tf_uniform(uint32_t ka, uint32_t kb, uint32_t i) {
    uint32_t o0, o1;
    tf2x32(ka, kb, 0u, i, o0, o1);
    uint32_t bits = o0 ^ o1;
    float f = __uint_as_float((bits >> 9) | 0x3f800000u) - 1.0f;
    return fmaxf(f, 0.0f);
}

// ---------------- kernel 0 ----------------
__global__ void k_init() {
    g_dmin_bits = 0x7f800000;
    g_dmax_bits = 0x00000000;
}

// ---------------- kernel 1: transpose planes to channel-last fp16 ----------------
__global__ void k_transpose(const float* __restrict__ front, const float* __restrict__ back) {
    __shared__ float tf[32][33];
    __shared__ float tb[32][33];
    int bp = blockIdx.z;
    int y  = blockIdx.y;
    int x0 = blockIdx.x * 32;
    int tx = threadIdx.x, ty = threadIdx.y;
    __half2* out = (__half2*)g_planes_h;
#pragma unroll
    for (int i = 0; i < 4; i++) {
        int c = ty + i * 8;
        size_t src = ((size_t)(bp * 32 + c) * 65536) + (size_t)y * 256 + x0 + tx;
        tf[c][tx] = front[src];
        tb[c][tx] = back[src];
    }
    __syncthreads();
#pragma unroll
    for (int i = 0; i < 4; i++) {
        int xx = ty + i * 8;
        out[(((size_t)bp * 65536) + (size_t)y * 256 + x0 + xx) * 32 + tx] =
            __floats2half2_rn(tf[tx][xx], tb[tx][xx]);
    }
}

// ---------------- kernel 2: model, warp per 16-sample group, fp16 mma MLP ----------------
// 512-thread blocks (16 warps), 2 blocks/SM. coarse pass computes its own depths.
// smem float-offsets:
//   w1h : 64 n x 104 k halves = 3328 floats
//   w2h : 40 n x  72 k halves = 1440 floats
//   b1s 64, b2s 40, wsig 96
//   xb  : 16 warps x 16 x 104 halves = 13312 floats
//   hb  : 16 warps x 16 x  72 halves =  9216 floats
#define SM_W1H  0
#define SM_W2H  3328
#define SM_B1   4768
#define SM_B2   4832
#define SM_WSIG 4872
#define SM_XB   4968
#define SM_HB   18280
#define SM_TOTAL_BYTES (27496*4)

extern __shared__ __align__(16) float smem[];

struct Axis { float w0, w1; int i0, i1; bool ok; };
__device__ __forceinline__ Axis axis_prep(float g) {
    Axis a;
    float x = (g + 1.0f) * 128.0f - 0.5f;
    float x0f = floorf(x);
    int x0 = (int)x0f;
    float w = x - x0f;
    bool v0 = (x0 >= 0) & (x0 < 256);
    bool v1 = (x0 >= -1) & (x0 < 255);
    a.w0 = v0 ? 1.0f - w : 0.0f;
    a.w1 = v1 ? w : 0.0f;
    a.i0 = min(max(x0, 0), 255);
    a.i1 = min(max(x0 + 1, 0), 255);
    a.ok = (x0 >= -1) & (x0 <= 255);
    return a;
}

__global__ void __launch_bounds__(512, 2) k_model(
    const float* __restrict__ ro, const float* __restrict__ rd,
    const float* __restrict__ weight,
    const float* __restrict__ w1, const float* __restrict__ b1,
    const float* __restrict__ w2, const float* __restrict__ b2,
    int fine_pass)
{
    __half* w1h = (__half*)(smem + SM_W1H);
    __half* w2h = (__half*)(smem + SM_W2H);
    float* b1s  = smem + SM_B1;
    float* b2s  = smem + SM_B2;
    float* wsig = smem + SM_WSIG;

    int tid = threadIdx.x;
    for (int i = tid; i < 96 * 64; i += 512) {
        int k = i >> 6, n = i & 63;
        w1h[n * 104 + k] = __float2half(w1[i]);
    }
    for (int i = tid; i < 64 * 40; i += 512) {
        int k = i / 40, n = i % 40;
        w2h[n * 72 + k] = (n < 33) ? __float2half(w2[k * 33 + n]) : __half(0.0f);
    }
    if (tid < 64) b1s[tid] = b1[tid];
    if (tid < 40) b2s[tid] = (tid < 33) ? b2[tid] : 0.0f;
    if (tid < 96) wsig[tid] = 1.0f / (1.0f + expf(-weight[tid]));
    __syncthreads();

    float* cols = fine_pass ? g_col_f : g_col_c;
    float* sigs = fine_pass ? g_sig_f : g_sig_c;

    int lane = tid & 31, wrp = tid >> 5;
    int tq = lane & 3;
    __half* xh = (__half*)(smem + SM_XB) + wrp * 1664;   // [16][104]
    __half* hh = (__half*)(smem + SM_HB) + wrp * 1152;   // [16][72]
    float*  outf = (float*)xh;                           // reuse as [16][44] float

    uint32_t a_x = smaddr(xh) + (((lane & 15) * 104 + ((lane >> 4) * 8)) * 2);
    uint32_t a_h = smaddr(hh) + (((lane & 15) * 72  + ((lane >> 4) * 8)) * 2);
    uint32_t b_w1 = smaddr(w1h) + (((lane & 7) * 104 + (((lane >> 3) & 1) * 8)) * 2);
    uint32_t b_w2 = smaddr(w2h) + (((lane & 7) * 72  + (((lane >> 3) & 1) * 8)) * 2);

    float wk0 = wsig[lane], wk1 = wsig[32 + lane], wk2 = wsig[64 + lane];

    uint32_t ka0, kb0; derive_key(0u, ka0, kb0);  // coarse-depth key (only used when !fine_pass)

    int g0 = blockIdx.x * 16 + wrp;
    int nG = gridDim.x * 16;

    for (int g = g0; g < NG16; g += nG) {
        int smp0 = g * 16;
        int ray = g / 3;
        int b = ray >> 12;
        float ox = 2.0f * ro[ray * 3 + 0], oy = 2.0f * ro[ray * 3 + 1], oz = 2.0f * ro[ray * 3 + 2];
        float dx = 2.0f * rd[ray * 3 + 0], dy = 2.0f * rd[ray * 3 + 1], dz = 2.0f * rd[ray * 3 + 2];
        const __half2* pb0 = (const __half2*)g_planes_h + (size_t)b * 3 * 65536 * 32 + (size_t)lane;
        const __half2* pb1 = pb0 + (size_t)65536 * 32;
        const __half2* pb2 = pb1 + (size_t)65536 * 32;

        int sidx = smp0 + (lane & 15);
        float dval;
        if (!fine_pass) {
            // stratified depth computed inline (same formula as the old k_depth_coarse)
            int sloc = (g % 3) * 16 + (lane & 15);
            float u = tf_uniform(ka0, kb0, (uint32_t)sidx);
            float d0 = RAY_START + (float)sloc * STEPF;
            dval = d0 + u * STEPF;
            if (lane < 16) g_depth_c[sidx] = dval;
        } else {
            dval = g_depth_f[sidx];
        }

        // ---- phase A: gather 16 samples, lane = channel; OOB skips (warp-uniform) ----
#pragma unroll 4
        for (int s = 0; s < 16; s++) {
            float d = __shfl_sync(0xffffffffu, dval, s);
            float cx = fmaf(d, dx, ox);
            float cy = fmaf(d, dy, oy);
            float cz = fmaf(d, dz, oz);
            float xv0 = 0.0f, xv1 = 0.0f, xv2 = 0.0f;
            Axis ax = axis_prep(cx);
            if (ax.ok) {
                Axis ay = axis_prep(cy);
                Axis az = axis_prep(cz);
                if (ay.ok) {   // plane 0: (ax, ay)
                    float2 v00 = __half22float2(pb0[(ay.i0 * 256 + ax.i0) * 32]);
                    float2 v01 = __half22float2(pb0[(ay.i0 * 256 + ax.i1) * 32]);
                    float2 v10 = __half22float2(pb0[(ay.i1 * 256 + ax.i0) * 32]);
                    float2 v11 = __half22float2(pb0[(ay.i1 * 256 + ax.i1) * 32]);
                    float w00 = ax.w0 * ay.w0, w01 = ax.w1 * ay.w0;
                    float w10 = ax.w0 * ay.w1, w11 = ax.w1 * ay.w1;
                    float aF = fmaf(w11, v11.x, fmaf(w10, v10.x, fmaf(w01, v01.x, w00 * v00.x)));
                    float aB = fmaf(w11, v11.y, fmaf(w10, v10.y, fmaf(w01, v01.y, w00 * v00.y)));
                    xv0 = wk0 * aF + (1.0f - wk0) * aB;
                }
                if (az.ok) {
                    {   // plane 1: (ax, az)
                        float2 v00 = __half22float2(pb1[(az.i0 * 256 + ax.i0) * 32]);
                        float2 v01 = __half22float2(pb1[(az.i0 * 256 + ax.i1) * 32]);
                        float2 v10 = __half22float2(pb1[(az.i1 * 256 + ax.i0) * 32]);
                        float2 v11 = __half22float2(pb1[(az.i1 * 256 + ax.i1) * 32]);
                        float w00 = ax.w0 * az.w0, w01 = ax.w1 * az.w0;
                        float w10 = ax.w0 * az.w1, w11 = ax.w1 * az.w1;
                        float aF = fmaf(w11, v11.x, fmaf(w10, v10.x, fmaf(w01, v01.x, w00 * v00.x)));
                        float aB = fmaf(w11, v11.y, fmaf(w10, v10.y, fmaf(w01, v01.y, w00 * v00.y)));
                        xv1 = wk1 * aF + (1.0f - wk1) * aB;
                    }
                    {   // plane 2: (az, ax)
                        float2 v00 = __half22float2(pb2[(ax.i0 * 256 + az.i0) * 32]);
                        float2 v01 = __half22float2(pb2[(ax.i0 * 256 + az.i1) * 32]);
                        float2 v10 = __half22float2(pb2[(ax.i1 * 256 + az.i0) * 32]);
                        float2 v11 = __half22float2(pb2[(ax.i1 * 256 + az.i1) * 32]);
                        float w00 = az.w0 * ax.w0, w01 = az.w1 * ax.w0;
                        float w10 = az.w0 * ax.w1, w11 = az.w1 * ax.w1;
                        float aF = fmaf(w11, v11.x, fmaf(w10, v10.x, fmaf(w01, v01.x, w00 * v00.x)));
                        float aB = fmaf(w11, v11.y, fmaf(w10, v10.y, fmaf(w01, v01.y, w00 * v00.y)));
                        xv2 = wk2 * aF + (1.0f - wk2) * aB;
                    }
                }
            }
            xh[s * 104 + lane]      = __float2half(xv0);
            xh[s * 104 + 32 + lane] = __float2half(xv1);
            xh[s * 104 + 64 + lane] = __float2half(xv2);
        }
        __syncwarp();

        // ---- layer1: [16x96] @ [96x64], fp16 mma, n split in halves ----
#pragma unroll
        for (int hn = 0; hn < 2; hn++) {
            float d1[4][4];
#pragma unroll
            for (int nt2 = 0; nt2 < 4; nt2++) {
                int nt = hn * 4 + nt2;
                float bl = b1s[nt * 8 + 2 * tq], bh = b1s[nt * 8 + 2 * tq + 1];
                d1[nt2][0] = bl; d1[nt2][1] = bh; d1[nt2][2] = bl; d1[nt2][3] = bh;
            }
#pragma unroll
            for (int kt = 0; kt < 6; kt++) {
                uint32_t a0, a1, a2, a3;
                ldsm_x4(a0, a1, a2, a3, a_x + kt * 32);
#pragma unroll
                for (int nt2 = 0; nt2 < 4; nt2++) {
                    int nt = hn * 4 + nt2;
                    uint32_t bv0, bv1;
                    ldsm_x2(bv0, bv1, b_w1 + nt * 1664 + kt * 32);
                    mma_f16(d1[nt2][0], d1[nt2][1], d1[nt2][2], d1[nt2][3], a0, a1, a2, a3, bv0, bv1);
                }
            }
            int gq = lane >> 2;
#pragma unroll
            for (int nt2 = 0; nt2 < 4; nt2++) {
                int nt = hn * 4 + nt2;
                *(__half2*)(hh + gq * 72 + nt * 8 + 2 * tq) =
                    __floats2half2_rn(softplus_fast(d1[nt2][0]), softplus_fast(d1[nt2][1]));
                *(__half2*)(hh + (gq + 8) * 72 + nt * 8 + 2 * tq) =
                    __floats2half2_rn(softplus_fast(d1[nt2][2]), softplus_fast(d1[nt2][3]));
            }
        }
        __syncwarp();

        // ---- layer2: [16x64] @ [64x40] ----
        float d2[5][4];
#pragma unroll
        for (int nt = 0; nt < 5; nt++) {
            float bl = b2s[nt * 8 + 2 * tq], bh = b2s[nt * 8 + 2 * tq + 1];
            d2[nt][0] = bl; d2[nt][1] = bh; d2[nt][2] = bl; d2[nt][3] = bh;
        }
#pragma unroll
        for (int kt = 0; kt < 4; kt++) {
            uint32_t a0, a1, a2, a3;
            ldsm_x4(a0, a1, a2, a3, a_h + kt * 32);
#pragma unroll
            for (int nt = 0; nt < 5; nt++) {
                uint32_t bv0, bv1;
                ldsm_x2(bv0, bv1, b_w2 + nt * 1152 + kt * 32);
                mma_f16(d2[nt][0], d2[nt][1], d2[nt][2], d2[nt][3], a0, a1, a2, a3, bv0, bv1);
            }
        }
        __syncwarp();
        {
            int gq = lane >> 2;
#pragma unroll
            for (int nt = 0; nt < 5; nt++) {
                *(float2*)(outf + gq * 44 + nt * 8 + 2 * tq)       = make_float2(d2[nt][0], d2[nt][1]);
                *(float2*)(outf + (gq + 8) * 44 + nt * 8 + 2 * tq) = make_float2(d2[nt][2], d2[nt][3]);
            }
        }
        __syncwarp();

#pragma unroll 4
        for (int s = 0; s < 16; s++) {
            float v = outf[s * 44 + 1 + lane];
            cols[(size_t)(smp0 + s) * 32 + lane] = sigmoid_fast(v) * 1.002f - 0.001f;
        }
        if (lane < 16) sigs[smp0 + lane] = outf[lane * 44];
        __syncwarp();
    }
}

// ---------------- kernel 3: fused coarse weights + importance sampling + minmax ----------------
#define FD_T 64
__global__ void __launch_bounds__(FD_T) k_fine() {
    __shared__ float zm_s[FD_T][49];
    __shared__ float cdf_s[FD_T][47];
    __shared__ float w_s[FD_T][49];
    int t = threadIdx.x;
    int ray = blockIdx.x * FD_T + t;
    float* zm  = zm_s[t];
    float* cdf = cdf_s[t];
    float* wrow = w_s[t];
    const float* zrow = g_depth_c + ray * 48;
    const float* srow = g_sig_c + ray * 48;

    float z0, z47;
    {
        float T = 1.0f;
        float zp = zrow[0];
        z0 = zp;
        float sp = srow[0];
        for (int s = 1; s < 48; s++) {
            float z = zrow[s];
            float sg = srow[s];
            float dens = softplusf(0.5f * (sp + sg) - 1.0f);
            float alpha = 1.0f - expf(-dens * (z - zp));
            wrow[s - 1] = alpha * T;
            zm[s - 1] = 0.5f * (zp + z);
            T *= (1.0f - alpha + 1e-10f);
            zp = z; sp = sg;
        }
        z47 = zp;
    }

    {
        float dmin = z0, dmax = z47;
#pragma unroll
        for (int off = 16; off; off >>= 1) {
            dmin = fminf(dmin, __shfl_xor_sync(0xffffffffu, dmin, off));
            dmax = fmaxf(dmax, __shfl_xor_sync(0xffffffffu, dmax, off));
        }
        if ((t & 31) == 0) {
            atomicMin(&g_dmin_bits, __float_as_int(dmin));
            atomicMax(&g_dmax_bits, __float_as_int(dmax));
        }
    }

    float sum = 0.0f;
    for (int j = 0; j < 45; j++) {
        int i = j + 1;
        float wim1 = wrow[i - 1], wi = wrow[i], wip1 = wrow[i + 1];
        float wmi  = fmaxf(wim1, wi);
        float wmi1 = fmaxf(wi, wip1);
        float wsj = 0.5f * (wmi + wmi1) + 0.01f + 1e-5f;
        cdf[j + 1] = wsj;
        sum += wsj;
    }
    cdf[0] = 0.0f;
    float run = 0.0f;
    for (int j = 0; j < 45; j++) {
        run += cdf[j + 1] / sum;
        cdf[j + 1] = run;
    }

    uint32_t ka, kb; derive_key(1u, ka, kb);
    for (int j = 0; j < 48; j++) {
        float u = tf_uniform(ka, kb, (uint32_t)(ray * 48 + j));
        int pos = 0;
#pragma unroll
        for (int step = 32; step; step >>= 1) {
            int np = pos + step;
            if (np <= 46 && cdf[np - 1] <= u) pos = np;
        }
        int ind = pos;
        int below = ind - 1; if (below < 0) below = 0;
        int above = ind;     if (above > 45) above = 45;
        float c0 = cdf[below], c1 = cdf[above];
        float b0 = zm[below],  b1v = zm[above];
        float denom = c1 - c0;
        if (denom < 1e-5f) denom = 1.0f;
        g_depth_f[ray * 48 + j] = b0 + (u - c0) / denom * (b1v - b0);
    }
}

// ---------------- kernel 4: unify + final march, warp per ray ----------------
__global__ void __launch_bounds__(256) k_final(
    const float* __restrict__ ro, const float* __restrict__ rd,
    float* __restrict__ out)
{
    __shared__ __align__(16) float sd[8][96];
    __shared__ __align__(16) float ssg[8][96];
    __shared__ __align__(16) int   sidx[8][96];
    int lane = threadIdx.x & 31, wrp = threadIdx.x >> 5;
    int ray = blockIdx.x * 8 + wrp;

    for (int i = lane; i < 48; i += 32) {
        sd[wrp][i]       = g_depth_c[ray * 48 + i];
        sd[wrp][48 + i]  = g_depth_f[ray * 48 + i];
        ssg[wrp][i]      = g_sig_c[ray * 48 + i];
        ssg[wrp][48 + i] = g_sig_f[ray * 48 + i];
    }
    __syncwarp();
#pragma unroll
    for (int t = 0; t < 3; t++) {
        int e = lane + t * 32;
        float de = sd[wrp][e];
        int rank = 0;
        for (int j = 0; j < 96; j++) {
            float dj = sd[wrp][j];
            rank += (dj < de || (dj == de && j < e)) ? 1 : 0;
        }
        sidx[wrp][rank] = e;
    }
    __syncwarp();

    float T = 1.0f, accW = 0.0f, accWD = 0.0f, accC = 0.0f;
    int i0 = sidx[wrp][0];
    float dp = sd[wrp][i0], sp = ssg[wrp][i0];
    const float* cb0 = (i0 < 48) ? g_col_c : g_col_f;
    float cp = cb0[((size_t)ray * 48 + (i0 < 48 ? i0 : i0 - 48)) * 32 + lane];

    for (int s = 1; s < 96; s++) {
        int i = sidx[wrp][s];
        float dc = sd[wrp][i], sc = ssg[wrp][i];
        const float* cb = (i < 48) ? g_col_c : g_col_f;
        float cc = cb[((size_t)ray * 48 + (i < 48 ? i : i - 48)) * 32 + lane];
        float delta = dc - dp;
        float dens = softplus_fast(0.5f * (sc + sp) - 1.0f);
        float alpha = 1.0f - __expf(-dens * delta);
        float wgt = alpha * T;
        T *= (1.0f - alpha + 1e-10f);
        accC  += wgt * 0.5f * (cc + cp);
        accW  += wgt;
        accWD += wgt * 0.5f * (dc + dp);
        dp = dc; sp = sc; cp = cc;
    }

    out[OUT_RGB + (size_t)ray * 32 + lane] = accC * 2.0f - 1.0f;
    if (lane == 0) {
        float wt = accW;
        float dep = accWD / wt;
        if (isnan(dep)) dep = __int_as_float(0x7f800000);
        float dmin = __int_as_float(g_dmin_bits);
        float dmax = __int_as_float(g_dmax_bits);
        dep = fminf(fmaxf(dep, dmin), dmax);
        out[OUT_DEPTH + ray] = dep;
        out[OUT_WT + ray] = wt;
    }
    if (lane < 3) {
        float o_ = ro[ray * 3 + lane], d_ = rd[ray * 3 + lane];
        out[OUT_XYZ + (size_t)ray * 3 + lane] = 2.0f * (o_ * accW + d_ * accWD) - 1.0f;
    }
}

// ---------------- launcher ----------------
extern "C" void kernel_launch(void* const* d_in, const int* in_sizes, int n_in,
                              void* d_out, int out_size) {
    const float* front  = (const float*)d_in[0];
    const float* back   = (const float*)d_in[1];
    const float* ro     = (const float*)d_in[2];
    const float* rd     = (const float*)d_in[3];
    const float* weight = (const float*)d_in[4];
    const float* w1     = (const float*)d_in[5];
    const float* b1     = (const float*)d_in[6];
    const float* w2     = (const float*)d_in[7];
    const float* b2     = (const float*)d_in[8];
    float* out = (float*)d_out;

    cudaFuncSetAttribute(k_model, cudaFuncAttributeMaxDynamicSharedMemorySize, SM_TOTAL_BYTES);

    k_init<<<1, 1>>>();
    k_transpose<<<dim3(8, 256, 6), dim3(32, 8)>>>(front, back);
    k_model<<<296, 512, SM_TOTAL_BYTES>>>(ro, rd, weight, w1, b1, w2, b2, 0);
    k_fine<<<NRAY / FD_T, FD_T>>>();
    k_model<<<296, 512, SM_TOTAL_BYTES>>>(ro, rd, weight, w1, b1, w2, b2, 1);
    k_final<<<NRAY / 8, 256>>>(ro, rd, out);
    (void)in_sizes; (void)n_in; (void)out_size;
}

// round 11
// speedup vs baseline: 4.4332x; 1.0727x over previous
#include <cuda_runtime.h>
#include <cuda_fp16.h>
#include <cstdint>
#include <math.h>

// ---------------- problem constants ----------------
#define Bb 2
#define Rr 4096
#define Ss 48
#define NRAY   (Bb*Rr)        // 8192
#define NSAMP  (NRAY*Ss)      // 393216
#define NG16   (NSAMP/16)     // 24576

#define RAY_START 2.25f
#define STEPF 0.0223404255319148936f  // (3.3-2.25)/47

#define OUT_RGB   0
#define OUT_DEPTH 262144
#define OUT_WT    270336
#define OUT_XYZ   278528

// ---------------- scratch ----------------
__device__ __half g_planes_h[(size_t)Bb*3*256*256*64];
__device__ float g_depth_c[NSAMP];
__device__ float g_depth_f[NSAMP];
__device__ float g_col_c[(size_t)NSAMP*32];
__device__ float g_col_f[(size_t)NSAMP*32];
__device__ float g_sig_c[NSAMP];
__device__ float g_sig_f[NSAMP];
__device__ int   g_dmin_bits;
__device__ int   g_dmax_bits;

// ---------------- math helpers ----------------
__device__ __forceinline__ float softplusf(float x) {
    return fmaxf(x, 0.0f) + log1pf(expf(-fabsf(x)));
}
__device__ __forceinline__ float softplus_fast(float x) {
    return fmaxf(x, 0.0f) + __logf(1.0f + __expf(-fabsf(x)));
}
__device__ __forceinline__ float sigmoid_fast(float x) {
    return __fdividef(1.0f, 1.0f + __expf(-x));
}

__device__ __forceinline__ uint32_t smaddr(const void* p) {
    return (uint32_t)__cvta_generic_to_shared(p);
}
__device__ __forceinline__ void ldsm_x4(uint32_t& r0, uint32_t& r1, uint32_t& r2, uint32_t& r3, uint32_t a) {
    asm volatile("ldmatrix.sync.aligned.m8n8.x4.shared.b16 {%0,%1,%2,%3}, [%4];"
                 : "=r"(r0), "=r"(r1), "=r"(r2), "=r"(r3) : "r"(a));
}
__device__ __forceinline__ void ldsm_x2(uint32_t& r0, uint32_t& r1, uint32_t a) {
    asm volatile("ldmatrix.sync.aligned.m8n8.x2.shared.b16 {%0,%1}, [%2];"
                 : "=r"(r0), "=r"(r1) : "r"(a));
}
__device__ __forceinline__ void mma_f16(float& d0, float& d1, float& d2, float& d3,
                                        uint32_t a0, uint32_t a1, uint32_t a2, uint32_t a3,
                                        uint32_t b0, uint32_t b1) {
    asm volatile(
        "mma.sync.aligned.m16n8k16.row.col.f32.f16.f16.f32 "
        "{%0,%1,%2,%3}, {%4,%5,%6,%7}, {%8,%9}, {%0,%1,%2,%3};"
        : "+f"(d0), "+f"(d1), "+f"(d2), "+f"(d3)
        : "r"(a0), "r"(a1), "r"(a2), "r"(a3), "r"(b0), "r"(b1));
}

// ---------------- Threefry-2x32 (JAX, partitionable variant) ----------------
__device__ __forceinline__ uint32_t rotl32(uint32_t x, int r) {
    return (x << r) | (x >> (32 - r));
}
__device__ __forceinline__ void tf2x32(uint32_t k0, uint32_t k1,
                                       uint32_t x0, uint32_t x1,
                                       uint32_t& o0, uint32_t& o1) {
    uint32_t ks2 = k0 ^ k1 ^ 0x1BD11BDAu;
    x0 += k0; x1 += k1;
#define TFR(r) { x0 += x1; x1 = rotl32(x1, r); x1 ^= x0; }
    TFR(13) TFR(15) TFR(26) TFR(6)  x0 += k1;  x1 += ks2 + 1u;
    TFR(17) TFR(29) TFR(16) TFR(24) x0 += ks2; x1 += k0 + 2u;
    TFR(13) TFR(15) TFR(26) TFR(6)  x0 += k0;  x1 += k1 + 3u;
    TFR(17) TFR(29) TFR(16) TFR(24) x0 += k1;  x1 += ks2 + 4u;
    TFR(13) TFR(15) TFR(26) TFR(6)  x0 += ks2; x1 += k0 + 5u;
#undef TFR
    o0 = x0; o1 = x1;
}
__device__ __forceinline__ void derive_key(uint32_t idx, uint32_t& ka, uint32_t& kb) {
    tf2x32(0u, 42u, 0u, idx, ka, kb);
}
__device__ __forceinline__ float tf_uniform(uint32_t ka, uint32_t kb, uint32_t i) {
    uint32_t o0, o1;
    tf2x32(ka, kb, 0u, i, o0, o1);
    uint32_t bits = o0 ^ o1;
    float f = __uint_as_float((bits >> 9) | 0x3f800000u) - 1.0f;
    return fmaxf(f, 0.0f);
}

// ---------------- kernel 1: transpose planes to channel-last fp16 (+ init scalars) ----------------
__global__ void k_transpose(const float* __restrict__ front, const float* __restrict__ back) {
    __shared__ float tf[32][33];
    __shared__ float tb[32][33];
    if (blockIdx.x == 0 && blockIdx.y == 0 && blockIdx.z == 0 &&
        threadIdx.x == 0 && threadIdx.y == 0) {
        g_dmin_bits = 0x7f800000;
        g_dmax_bits = 0x00000000;
    }
    int bp = blockIdx.z;
    int y  = blockIdx.y;
    int x0 = blockIdx.x * 32;
    int tx = threadIdx.x, ty = threadIdx.y;
    __half2* out = (__half2*)g_planes_h;
#pragma unroll
    for (int i = 0; i < 4; i++) {
        int c = ty + i * 8;
        size_t src = ((size_t)(bp * 32 + c) * 65536) + (size_t)y * 256 + x0 + tx;
        tf[c][tx] = front[src];
        tb[c][tx] = back[src];
    }
    __syncthreads();
#pragma unroll
    for (int i = 0; i < 4; i++) {
        int xx = ty + i * 8;
        out[(((size_t)bp * 65536) + (size_t)y * 256 + x0 + xx) * 32 + tx] =
            __floats2half2_rn(tf[tx][xx], tb[tx][xx]);
    }
}

// ---------------- kernel 2: model, warp per 16-sample group, fp16 mma MLP ----------------
#define SM_W1H  0
#define SM_W2H  3328
#define SM_B1   4768
#define SM_B2   4832
#define SM_WSIG 4872
#define SM_XB   4968
#define SM_HB   18280
#define SM_TOTAL_BYTES (27496*4)

extern __shared__ __align__(16) float smem[];

struct Axis { float w0, w1; int i0, i1; bool ok; };
__device__ __forceinline__ Axis axis_prep(float g) {
    Axis a;
    float x = (g + 1.0f) * 128.0f - 0.5f;
    float x0f = floorf(x);
    int x0 = (int)x0f;
    float w = x - x0f;
    bool v0 = (x0 >= 0) & (x0 < 256);
    bool v1 = (x0 >= -1) & (x0 < 255);
    a.w0 = v0 ? 1.0f - w : 0.0f;
    a.w1 = v1 ? w : 0.0f;
    a.i0 = min(max(x0, 0), 255);
    a.i1 = min(max(x0 + 1, 0), 255);
    a.ok = (x0 >= -1) & (x0 <= 255);
    return a;
}

__global__ void __launch_bounds__(512, 2) k_model(
    const float* __restrict__ ro, const float* __restrict__ rd,
    const float* __restrict__ weight,
    const float* __restrict__ w1, const float* __restrict__ b1,
    const float* __restrict__ w2, const float* __restrict__ b2,
    int fine_pass)
{
    __half* w1h = (__half*)(smem + SM_W1H);
    __half* w2h = (__half*)(smem + SM_W2H);
    float* b1s  = smem + SM_B1;
    float* b2s  = smem + SM_B2;
    float* wsig = smem + SM_WSIG;

    int tid = threadIdx.x;
    for (int i = tid; i < 96 * 64; i += 512) {
        int k = i >> 6, n = i & 63;
        w1h[n * 104 + k] = __float2half(w1[i]);
    }
    for (int i = tid; i < 64 * 40; i += 512) {
        int k = i / 40, n = i % 40;
        w2h[n * 72 + k] = (n < 33) ? __float2half(w2[k * 33 + n]) : __half(0.0f);
    }
    if (tid < 64) b1s[tid] = b1[tid];
    if (tid < 40) b2s[tid] = (tid < 33) ? b2[tid] : 0.0f;
    if (tid < 96) wsig[tid] = 1.0f / (1.0f + expf(-weight[tid]));
    __syncthreads();

    float* cols = fine_pass ? g_col_f : g_col_c;
    float* sigs = fine_pass ? g_sig_f : g_sig_c;

    int lane = tid & 31, wrp = tid >> 5;
    int tq = lane & 3;
    __half* xh = (__half*)(smem + SM_XB) + wrp * 1664;   // [16][104]
    __half* hh = (__half*)(smem + SM_HB) + wrp * 1152;   // [16][72]
    float*  outf = (float*)xh;                           // reuse as [16][44] float

    uint32_t a_x = smaddr(xh) + (((lane & 15) * 104 + ((lane >> 4) * 8)) * 2);
    uint32_t a_h = smaddr(hh) + (((lane & 15) * 72  + ((lane >> 4) * 8)) * 2);
    uint32_t b_w1 = smaddr(w1h) + (((lane & 7) * 104 + (((lane >> 3) & 1) * 8)) * 2);
    uint32_t b_w2 = smaddr(w2h) + (((lane & 7) * 72  + (((lane >> 3) & 1) * 8)) * 2);

    float wk0 = wsig[lane], wk1 = wsig[32 + lane], wk2 = wsig[64 + lane];

    uint32_t ka0, kb0; derive_key(0u, ka0, kb0);

    int g0 = blockIdx.x * 16 + wrp;
    int nG = gridDim.x * 16;

    for (int g = g0; g < NG16; g += nG) {
        int smp0 = g * 16;
        int ray = g / 3;
        int b = ray >> 12;
        float ox = 2.0f * ro[ray * 3 + 0], oy = 2.0f * ro[ray * 3 + 1], oz = 2.0f * ro[ray * 3 + 2];
        float dx = 2.0f * rd[ray * 3 + 0], dy = 2.0f * rd[ray * 3 + 1], dz = 2.0f * rd[ray * 3 + 2];
        const __half2* pb0 = (const __half2*)g_planes_h + (size_t)b * 3 * 65536 * 32 + (size_t)lane;
        const __half2* pb1 = pb0 + (size_t)65536 * 32;
        const __half2* pb2 = pb1 + (size_t)65536 * 32;

        int sidx = smp0 + (lane & 15);
        float dval;
        if (!fine_pass) {
            int sloc = (g % 3) * 16 + (lane & 15);
            float u = tf_uniform(ka0, kb0, (uint32_t)sidx);
            float d0 = RAY_START + (float)sloc * STEPF;
            dval = d0 + u * STEPF;
            if (lane < 16) g_depth_c[sidx] = dval;
        } else {
            dval = g_depth_f[sidx];
        }

        // ---- phase A: gather 16 samples, lane = channel; OOB skips (warp-uniform) ----
#pragma unroll 4
        for (int s = 0; s < 16; s++) {
            float d = __shfl_sync(0xffffffffu, dval, s);
            float cx = fmaf(d, dx, ox);
            float cy = fmaf(d, dy, oy);
            float cz = fmaf(d, dz, oz);
            float xv0 = 0.0f, xv1 = 0.0f, xv2 = 0.0f;
            Axis ax = axis_prep(cx);
            if (ax.ok) {
                Axis ay = axis_prep(cy);
                Axis az = axis_prep(cz);
                if (ay.ok) {   // plane 0: (ax, ay)
                    float2 v00 = __half22float2(pb0[(ay.i0 * 256 + ax.i0) * 32]);
                    float2 v01 = __half22float2(pb0[(ay.i0 * 256 + ax.i1) * 32]);
                    float2 v10 = __half22float2(pb0[(ay.i1 * 256 + ax.i0) * 32]);
                    float2 v11 = __half22float2(pb0[(ay.i1 * 256 + ax.i1) * 32]);
                    float w00 = ax.w0 * ay.w0, w01 = ax.w1 * ay.w0;
                    float w10 = ax.w0 * ay.w1, w11 = ax.w1 * ay.w1;
                    float aF = fmaf(w11, v11.x, fmaf(w10, v10.x, fmaf(w01, v01.x, w00 * v00.x)));
                    float aB = fmaf(w11, v11.y, fmaf(w10, v10.y, fmaf(w01, v01.y, w00 * v00.y)));
                    xv0 = wk0 * aF + (1.0f - wk0) * aB;
                }
                if (az.ok) {
                    {   // plane 1: (ax, az)
                        float2 v00 = __half22float2(pb1[(az.i0 * 256 + ax.i0) * 32]);
                        float2 v01 = __half22float2(pb1[(az.i0 * 256 + ax.i1) * 32]);
                        float2 v10 = __half22float2(pb1[(az.i1 * 256 + ax.i0) * 32]);
                        float2 v11 = __half22float2(pb1[(az.i1 * 256 + ax.i1) * 32]);
                        float w00 = ax.w0 * az.w0, w01 = ax.w1 * az.w0;
                        float w10 = ax.w0 * az.w1, w11 = ax.w1 * az.w1;
                        float aF = fmaf(w11, v11.x, fmaf(w10, v10.x, fmaf(w01, v01.x, w00 * v00.x)));
                        float aB = fmaf(w11, v11.y, fmaf(w10, v10.y, fmaf(w01, v01.y, w00 * v00.y)));
                        xv1 = wk1 * aF + (1.0f - wk1) * aB;
                    }
                    {   // plane 2: (az, ax)
                        float2 v00 = __half22float2(pb2[(ax.i0 * 256 + az.i0) * 32]);
                        float2 v01 = __half22float2(pb2[(ax.i0 * 256 + az.i1) * 32]);
                        float2 v10 = __half22float2(pb2[(ax.i1 * 256 + az.i0) * 32]);
                        float2 v11 = __half22float2(pb2[(ax.i1 * 256 + az.i1) * 32]);
                        float w00 = az.w0 * ax.w0, w01 = az.w1 * ax.w0;
                        float w10 = az.w0 * ax.w1, w11 = az.w1 * ax.w1;
                        float aF = fmaf(w11, v11.x, fmaf(w10, v10.x, fmaf(w01, v01.x, w00 * v00.x)));
                        float aB = fmaf(w11, v11.y, fmaf(w10, v10.y, fmaf(w01, v01.y, w00 * v00.y)));
                        xv2 = wk2 * aF + (1.0f - wk2) * aB;
                    }
                }
            }
            xh[s * 104 + lane]      = __float2half(xv0);
            xh[s * 104 + 32 + lane] = __float2half(xv1);
            xh[s * 104 + 64 + lane] = __float2half(xv2);
        }
        __syncwarp();

        // ---- layer1: [16x96] @ [96x64], fp16 mma, n split in halves ----
#pragma unroll
        for (int hn = 0; hn < 2; hn++) {
            float d1[4][4];
#pragma unroll
            for (int nt2 = 0; nt2 < 4; nt2++) {
                int nt = hn * 4 + nt2;
                float bl = b1s[nt * 8 + 2 * tq], bh = b1s[nt * 8 + 2 * tq + 1];
                d1[nt2][0] = bl; d1[nt2][1] = bh; d1[nt2][2] = bl; d1[nt2][3] = bh;
            }
#pragma unroll
            for (int kt = 0; kt < 6; kt++) {
                uint32_t a0, a1, a2, a3;
                ldsm_x4(a0, a1, a2, a3, a_x + kt * 32);
#pragma unroll
                for (int nt2 = 0; nt2 < 4; nt2++) {
                    int nt = hn * 4 + nt2;
                    uint32_t bv0, bv1;
                    ldsm_x2(bv0, bv1, b_w1 + nt * 1664 + kt * 32);
                    mma_f16(d1[nt2][0], d1[nt2][1], d1[nt2][2], d1[nt2][3], a0, a1, a2, a3, bv0, bv1);
                }
            }
            int gq = lane >> 2;
#pragma unroll
            for (int nt2 = 0; nt2 < 4; nt2++) {
                int nt = hn * 4 + nt2;
                *(__half2*)(hh + gq * 72 + nt * 8 + 2 * tq) =
                    __floats2half2_rn(softplus_fast(d1[nt2][0]), softplus_fast(d1[nt2][1]));
                *(__half2*)(hh + (gq + 8) * 72 + nt * 8 + 2 * tq) =
                    __floats2half2_rn(softplus_fast(d1[nt2][2]), softplus_fast(d1[nt2][3]));
            }
        }
        __syncwarp();

        // ---- layer2: [16x64] @ [64x40] ----
        float d2[5][4];
#pragma unroll
        for (int nt = 0; nt < 5; nt++) {
            float bl = b2s[nt * 8 + 2 * tq], bh = b2s[nt * 8 + 2 * tq + 1];
            d2[nt][0] = bl; d2[nt][1] = bh; d2[nt][2] = bl; d2[nt][3] = bh;
        }
#pragma unroll
        for (int kt = 0; kt < 4; kt++) {
            uint32_t a0, a1, a2, a3;
            ldsm_x4(a0, a1, a2, a3, a_h + kt * 32);
#pragma unroll
            for (int nt = 0; nt < 5; nt++) {
                uint32_t bv0, bv1;
                ldsm_x2(bv0, bv1, b_w2 + nt * 1152 + kt * 32);
                mma_f16(d2[nt][0], d2[nt][1], d2[nt][2], d2[nt][3], a0, a1, a2, a3, bv0, bv1);
            }
        }
        __syncwarp();
        {
            int gq = lane >> 2;
#pragma unroll
            for (int nt = 0; nt < 5; nt++) {
                *(float2*)(outf + gq * 44 + nt * 8 + 2 * tq)       = make_float2(d2[nt][0], d2[nt][1]);
                *(float2*)(outf + (gq + 8) * 44 + nt * 8 + 2 * tq) = make_float2(d2[nt][2], d2[nt][3]);
            }
        }
        __syncwarp();

#pragma unroll 4
        for (int s = 0; s < 16; s++) {
            float v = outf[s * 44 + 1 + lane];
            cols[(size_t)(smp0 + s) * 32 + lane] = sigmoid_fast(v) * 1.002f - 0.001f;
        }
        if (lane < 16) sigs[smp0 + lane] = outf[lane * 44];
        __syncwarp();
    }
}

// ---------------- kernel 3: fused coarse weights + importance sampling, WARP PER RAY ----------------
#define KF_W 8
__global__ void __launch_bounds__(KF_W*32) k_fine() {
    __shared__ float zsh[KF_W][49];
    __shared__ float ssh[KF_W][49];
    __shared__ float wsh[KF_W][48];
    __shared__ float zmsh[KF_W][48];
    __shared__ float cdfsh[KF_W][47];
    __shared__ float bmn[KF_W], bmx[KF_W];
    int lane = threadIdx.x & 31, wrp = threadIdx.x >> 5;
    int ray = blockIdx.x * KF_W + wrp;
    float* z   = zsh[wrp];
    float* sg  = ssh[wrp];
    float* w   = wsh[wrp];
    float* zm  = zmsh[wrp];
    float* cdf = cdfsh[wrp];

    for (int i = lane; i < 48; i += 32) {
        z[i]  = g_depth_c[ray * 48 + i];
        sg[i] = g_sig_c[ray * 48 + i];
    }
    __syncwarp();

    // intervals: 47 total; lane -> i=lane (all valid), i=32+lane (lane<15)
    float a0, t0, a1 = 0.0f, t1 = 1.0f;
    {
        int i = lane;
        float dens = softplusf(0.5f * (sg[i] + sg[i + 1]) - 1.0f);
        a0 = 1.0f - expf(-dens * (z[i + 1] - z[i]));
        t0 = 1.0f - a0 + 1e-10f;
        zm[i] = 0.5f * (z[i] + z[i + 1]);
    }
    if (lane < 15) {
        int i = 32 + lane;
        float dens = softplusf(0.5f * (sg[i] + sg[i + 1]) - 1.0f);
        a1 = 1.0f - expf(-dens * (z[i + 1] - z[i]));
        t1 = 1.0f - a1 + 1e-10f;
        zm[i] = 0.5f * (z[i] + z[i + 1]);
    }
    // exclusive product scan over t[0..46]
    float p0 = t0;
#pragma unroll
    for (int off = 1; off < 32; off <<= 1) {
        float v = __shfl_up_sync(0xffffffffu, p0, off);
        if (lane >= off) p0 *= v;
    }
    float tot0 = __shfl_sync(0xffffffffu, p0, 31);
    float p0prev = __shfl_up_sync(0xffffffffu, p0, 1);
    float P0 = (lane == 0) ? 1.0f : p0prev;
    float p1 = t1;
#pragma unroll
    for (int off = 1; off < 32; off <<= 1) {
        float v = __shfl_up_sync(0xffffffffu, p1, off);
        if (lane >= off) p1 *= v;
    }
    float p1prev = __shfl_up_sync(0xffffffffu, p1, 1);
    float P1 = tot0 * ((lane == 0) ? 1.0f : p1prev);

    w[lane] = a0 * P0;
    if (lane < 15) w[32 + lane] = a1 * P1;
    __syncwarp();

    // block-level depth min/max (one atomic pair per block)
    if (lane == 0) { bmn[wrp] = z[0]; bmx[wrp] = z[47]; }
    __syncthreads();
    if (threadIdx.x == 0) {
        float mn = bmn[0], mx = bmx[0];
#pragma unroll
        for (int i = 1; i < KF_W; i++) { mn = fminf(mn, bmn[i]); mx = fmaxf(mx, bmx[i]); }
        atomicMin(&g_dmin_bits, __float_as_int(mn));
        atomicMax(&g_dmax_bits, __float_as_int(mx));
    }

    // ws[j] = 0.5*(max(w[j],w[j+1]) + max(w[j+1],w[j+2])) + 0.01 + 1e-5, j=0..44
    float s0 = 0.0f, s1 = 0.0f;
    {
        int j = lane;
        if (j < 45)
            s0 = 0.5f * (fmaxf(w[j], w[j + 1]) + fmaxf(w[j + 1], w[j + 2])) + 0.01f + 1e-5f;
    }
    if (lane < 13) {
        int j = 32 + lane;
        s1 = 0.5f * (fmaxf(w[j], w[j + 1]) + fmaxf(w[j + 1], w[j + 2])) + 0.01f + 1e-5f;
    }
    // inclusive sum scan over ws[0..44]
    float q0 = s0;
#pragma unroll
    for (int off = 1; off < 32; off <<= 1) {
        float v = __shfl_up_sync(0xffffffffu, q0, off);
        if (lane >= off) q0 += v;
    }
    float tot0s = __shfl_sync(0xffffffffu, q0, 31);
    float q1 = s1;
#pragma unroll
    for (int off = 1; off < 32; off <<= 1) {
        float v = __shfl_up_sync(0xffffffffu, q1, off);
        if (lane >= off) q1 += v;
    }
    float sum = tot0s + __shfl_sync(0xffffffffu, q1, 31);
    // cdf[0..45]: cdf[j+1] = incl[j]/sum
    if (lane == 0) cdf[0] = 0.0f;
    if (lane < 45) cdf[lane + 1] = q0 / sum;          // wait: only j<45 valid; lane 0..31 all j<45? lane<=31<45 yes
    if (lane < 13) cdf[33 + lane] = (tot0s + q1) / sum;
    __syncwarp();

    uint32_t ka, kb; derive_key(1u, ka, kb);
#pragma unroll
    for (int half = 0; half < 2; half++) {
        int j = half * 32 + lane;
        if (j < 48) {
            float u = tf_uniform(ka, kb, (uint32_t)(ray * 48 + j));
            int pos = 0;
#pragma unroll
            for (int step = 32; step; step >>= 1) {
                int np = pos + step;
                if (np <= 46 && cdf[np - 1] <= u) pos = np;
            }
            int ind = pos;
            int below = ind - 1; if (below < 0) below = 0;
            int above = ind;     if (above > 45) above = 45;
            float c0 = cdf[below], c1 = cdf[above];
            float b0 = zm[below],  b1v = zm[above];
            float denom = c1 - c0;
            if (denom < 1e-5f) denom = 1.0f;
            g_depth_f[ray * 48 + j] = b0 + (u - c0) / denom * (b1v - b0);
        }
    }
}

// ---------------- kernel 4: unify + final march, warp per ray ----------------
__global__ void __launch_bounds__(256) k_final(
    const float* __restrict__ ro, const float* __restrict__ rd,
    float* __restrict__ out)
{
    __shared__ __align__(16) float sd[8][96];
    __shared__ __align__(16) float ssg[8][96];
    __shared__ __align__(16) int   sidx[8][96];
    int lane = threadIdx.x & 31, wrp = threadIdx.x >> 5;
    int ray = blockIdx.x * 8 + wrp;

    for (int i = lane; i < 48; i += 32) {
        sd[wrp][i]       = g_depth_c[ray * 48 + i];
        sd[wrp][48 + i]  = g_depth_f[ray * 48 + i];
        ssg[wrp][i]      = g_sig_c[ray * 48 + i];
        ssg[wrp][48 + i] = g_sig_f[ray * 48 + i];
    }
    __syncwarp();
#pragma unroll
    for (int t = 0; t < 3; t++) {
        int e = lane + t * 32;
        float de = sd[wrp][e];
        int rank = 0;
        for (int j = 0; j < 96; j++) {
            float dj = sd[wrp][j];
            rank += (dj < de || (dj == de && j < e)) ? 1 : 0;
        }
        sidx[wrp][rank] = e;
    }
    __syncwarp();

    float T = 1.0f, accW = 0.0f, accWD = 0.0f, accC = 0.0f;
    int i0 = sidx[wrp][0];
    float dp = sd[wrp][i0], sp = ssg[wrp][i0];
    const float* cb0 = (i0 < 48) ? g_col_c : g_col_f;
    float cp = cb0[((size_t)ray * 48 + (i0 < 48 ? i0 : i0 - 48)) * 32 + lane];

    for (int s = 1; s < 96; s++) {
        int i = sidx[wrp][s];
        float dc = sd[wrp][i], sc = ssg[wrp][i];
        const float* cb = (i < 48) ? g_col_c : g_col_f;
        float cc = cb[((size_t)ray * 48 + (i < 48 ? i : i - 48)) * 32 + lane];
        float delta = dc - dp;
        float dens = softplus_fast(0.5f * (sc + sp) - 1.0f);
        float alpha = 1.0f - __expf(-dens * delta);
        float wgt = alpha * T;
        T *= (1.0f - alpha + 1e-10f);
        accC  += wgt * 0.5f * (cc + cp);
        accW  += wgt;
        accWD += wgt * 0.5f * (dc + dp);
        dp = dc; sp = sc; cp = cc;
    }

    out[OUT_RGB + (size_t)ray * 32 + lane] = accC * 2.0f - 1.0f;
    if (lane == 0) {
        float wt = accW;
        float dep = accWD / wt;
        if (isnan(dep)) dep = __int_as_float(0x7f800000);
        float dmin = __int_as_float(g_dmin_bits);
        float dmax = __int_as_float(g_dmax_bits);
        dep = fminf(fmaxf(dep, dmin), dmax);
        out[OUT_DEPTH + ray] = dep;
        out[OUT_WT + ray] = wt;
    }
    if (lane < 3) {
        float o_ = ro[ray * 3 + lane], d_ = rd[ray * 3 + lane];
        out[OUT_XYZ + (size_t)ray * 3 + lane] = 2.0f * (o_ * accW + d_ * accWD) - 1.0f;
    }
}

// ---------------- launcher ----------------
extern "C" void kernel_launch(void* const* d_in, const int* in_sizes, int n_in,
                              void* d_out, int out_size) {
    const float* front  = (const float*)d_in[0];
    const float* back   = (const float*)d_in[1];
    const float* ro     = (const float*)d_in[2];
    const float* rd     = (const float*)d_in[3];
    const float* weight = (const float*)d_in[4];
    const float* w1     = (const float*)d_in[5];
    const float* b1     = (const float*)d_in[6];
    const float* w2     = (const float*)d_in[7];
    const float* b2     = (const float*)d_in[8];
    float* out = (float*)d_out;

    cudaFuncSetAttribute(k_model, cudaFuncAttributeMaxDynamicSharedMemorySize, SM_TOTAL_BYTES);

    k_transpose<<<dim3(8, 256, 6), dim3(32, 8)>>>(front, back);
    k_model<<<296, 512, SM_TOTAL_BYTES>>>(ro, rd, weight, w1, b1, w2, b2, 0);
    k_fine<<<NRAY / KF_W, KF_W * 32>>>();
    k_model<<<296, 512, SM_TOTAL_BYTES>>>(ro, rd, weight, w1, b1, w2, b2, 1);
    k_final<<<NRAY / 8, 256>>>(ro, rd, out);
    (void)in_sizes; (void)n_in; (void)out_size;
}

// round 12
// speedup vs baseline: 4.7743x; 1.0769x over previous
#include <cuda_runtime.h>
#include <cuda_fp16.h>
#include <cstdint>
#include <math.h>

// ---------------- problem constants ----------------
#define Bb 2
#define Rr 4096
#define Ss 48
#define NRAY   (Bb*Rr)        // 8192
#define NSAMP  (NRAY*Ss)      // 393216
#define NG16   (NSAMP/16)     // 24576

#define RAY_START 2.25f
#define STEPF 0.0223404255319148936f  // (3.3-2.25)/47

#define OUT_RGB   0
#define OUT_DEPTH 262144
#define OUT_WT    270336
#define OUT_XYZ   278528

#define MODEL_BLOCKS 296
#define MODEL_WARPS  (MODEL_BLOCKS*16)   // 4736

// ---------------- scratch ----------------
__device__ __half g_planes_h[(size_t)Bb*3*256*256*64];
__device__ float g_depth_c[NSAMP];
__device__ float g_depth_f[NSAMP];
__device__ float g_col_c[(size_t)NSAMP*32];
__device__ float g_col_f[(size_t)NSAMP*32];
__device__ float g_sig_c[NSAMP];
__device__ float g_sig_f[NSAMP];
__device__ int   g_dmin_bits;
__device__ int   g_dmax_bits;
__device__ unsigned int g_ctr0;   // coarse-pass work counter (reset in k_transpose)
__device__ unsigned int g_ctr1;   // fine-pass work counter (reset in k_fine)

// ---------------- math helpers ----------------
__device__ __forceinline__ float softplusf(float x) {
    return fmaxf(x, 0.0f) + log1pf(expf(-fabsf(x)));
}
__device__ __forceinline__ float softplus_fast(float x) {
    return fmaxf(x, 0.0f) + __logf(1.0f + __expf(-fabsf(x)));
}
__device__ __forceinline__ float sigmoid_fast(float x) {
    return __fdividef(1.0f, 1.0f + __expf(-x));
}

__device__ __forceinline__ uint32_t smaddr(const void* p) {
    return (uint32_t)__cvta_generic_to_shared(p);
}
__device__ __forceinline__ void ldsm_x4(uint32_t& r0, uint32_t& r1, uint32_t& r2, uint32_t& r3, uint32_t a) {
    asm volatile("ldmatrix.sync.aligned.m8n8.x4.shared.b16 {%0,%1,%2,%3}, [%4];"
                 : "=r"(r0), "=r"(r1), "=r"(r2), "=r"(r3) : "r"(a));
}
__device__ __forceinline__ void ldsm_x2(uint32_t& r0, uint32_t& r1, uint32_t a) {
    asm volatile("ldmatrix.sync.aligned.m8n8.x2.shared.b16 {%0,%1}, [%2];"
                 : "=r"(r0), "=r"(r1) : "r"(a));
}
__device__ __forceinline__ void mma_f16(float& d0, float& d1, float& d2, float& d3,
                                        uint32_t a0, uint32_t a1, uint32_t a2, uint32_t a3,
                                        uint32_t b0, uint32_t b1) {
    asm volatile(
        "mma.sync.aligned.m16n8k16.row.col.f32.f16.f16.f32 "
        "{%0,%1,%2,%3}, {%4,%5,%6,%7}, {%8,%9}, {%0,%1,%2,%3};"
        : "+f"(d0), "+f"(d1), "+f"(d2), "+f"(d3)
        : "r"(a0), "r"(a1), "r"(a2), "r"(a3), "r"(b0), "r"(b1));
}

// ---------------- Threefry-2x32 (JAX, partitionable variant) ----------------
__device__ __forceinline__ uint32_t rotl32(uint32_t x, int r) {
    return (x << r) | (x >> (32 - r));
}
__device__ __forceinline__ void tf2x32(uint32_t k0, uint32_t k1,
                                       uint32_t x0, uint32_t x1,
                                       uint32_t& o0, uint32_t& o1) {
    uint32_t ks2 = k0 ^ k1 ^ 0x1BD11BDAu;
    x0 += k0; x1 += k1;
#define TFR(r) { x0 += x1; x1 = rotl32(x1, r); x1 ^= x0; }
    TFR(13) TFR(15) TFR(26) TFR(6)  x0 += k1;  x1 += ks2 + 1u;
    TFR(17) TFR(29) TFR(16) TFR(24) x0 += ks2; x1 += k0 + 2u;
    TFR(13) TFR(15) TFR(26) TFR(6)  x0 += k0;  x1 += k1 + 3u;
    TFR(17) TFR(29) TFR(16) TFR(24) x0 += k1;  x1 += ks2 + 4u;
    TFR(13) TFR(15) TFR(26) TFR(6)  x0 += ks2; x1 += k0 + 5u;
#undef TFR
    o0 = x0; o1 = x1;
}
__device__ __forceinline__ void derive_key(uint32_t idx, uint32_t& ka, uint32_t& kb) {
    tf2x32(0u, 42u, 0u, idx, ka, kb);
}
__device__ __forceinline__ float tf_uniform(uint32_t ka, uint32_t kb, uint32_t i) {
    uint32_t o0, o1;
    tf2x32(ka, kb, 0u, i, o0, o1);
    uint32_t bits = o0 ^ o1;
    float f = __uint_as_float((bits >> 9) | 0x3f800000u) - 1.0f;
    return fmaxf(f, 0.0f);
}

// ---------------- kernel 1: transpose planes to channel-last fp16 (+ init scalars) ----------------
__global__ void k_transpose(const float* __restrict__ front, const float* __restrict__ back) {
    __shared__ float tf[32][33];
    __shared__ float tb[32][33];
    if (blockIdx.x == 0 && blockIdx.y == 0 && blockIdx.z == 0 &&
        threadIdx.x == 0 && threadIdx.y == 0) {
        g_dmin_bits = 0x7f800000;
        g_dmax_bits = 0x00000000;
        g_ctr0 = MODEL_WARPS;     // coarse-pass counter: warps own [0, MODEL_WARPS) statically
    }
    int bp = blockIdx.z;
    int y  = blockIdx.y;
    int x0 = blockIdx.x * 32;
    int tx = threadIdx.x, ty = threadIdx.y;
    __half2* out = (__half2*)g_planes_h;
#pragma unroll
    for (int i = 0; i < 4; i++) {
        int c = ty + i * 8;
        size_t src = ((size_t)(bp * 32 + c) * 65536) + (size_t)y * 256 + x0 + tx;
        tf[c][tx] = front[src];
        tb[c][tx] = back[src];
    }
    __syncthreads();
#pragma unroll
    for (int i = 0; i < 4; i++) {
        int xx = ty + i * 8;
        out[(((size_t)bp * 65536) + (size_t)y * 256 + x0 + xx) * 32 + tx] =
            __floats2half2_rn(tf[tx][xx], tb[tx][xx]);
    }
}

// ---------------- kernel 2: model, warp per 16-sample group, fp16 mma MLP ----------------
#define SM_W1H  0
#define SM_W2H  3328
#define SM_B1   4768
#define SM_B2   4832
#define SM_WSIG 4872
#define SM_XB   4968
#define SM_HB   18280
#define SM_TOTAL_BYTES (27496*4)

extern __shared__ __align__(16) float smem[];

struct Axis { float w0, w1; int i0, i1; bool ok; };
__device__ __forceinline__ Axis axis_prep(float g) {
    Axis a;
    float x = (g + 1.0f) * 128.0f - 0.5f;
    float x0f = floorf(x);
    int x0 = (int)x0f;
    float w = x - x0f;
    bool v0 = (x0 >= 0) & (x0 < 256);
    bool v1 = (x0 >= -1) & (x0 < 255);
    a.w0 = v0 ? 1.0f - w : 0.0f;
    a.w1 = v1 ? w : 0.0f;
    a.i0 = min(max(x0, 0), 255);
    a.i1 = min(max(x0 + 1, 0), 255);
    a.ok = (x0 >= -1) & (x0 <= 255);
    return a;
}

__global__ void __launch_bounds__(512, 2) k_model(
    const float* __restrict__ ro, const float* __restrict__ rd,
    const float* __restrict__ weight,
    const float* __restrict__ w1, const float* __restrict__ b1,
    const float* __restrict__ w2, const float* __restrict__ b2,
    int fine_pass)
{
    __half* w1h = (__half*)(smem + SM_W1H);
    __half* w2h = (__half*)(smem + SM_W2H);
    float* b1s  = smem + SM_B1;
    float* b2s  = smem + SM_B2;
    float* wsig = smem + SM_WSIG;

    int tid = threadIdx.x;
    for (int i = tid; i < 96 * 64; i += 512) {
        int k = i >> 6, n = i & 63;
        w1h[n * 104 + k] = __float2half(w1[i]);
    }
    for (int i = tid; i < 64 * 40; i += 512) {
        int k = i / 40, n = i % 40;
        w2h[n * 72 + k] = (n < 33) ? __float2half(w2[k * 33 + n]) : __half(0.0f);
    }
    if (tid < 64) b1s[tid] = b1[tid];
    if (tid < 40) b2s[tid] = (tid < 33) ? b2[tid] : 0.0f;
    if (tid < 96) wsig[tid] = 1.0f / (1.0f + expf(-weight[tid]));
    __syncthreads();

    float* cols = fine_pass ? g_col_f : g_col_c;
    float* sigs = fine_pass ? g_sig_f : g_sig_c;
    unsigned int* ctr = fine_pass ? &g_ctr1 : &g_ctr0;

    int lane = tid & 31, wrp = tid >> 5;
    int tq = lane & 3;
    __half* xh = (__half*)(smem + SM_XB) + wrp * 1664;   // [16][104]
    __half* hh = (__half*)(smem + SM_HB) + wrp * 1152;   // [16][72]
    float*  outf = (float*)xh;                           // reuse as [16][44] float

    uint32_t a_x = smaddr(xh) + (((lane & 15) * 104 + ((lane >> 4) * 8)) * 2);
    uint32_t a_h = smaddr(hh) + (((lane & 15) * 72  + ((lane >> 4) * 8)) * 2);
    uint32_t b_w1 = smaddr(w1h) + (((lane & 7) * 104 + (((lane >> 3) & 1) * 8)) * 2);
    uint32_t b_w2 = smaddr(w2h) + (((lane & 7) * 72  + (((lane >> 3) & 1) * 8)) * 2);

    float wk0 = wsig[lane], wk1 = wsig[32 + lane], wk2 = wsig[64 + lane];

    uint32_t ka0, kb0; derive_key(0u, ka0, kb0);

    // dynamic work-stealing: first group = static warp id, then atomic grabs
    int g = blockIdx.x * 16 + wrp;

    while (g < NG16) {
        int smp0 = g * 16;
        int ray = g / 3;
        int b = ray >> 12;
        float ox = 2.0f * ro[ray * 3 + 0], oy = 2.0f * ro[ray * 3 + 1], oz = 2.0f * ro[ray * 3 + 2];
        float dx = 2.0f * rd[ray * 3 + 0], dy = 2.0f * rd[ray * 3 + 1], dz = 2.0f * rd[ray * 3 + 2];
        const __half2* pb0 = (const __half2*)g_planes_h + (size_t)b * 3 * 65536 * 32 + (size_t)lane;
        const __half2* pb1 = pb0 + (size_t)65536 * 32;
        const __half2* pb2 = pb1 + (size_t)65536 * 32;

        int sidx = smp0 + (lane & 15);
        float dval;
        if (!fine_pass) {
            int sloc = (g % 3) * 16 + (lane & 15);
            float u = tf_uniform(ka0, kb0, (uint32_t)sidx);
            float d0 = RAY_START + (float)sloc * STEPF;
            dval = d0 + u * STEPF;
            if (lane < 16) g_depth_c[sidx] = dval;
        } else {
            dval = g_depth_f[sidx];
        }

        // grab next group early (overlaps with the gather work below)
        int gnext;
        if (lane == 0) gnext = (int)atomicAdd(ctr, 1u);
        gnext = __shfl_sync(0xffffffffu, gnext, 0);

        // ---- phase A: gather 16 samples, lane = channel; OOB skips (warp-uniform) ----
#pragma unroll 4
        for (int s = 0; s < 16; s++) {
            float d = __shfl_sync(0xffffffffu, dval, s);
            float cx = fmaf(d, dx, ox);
            float cy = fmaf(d, dy, oy);
            float cz = fmaf(d, dz, oz);
            float xv0 = 0.0f, xv1 = 0.0f, xv2 = 0.0f;
            Axis ax = axis_prep(cx);
            if (ax.ok) {
                Axis ay = axis_prep(cy);
                Axis az = axis_prep(cz);
                if (ay.ok) {   // plane 0: (ax, ay)
                    float2 v00 = __half22float2(pb0[(ay.i0 * 256 + ax.i0) * 32]);
                    float2 v01 = __half22float2(pb0[(ay.i0 * 256 + ax.i1) * 32]);
                    float2 v10 = __half22float2(pb0[(ay.i1 * 256 + ax.i0) * 32]);
                    float2 v11 = __half22float2(pb0[(ay.i1 * 256 + ax.i1) * 32]);
                    float w00 = ax.w0 * ay.w0, w01 = ax.w1 * ay.w0;
                    float w10 = ax.w0 * ay.w1, w11 = ax.w1 * ay.w1;
                    float aF = fmaf(w11, v11.x, fmaf(w10, v10.x, fmaf(w01, v01.x, w00 * v00.x)));
                    float aB = fmaf(w11, v11.y, fmaf(w10, v10.y, fmaf(w01, v01.y, w00 * v00.y)));
                    xv0 = wk0 * aF + (1.0f - wk0) * aB;
                }
                if (az.ok) {
                    {   // plane 1: (ax, az)
                        float2 v00 = __half22float2(pb1[(az.i0 * 256 + ax.i0) * 32]);
                        float2 v01 = __half22float2(pb1[(az.i0 * 256 + ax.i1) * 32]);
                        float2 v10 = __half22float2(pb1[(az.i1 * 256 + ax.i0) * 32]);
                        float2 v11 = __half22float2(pb1[(az.i1 * 256 + ax.i1) * 32]);
                        float w00 = ax.w0 * az.w0, w01 = ax.w1 * az.w0;
                        float w10 = ax.w0 * az.w1, w11 = ax.w1 * az.w1;
                        float aF = fmaf(w11, v11.x, fmaf(w10, v10.x, fmaf(w01, v01.x, w00 * v00.x)));
                        float aB = fmaf(w11, v11.y, fmaf(w10, v10.y, fmaf(w01, v01.y, w00 * v00.y)));
                        xv1 = wk1 * aF + (1.0f - wk1) * aB;
                    }
                    {   // plane 2: (az, ax)
                        float2 v00 = __half22float2(pb2[(ax.i0 * 256 + az.i0) * 32]);
                        float2 v01 = __half22float2(pb2[(ax.i0 * 256 + az.i1) * 32]);
                        float2 v10 = __half22float2(pb2[(ax.i1 * 256 + az.i0) * 32]);
                        float2 v11 = __half22float2(pb2[(ax.i1 * 256 + az.i1) * 32]);
                        float w00 = az.w0 * ax.w0, w01 = az.w1 * ax.w0;
                        float w10 = az.w0 * ax.w1, w11 = az.w1 * ax.w1;
                        float aF = fmaf(w11, v11.x, fmaf(w10, v10.x, fmaf(w01, v01.x, w00 * v00.x)));
                        float aB = fmaf(w11, v11.y, fmaf(w10, v10.y, fmaf(w01, v01.y, w00 * v00.y)));
                        xv2 = wk2 * aF + (1.0f - wk2) * aB;
                    }
                }
            }
            xh[s * 104 + lane]      = __float2half(xv0);
            xh[s * 104 + 32 + lane] = __float2half(xv1);
            xh[s * 104 + 64 + lane] = __float2half(xv2);
        }
        __syncwarp();

        // ---- layer1: [16x96] @ [96x64], fp16 mma, n split in halves ----
#pragma unroll
        for (int hn = 0; hn < 2; hn++) {
            float d1[4][4];
#pragma unroll
            for (int nt2 = 0; nt2 < 4; nt2++) {
                int nt = hn * 4 + nt2;
                float bl = b1s[nt * 8 + 2 * tq], bh = b1s[nt * 8 + 2 * tq + 1];
                d1[nt2][0] = bl; d1[nt2][1] = bh; d1[nt2][2] = bl; d1[nt2][3] = bh;
            }
#pragma unroll
            for (int kt = 0; kt < 6; kt++) {
                uint32_t a0, a1, a2, a3;
                ldsm_x4(a0, a1, a2, a3, a_x + kt * 32);
#pragma unroll
                for (int nt2 = 0; nt2 < 4; nt2++) {
                    int nt = hn * 4 + nt2;
                    uint32_t bv0, bv1;
                    ldsm_x2(bv0, bv1, b_w1 + nt * 1664 + kt * 32);
                    mma_f16(d1[nt2][0], d1[nt2][1], d1[nt2][2], d1[nt2][3], a0, a1, a2, a3, bv0, bv1);
                }
            }
            int gq = lane >> 2;
#pragma unroll
            for (int nt2 = 0; nt2 < 4; nt2++) {
                int nt = hn * 4 + nt2;
                *(__half2*)(hh + gq * 72 + nt * 8 + 2 * tq) =
                    __floats2half2_rn(softplus_fast(d1[nt2][0]), softplus_fast(d1[nt2][1]));
                *(__half2*)(hh + (gq + 8) * 72 + nt * 8 + 2 * tq) =
                    __floats2half2_rn(softplus_fast(d1[nt2][2]), softplus_fast(d1[nt2][3]));
            }
        }
        __syncwarp();

        // ---- layer2: [16x64] @ [64x40] ----
        float d2[5][4];
#pragma unroll
        for (int nt = 0; nt < 5; nt++) {
            float bl = b2s[nt * 8 + 2 * tq], bh = b2s[nt * 8 + 2 * tq + 1];
            d2[nt][0] = bl; d2[nt][1] = bh; d2[nt][2] = bl; d2[nt][3] = bh;
        }
#pragma unroll
        for (int kt = 0; kt < 4; kt++) {
            uint32_t a0, a1, a2, a3;
            ldsm_x4(a0, a1, a2, a3, a_h + kt * 32);
#pragma unroll
            for (int nt = 0; nt < 5; nt++) {
                uint32_t bv0, bv1;
                ldsm_x2(bv0, bv1, b_w2 + nt * 1152 + kt * 32);
                mma_f16(d2[nt][0], d2[nt][1], d2[nt][2], d2[nt][3], a0, a1, a2, a3, bv0, bv1);
            }
        }
        __syncwarp();
        {
            int gq = lane >> 2;
#pragma unroll
            for (int nt = 0; nt < 5; nt++) {
                *(float2*)(outf + gq * 44 + nt * 8 + 2 * tq)       = make_float2(d2[nt][0], d2[nt][1]);
                *(float2*)(outf + (gq + 8) * 44 + nt * 8 + 2 * tq) = make_float2(d2[nt][2], d2[nt][3]);
            }
        }
        __syncwarp();

#pragma unroll 4
        for (int s = 0; s < 16; s++) {
            float v = outf[s * 44 + 1 + lane];
            cols[(size_t)(smp0 + s) * 32 + lane] = sigmoid_fast(v) * 1.002f - 0.001f;
        }
        if (lane < 16) sigs[smp0 + lane] = outf[lane * 44];
        __syncwarp();

        g = gnext;
    }
}

// ---------------- kernel 3: fused coarse weights + importance sampling, WARP PER RAY ----------------
#define KF_W 8
__global__ void __launch_bounds__(KF_W*32) k_fine() {
    __shared__ float zsh[KF_W][49];
    __shared__ float ssh[KF_W][49];
    __shared__ float wsh[KF_W][48];
    __shared__ float zmsh[KF_W][48];
    __shared__ float cdfsh[KF_W][47];
    __shared__ float bmn[KF_W], bmx[KF_W];
    if (blockIdx.x == 0 && threadIdx.x == 0) g_ctr1 = MODEL_WARPS;  // reset fine-pass counter
    int lane = threadIdx.x & 31, wrp = threadIdx.x >> 5;
    int ray = blockIdx.x * KF_W + wrp;
    float* z   = zsh[wrp];
    float* sg  = ssh[wrp];
    float* w   = wsh[wrp];
    float* zm  = zmsh[wrp];
    float* cdf = cdfsh[wrp];

    for (int i = lane; i < 48; i += 32) {
        z[i]  = g_depth_c[ray * 48 + i];
        sg[i] = g_sig_c[ray * 48 + i];
    }
    __syncwarp();

    float a0, t0, a1 = 0.0f, t1 = 1.0f;
    {
        int i = lane;
        float dens = softplusf(0.5f * (sg[i] + sg[i + 1]) - 1.0f);
        a0 = 1.0f - expf(-dens * (z[i + 1] - z[i]));
        t0 = 1.0f - a0 + 1e-10f;
        zm[i] = 0.5f * (z[i] + z[i + 1]);
    }
    if (lane < 15) {
        int i = 32 + lane;
        float dens = softplusf(0.5f * (sg[i] + sg[i + 1]) - 1.0f);
        a1 = 1.0f - expf(-dens * (z[i + 1] - z[i]));
        t1 = 1.0f - a1 + 1e-10f;
        zm[i] = 0.5f * (z[i] + z[i + 1]);
    }
    float p0 = t0;
#pragma unroll
    for (int off = 1; off < 32; off <<= 1) {
        float v = __shfl_up_sync(0xffffffffu, p0, off);
        if (lane >= off) p0 *= v;
    }
    float tot0 = __shfl_sync(0xffffffffu, p0, 31);
    float p0prev = __shfl_up_sync(0xffffffffu, p0, 1);
    float P0 = (lane == 0) ? 1.0f : p0prev;
    float p1 = t1;
#pragma unroll
    for (int off = 1; off < 32; off <<= 1) {
        float v = __shfl_up_sync(0xffffffffu, p1, off);
        if (lane >= off) p1 *= v;
    }
    float p1prev = __shfl_up_sync(0xffffffffu, p1, 1);
    float P1 = tot0 * ((lane == 0) ? 1.0f : p1prev);

    w[lane] = a0 * P0;
    if (lane < 15) w[32 + lane] = a1 * P1;
    __syncwarp();

    if (lane == 0) { bmn[wrp] = z[0]; bmx[wrp] = z[47]; }
    __syncthreads();
    if (threadIdx.x == 0) {
        float mn = bmn[0], mx = bmx[0];
#pragma unroll
        for (int i = 1; i < KF_W; i++) { mn = fminf(mn, bmn[i]); mx = fmaxf(mx, bmx[i]); }
        atomicMin(&g_dmin_bits, __float_as_int(mn));
        atomicMax(&g_dmax_bits, __float_as_int(mx));
    }

    float s0 = 0.0f, s1 = 0.0f;
    {
        int j = lane;
        if (j < 45)
            s0 = 0.5f * (fmaxf(w[j], w[j + 1]) + fmaxf(w[j + 1], w[j + 2])) + 0.01f + 1e-5f;
    }
    if (lane < 13) {
        int j = 32 + lane;
        s1 = 0.5f * (fmaxf(w[j], w[j + 1]) + fmaxf(w[j + 1], w[j + 2])) + 0.01f + 1e-5f;
    }
    float q0 = s0;
#pragma unroll
    for (int off = 1; off < 32; off <<= 1) {
        float v = __shfl_up_sync(0xffffffffu, q0, off);
        if (lane >= off) q0 += v;
    }
    float tot0s = __shfl_sync(0xffffffffu, q0, 31);
    float q1 = s1;
#pragma unroll
    for (int off = 1; off < 32; off <<= 1) {
        float v = __shfl_up_sync(0xffffffffu, q1, off);
        if (lane >= off) q1 += v;
    }
    float sum = tot0s + __shfl_sync(0xffffffffu, q1, 31);
    if (lane == 0) cdf[0] = 0.0f;
    if (lane < 45) cdf[lane + 1] = q0 / sum;
    if (lane < 13) cdf[33 + lane] = (tot0s + q1) / sum;
    __syncwarp();

    uint32_t ka, kb; derive_key(1u, ka, kb);
#pragma unroll
    for (int half = 0; half < 2; half++) {
        int j = half * 32 + lane;
        if (j < 48) {
            float u = tf_uniform(ka, kb, (uint32_t)(ray * 48 + j));
            int pos = 0;
#pragma unroll
            for (int step = 32; step; step >>= 1) {
                int np = pos + step;
                if (np <= 46 && cdf[np - 1] <= u) pos = np;
            }
            int ind = pos;
            int below = ind - 1; if (below < 0) below = 0;
            int above = ind;     if (above > 45) above = 45;
            float c0 = cdf[below], c1 = cdf[above];
            float b0 = zm[below],  b1v = zm[above];
            float denom = c1 - c0;
            if (denom < 1e-5f) denom = 1.0f;
            g_depth_f[ray * 48 + j] = b0 + (u - c0) / denom * (b1v - b0);
        }
    }
}

// ---------------- kernel 4: unify + final march, warp per ray ----------------
__global__ void __launch_bounds__(256) k_final(
    const float* __restrict__ ro, const float* __restrict__ rd,
    float* __restrict__ out)
{
    __shared__ __align__(16) float sd[8][96];
    __shared__ __align__(16) float ssg[8][96];
    __shared__ __align__(16) int   sidx[8][96];
    int lane = threadIdx.x & 31, wrp = threadIdx.x >> 5;
    int ray = blockIdx.x * 8 + wrp;

    for (int i = lane; i < 48; i += 32) {
        sd[wrp][i]       = g_depth_c[ray * 48 + i];
        sd[wrp][48 + i]  = g_depth_f[ray * 48 + i];
        ssg[wrp][i]      = g_sig_c[ray * 48 + i];
        ssg[wrp][48 + i] = g_sig_f[ray * 48 + i];
    }
    __syncwarp();
#pragma unroll
    for (int t = 0; t < 3; t++) {
        int e = lane + t * 32;
        float de = sd[wrp][e];
        int rank = 0;
        for (int j = 0; j < 96; j++) {
            float dj = sd[wrp][j];
            rank += (dj < de || (dj == de && j < e)) ? 1 : 0;
        }
        sidx[wrp][rank] = e;
    }
    __syncwarp();

    float T = 1.0f, accW = 0.0f, accWD = 0.0f, accC = 0.0f;
    int i0 = sidx[wrp][0];
    float dp = sd[wrp][i0], sp = ssg[wrp][i0];
    const float* cb0 = (i0 < 48) ? g_col_c : g_col_f;
    float cp = cb0[((size_t)ray * 48 + (i0 < 48 ? i0 : i0 - 48)) * 32 + lane];

    for (int s = 1; s < 96; s++) {
        int i = sidx[wrp][s];
        float dc = sd[wrp][i], sc = ssg[wrp][i];
        const float* cb = (i < 48) ? g_col_c : g_col_f;
        float cc = cb[((size_t)ray * 48 + (i < 48 ? i : i - 48)) * 32 + lane];
        float delta = dc - dp;
        float dens = softplus_fast(0.5f * (sc + sp) - 1.0f);
        float alpha = 1.0f - __expf(-dens * delta);
        float wgt = alpha * T;
        T *= (1.0f - alpha + 1e-10f);
        accC  += wgt * 0.5f * (cc + cp);
        accW  += wgt;
        accWD += wgt * 0.5f * (dc + dp);
        dp = dc; sp = sc; cp = cc;
    }

    out[OUT_RGB + (size_t)ray * 32 + lane] = accC * 2.0f - 1.0f;
    if (lane == 0) {
        float wt = accW;
        float dep = accWD / wt;
        if (isnan(dep)) dep = __int_as_float(0x7f800000);
        float dmin = __int_as_float(g_dmin_bits);
        float dmax = __int_as_float(g_dmax_bits);
        dep = fminf(fmaxf(dep, dmin), dmax);
        out[OUT_DEPTH + ray] = dep;
        out[OUT_WT + ray] = wt;
    }
    if (lane < 3) {
        float o_ = ro[ray * 3 + lane], d_ = rd[ray * 3 + lane];
        out[OUT_XYZ + (size_t)ray * 3 + lane] = 2.0f * (o_ * accW + d_ * accWD) - 1.0f;
    }
}

// ---------------- launcher ----------------
extern "C" void kernel_launch(void* const* d_in, const int* in_sizes, int n_in,
                              void* d_out, int out_size) {
    const float* front  = (const float*)d_in[0];
    const float* back   = (const float*)d_in[1];
    const float* ro     = (const float*)d_in[2];
    const float* rd     = (const float*)d_in[3];
    const float* weight = (const float*)d_in[4];
    const float* w1     = (const float*)d_in[5];
    const float* b1     = (const float*)d_in[6];
    const float* w2     = (const float*)d_in[7];
    const float* b2     = (const float*)d_in[8];
    float* out = (float*)d_out;

    cudaFuncSetAttribute(k_model, cudaFuncAttributeMaxDynamicSharedMemorySize, SM_TOTAL_BYTES);

    k_transpose<<<dim3(8, 256, 6), dim3(32, 8)>>>(front, back);
    k_model<<<MODEL_BLOCKS, 512, SM_TOTAL_BYTES>>>(ro, rd, weight, w1, b1, w2, b2, 0);
    k_fine<<<NRAY / KF_W, KF_W * 32>>>();
    k_model<<<MODEL_BLOCKS, 512, SM_TOTAL_BYTES>>>(ro, rd, weight, w1, b1, w2, b2, 1);
    k_final<<<NRAY / 8, 256>>>(ro, rd, out);
    (void)in_sizes; (void)n_in; (void)out_size;
}

// round 13
// speedup vs baseline: 5.0758x; 1.0631x over previous
#include <cuda_runtime.h>
#include <cuda_fp16.h>
#include <cstdint>
#include <math.h>

// ---------------- problem constants ----------------
#define Bb 2
#define Rr 4096
#define Ss 48
#define NRAY   (Bb*Rr)        // 8192
#define NSAMP  (NRAY*Ss)      // 393216
#define NG16   (NSAMP/16)     // 24576

#define RAY_START 2.25f
#define STEPF 0.0223404255319148936f  // (3.3-2.25)/47

#define OUT_RGB   0
#define OUT_DEPTH 262144
#define OUT_WT    270336
#define OUT_XYZ   278528

#define MODEL_BLOCKS 296
#define MODEL_WARPS  (MODEL_BLOCKS*16)   // 4736

// ---------------- scratch ----------------
__device__ __half g_planes_h[(size_t)Bb*3*256*256*64];
__device__ float g_depth_c[NSAMP];
__device__ float g_depth_f[NSAMP];
__device__ float g_col_c[(size_t)NSAMP*32];
__device__ float g_col_f[(size_t)NSAMP*32];
__device__ float g_sig_c[NSAMP];
__device__ float g_sig_f[NSAMP];
__device__ int   g_dmin_bits;
__device__ int   g_dmax_bits;
__device__ unsigned int g_ctr0;
__device__ unsigned int g_ctr1;

// ---------------- math helpers ----------------
__device__ __forceinline__ float softplusf(float x) {
    return fmaxf(x, 0.0f) + log1pf(expf(-fabsf(x)));
}
__device__ __forceinline__ float softplus_fast(float x) {
    return fmaxf(x, 0.0f) + __logf(1.0f + __expf(-fabsf(x)));
}
__device__ __forceinline__ float sigmoid_fast(float x) {
    return __fdividef(1.0f, 1.0f + __expf(-x));
}

__device__ __forceinline__ uint32_t smaddr(const void* p) {
    return (uint32_t)__cvta_generic_to_shared(p);
}
__device__ __forceinline__ void ldsm_x4(uint32_t& r0, uint32_t& r1, uint32_t& r2, uint32_t& r3, uint32_t a) {
    asm volatile("ldmatrix.sync.aligned.m8n8.x4.shared.b16 {%0,%1,%2,%3}, [%4];"
                 : "=r"(r0), "=r"(r1), "=r"(r2), "=r"(r3) : "r"(a));
}
__device__ __forceinline__ void ldsm_x2(uint32_t& r0, uint32_t& r1, uint32_t a) {
    asm volatile("ldmatrix.sync.aligned.m8n8.x2.shared.b16 {%0,%1}, [%2];"
                 : "=r"(r0), "=r"(r1) : "r"(a));
}
__device__ __forceinline__ void mma_f16(float& d0, float& d1, float& d2, float& d3,
                                        uint32_t a0, uint32_t a1, uint32_t a2, uint32_t a3,
                                        uint32_t b0, uint32_t b1) {
    asm volatile(
        "mma.sync.aligned.m16n8k16.row.col.f32.f16.f16.f32 "
        "{%0,%1,%2,%3}, {%4,%5,%6,%7}, {%8,%9}, {%0,%1,%2,%3};"
        : "+f"(d0), "+f"(d1), "+f"(d2), "+f"(d3)
        : "r"(a0), "r"(a1), "r"(a2), "r"(a3), "r"(b0), "r"(b1));
}

// ---------------- Threefry-2x32 (JAX, partitionable variant) ----------------
__device__ __forceinline__ uint32_t rotl32(uint32_t x, int r) {
    return (x << r) | (x >> (32 - r));
}
__device__ __forceinline__ void tf2x32(uint32_t k0, uint32_t k1,
                                       uint32_t x0, uint32_t x1,
                                       uint32_t& o0, uint32_t& o1) {
    uint32_t ks2 = k0 ^ k1 ^ 0x1BD11BDAu;
    x0 += k0; x1 += k1;
#define TFR(r) { x0 += x1; x1 = rotl32(x1, r); x1 ^= x0; }
    TFR(13) TFR(15) TFR(26) TFR(6)  x0 += k1;  x1 += ks2 + 1u;
    TFR(17) TFR(29) TFR(16) TFR(24) x0 += ks2; x1 += k0 + 2u;
    TFR(13) TFR(15) TFR(26) TFR(6)  x0 += k0;  x1 += k1 + 3u;
    TFR(17) TFR(29) TFR(16) TFR(24) x0 += k1;  x1 += ks2 + 4u;
    TFR(13) TFR(15) TFR(26) TFR(6)  x0 += ks2; x1 += k0 + 5u;
#undef TFR
    o0 = x0; o1 = x1;
}
__device__ __forceinline__ void derive_key(uint32_t idx, uint32_t& ka, uint32_t& kb) {
    tf2x32(0u, 42u, 0u, idx, ka, kb);
}
__device__ __forceinline__ float tf_uniform(uint32_t ka, uint32_t kb, uint32_t i) {
    uint32_t o0, o1;
    tf2x32(ka, kb, 0u, i, o0, o1);
    uint32_t bits = o0 ^ o1;
    float f = __uint_as_float((bits >> 9) | 0x3f800000u) - 1.0f;
    return fmaxf(f, 0.0f);
}

// ---------------- kernel 1: transpose planes to channel-last fp16 (+ init scalars) ----------------
__global__ void k_transpose(const float* __restrict__ front, const float* __restrict__ back) {
    __shared__ float tf[32][33];
    __shared__ float tb[32][33];
    if (blockIdx.x == 0 && blockIdx.y == 0 && blockIdx.z == 0 &&
        threadIdx.x == 0 && threadIdx.y == 0) {
        g_dmin_bits = 0x7f800000;
        g_dmax_bits = 0x00000000;
        g_ctr0 = MODEL_WARPS;
    }
    int bp = blockIdx.z;
    int y  = blockIdx.y;
    int x0 = blockIdx.x * 32;
    int tx = threadIdx.x, ty = threadIdx.y;
    __half2* out = (__half2*)g_planes_h;
#pragma unroll
    for (int i = 0; i < 4; i++) {
        int c = ty + i * 8;
        size_t src = ((size_t)(bp * 32 + c) * 65536) + (size_t)y * 256 + x0 + tx;
        tf[c][tx] = front[src];
        tb[c][tx] = back[src];
    }
    __syncthreads();
#pragma unroll
    for (int i = 0; i < 4; i++) {
        int xx = ty + i * 8;
        out[(((size_t)bp * 65536) + (size_t)y * 256 + x0 + xx) * 32 + tx] =
            __floats2half2_rn(tf[tx][xx], tb[tx][xx]);
    }
}

// ---------------- kernel 2: model, warp per 16-sample group, fp16 mma MLP ----------------
#define SM_W1H  0
#define SM_W2H  3328
#define SM_B1   4768
#define SM_B2   4832
#define SM_WSIG 4872
#define SM_XB   4968
#define SM_HB   18280
#define SM_TOTAL_BYTES (27496*4)

extern __shared__ __align__(16) float smem[];

struct Axis { float w0, w1; int i0, i1; bool ok; };
__device__ __forceinline__ Axis axis_prep(float g) {
    Axis a;
    float x = (g + 1.0f) * 128.0f - 0.5f;
    float x0f = floorf(x);
    int x0 = (int)x0f;
    float w = x - x0f;
    bool v0 = (x0 >= 0) & (x0 < 256);
    bool v1 = (x0 >= -1) & (x0 < 255);
    a.w0 = v0 ? 1.0f - w : 0.0f;
    a.w1 = v1 ? w : 0.0f;
    a.i0 = min(max(x0, 0), 255);
    a.i1 = min(max(x0 + 1, 0), 255);
    a.ok = (x0 >= -1) & (x0 <= 255);
    return a;
}

__global__ void __launch_bounds__(512, 2) k_model(
    const float* __restrict__ ro, const float* __restrict__ rd,
    const float* __restrict__ weight,
    const float* __restrict__ w1, const float* __restrict__ b1,
    const float* __restrict__ w2, const float* __restrict__ b2,
    int fine_pass)
{
    __half* w1h = (__half*)(smem + SM_W1H);
    __half* w2h = (__half*)(smem + SM_W2H);
    float* b1s  = smem + SM_B1;
    float* b2s  = smem + SM_B2;
    float* wsig = smem + SM_WSIG;

    int tid = threadIdx.x;
    for (int i = tid; i < 96 * 64; i += 512) {
        int k = i >> 6, n = i & 63;
        w1h[n * 104 + k] = __float2half(w1[i]);
    }
    for (int i = tid; i < 64 * 40; i += 512) {
        int k = i / 40, n = i % 40;
        w2h[n * 72 + k] = (n < 33) ? __float2half(w2[k * 33 + n]) : __half(0.0f);
    }
    if (tid < 64) b1s[tid] = b1[tid];
    if (tid < 40) b2s[tid] = (tid < 33) ? b2[tid] : 0.0f;
    if (tid < 96) wsig[tid] = 1.0f / (1.0f + expf(-weight[tid]));
    __syncthreads();

    float* cols = fine_pass ? g_col_f : g_col_c;
    float* sigs = fine_pass ? g_sig_f : g_sig_c;
    unsigned int* ctr = fine_pass ? &g_ctr1 : &g_ctr0;

    int lane = tid & 31, wrp = tid >> 5;
    int tq = lane & 3;
    __half* xh = (__half*)(smem + SM_XB) + wrp * 1664;   // [16][104]
    __half* hh = (__half*)(smem + SM_HB) + wrp * 1152;   // [16][72]
    float*  outf = (float*)xh;                           // reuse as [16][44] float

    uint32_t a_x = smaddr(xh) + (((lane & 15) * 104 + ((lane >> 4) * 8)) * 2);
    uint32_t a_h = smaddr(hh) + (((lane & 15) * 72  + ((lane >> 4) * 8)) * 2);
    uint32_t b_w1 = smaddr(w1h) + (((lane & 7) * 104 + (((lane >> 3) & 1) * 8)) * 2);
    uint32_t b_w2 = smaddr(w2h) + (((lane & 7) * 72  + (((lane >> 3) & 1) * 8)) * 2);

    float wk0 = wsig[lane], wk1 = wsig[32 + lane], wk2 = wsig[64 + lane];

    uint32_t ka0, kb0; derive_key(0u, ka0, kb0);

    int g = blockIdx.x * 16 + wrp;

    while (g < NG16) {
        int smp0 = g * 16;
        int ray = g / 3;
        int b = ray >> 12;
        float ox = 2.0f * ro[ray * 3 + 0], oy = 2.0f * ro[ray * 3 + 1], oz = 2.0f * ro[ray * 3 + 2];
        float dx = 2.0f * rd[ray * 3 + 0], dy = 2.0f * rd[ray * 3 + 1], dz = 2.0f * rd[ray * 3 + 2];
        const __half2* pb0 = (const __half2*)g_planes_h + (size_t)b * 3 * 65536 * 32 + (size_t)lane;
        const __half2* pb1 = pb0 + (size_t)65536 * 32;
        const __half2* pb2 = pb1 + (size_t)65536 * 32;

        int sidx = smp0 + (lane & 15);
        float dval;
        if (!fine_pass) {
            int sloc = (g % 3) * 16 + (lane & 15);
            float u = tf_uniform(ka0, kb0, (uint32_t)sidx);
            float d0 = RAY_START + (float)sloc * STEPF;
            dval = d0 + u * STEPF;
            if (lane < 16) g_depth_c[sidx] = dval;
        } else {
            dval = g_depth_f[sidx];
        }

        int gnext;
        if (lane == 0) gnext = (int)atomicAdd(ctr, 1u);
        gnext = __shfl_sync(0xffffffffu, gnext, 0);

        // ---- phase A: gather 16 samples, lane = channel; OOB skips (warp-uniform) ----
#pragma unroll 4
        for (int s = 0; s < 16; s++) {
            float d = __shfl_sync(0xffffffffu, dval, s);
            float cx = fmaf(d, dx, ox);
            float cy = fmaf(d, dy, oy);
            float cz = fmaf(d, dz, oz);
            float xv0 = 0.0f, xv1 = 0.0f, xv2 = 0.0f;
            Axis ax = axis_prep(cx);
            if (ax.ok) {
                Axis ay = axis_prep(cy);
                Axis az = axis_prep(cz);
                if (ay.ok) {   // plane 0: (ax, ay)
                    float2 v00 = __half22float2(pb0[(ay.i0 * 256 + ax.i0) * 32]);
                    float2 v01 = __half22float2(pb0[(ay.i0 * 256 + ax.i1) * 32]);
                    float2 v10 = __half22float2(pb0[(ay.i1 * 256 + ax.i0) * 32]);
                    float2 v11 = __half22float2(pb0[(ay.i1 * 256 + ax.i1) * 32]);
                    float w00 = ax.w0 * ay.w0, w01 = ax.w1 * ay.w0;
                    float w10 = ax.w0 * ay.w1, w11 = ax.w1 * ay.w1;
                    float aF = fmaf(w11, v11.x, fmaf(w10, v10.x, fmaf(w01, v01.x, w00 * v00.x)));
                    float aB = fmaf(w11, v11.y, fmaf(w10, v10.y, fmaf(w01, v01.y, w00 * v00.y)));
                    xv0 = wk0 * aF + (1.0f - wk0) * aB;
                }
                if (az.ok) {
                    {   // plane 1: (ax, az)
                        float2 v00 = __half22float2(pb1[(az.i0 * 256 + ax.i0) * 32]);
                        float2 v01 = __half22float2(pb1[(az.i0 * 256 + ax.i1) * 32]);
                        float2 v10 = __half22float2(pb1[(az.i1 * 256 + ax.i0) * 32]);
                        float2 v11 = __half22float2(pb1[(az.i1 * 256 + ax.i1) * 32]);
                        float w00 = ax.w0 * az.w0, w01 = ax.w1 * az.w0;
                        float w10 = ax.w0 * az.w1, w11 = ax.w1 * az.w1;
                        float aF = fmaf(w11, v11.x, fmaf(w10, v10.x, fmaf(w01, v01.x, w00 * v00.x)));
                        float aB = fmaf(w11, v11.y, fmaf(w10, v10.y, fmaf(w01, v01.y, w00 * v00.y)));
                        xv1 = wk1 * aF + (1.0f - wk1) * aB;
                    }
                    {   // plane 2: (az, ax)
                        float2 v00 = __half22float2(pb2[(ax.i0 * 256 + az.i0) * 32]);
                        float2 v01 = __half22float2(pb2[(ax.i0 * 256 + az.i1) * 32]);
                        float2 v10 = __half22float2(pb2[(ax.i1 * 256 + az.i0) * 32]);
                        float2 v11 = __half22float2(pb2[(ax.i1 * 256 + az.i1) * 32]);
                        float w00 = az.w0 * ax.w0, w01 = az.w1 * ax.w0;
                        float w10 = az.w0 * ax.w1, w11 = az.w1 * ax.w1;
                        float aF = fmaf(w11, v11.x, fmaf(w10, v10.x, fmaf(w01, v01.x, w00 * v00.x)));
                        float aB = fmaf(w11, v11.y, fmaf(w10, v10.y, fmaf(w01, v01.y, w00 * v00.y)));
                        xv2 = wk2 * aF + (1.0f - wk2) * aB;
                    }
                }
            }
            xh[s * 104 + lane]      = __float2half(xv0);
            xh[s * 104 + 32 + lane] = __float2half(xv1);
            xh[s * 104 + 64 + lane] = __float2half(xv2);
        }
        __syncwarp();

        // ---- layer1: [16x96] @ [96x64], fp16 mma, n split in halves ----
#pragma unroll
        for (int hn = 0; hn < 2; hn++) {
            float d1[4][4];
#pragma unroll
            for (int nt2 = 0; nt2 < 4; nt2++) {
                int nt = hn * 4 + nt2;
                float bl = b1s[nt * 8 + 2 * tq], bh = b1s[nt * 8 + 2 * tq + 1];
                d1[nt2][0] = bl; d1[nt2][1] = bh; d1[nt2][2] = bl; d1[nt2][3] = bh;
            }
#pragma unroll
            for (int kt = 0; kt < 6; kt++) {
                uint32_t a0, a1, a2, a3;
                ldsm_x4(a0, a1, a2, a3, a_x + kt * 32);
#pragma unroll
                for (int nt2 = 0; nt2 < 4; nt2++) {
                    int nt = hn * 4 + nt2;
                    uint32_t bv0, bv1;
                    ldsm_x2(bv0, bv1, b_w1 + nt * 1664 + kt * 32);
                    mma_f16(d1[nt2][0], d1[nt2][1], d1[nt2][2], d1[nt2][3], a0, a1, a2, a3, bv0, bv1);
                }
            }
            int gq = lane >> 2;
#pragma unroll
            for (int nt2 = 0; nt2 < 4; nt2++) {
                int nt = hn * 4 + nt2;
                *(__half2*)(hh + gq * 72 + nt * 8 + 2 * tq) =
                    __floats2half2_rn(softplus_fast(d1[nt2][0]), softplus_fast(d1[nt2][1]));
                *(__half2*)(hh + (gq + 8) * 72 + nt * 8 + 2 * tq) =
                    __floats2half2_rn(softplus_fast(d1[nt2][2]), softplus_fast(d1[nt2][3]));
            }
        }
        __syncwarp();

        // ---- layer2: [16x64] @ [64x40] ----
        float d2[5][4];
#pragma unroll
        for (int nt = 0; nt < 5; nt++) {
            float bl = b2s[nt * 8 + 2 * tq], bh = b2s[nt * 8 + 2 * tq + 1];
            d2[nt][0] = bl; d2[nt][1] = bh; d2[nt][2] = bl; d2[nt][3] = bh;
        }
#pragma unroll
        for (int kt = 0; kt < 4; kt++) {
            uint32_t a0, a1, a2, a3;
            ldsm_x4(a0, a1, a2, a3, a_h + kt * 32);
#pragma unroll
            for (int nt = 0; nt < 5; nt++) {
                uint32_t bv0, bv1;
                ldsm_x2(bv0, bv1, b_w2 + nt * 1152 + kt * 32);
                mma_f16(d2[nt][0], d2[nt][1], d2[nt][2], d2[nt][3], a0, a1, a2, a3, bv0, bv1);
            }
        }
        __syncwarp();
        {
            int gq = lane >> 2;
#pragma unroll
            for (int nt = 0; nt < 5; nt++) {
                *(float2*)(outf + gq * 44 + nt * 8 + 2 * tq)       = make_float2(d2[nt][0], d2[nt][1]);
                *(float2*)(outf + (gq + 8) * 44 + nt * 8 + 2 * tq) = make_float2(d2[nt][2], d2[nt][3]);
            }
        }
        __syncwarp();

#pragma unroll 4
        for (int s = 0; s < 16; s++) {
            float v = outf[s * 44 + 1 + lane];
            cols[(size_t)(smp0 + s) * 32 + lane] = sigmoid_fast(v) * 1.002f - 0.001f;
        }
        if (lane < 16) sigs[smp0 + lane] = outf[lane * 44];
        __syncwarp();

        g = gnext;
    }
}

// ---------------- kernel 3: fused coarse weights + importance sampling, warp per ray ----------------
#define KF_W 8
__global__ void __launch_bounds__(KF_W*32) k_fine() {
    __shared__ float zsh[KF_W][49];
    __shared__ float ssh[KF_W][49];
    __shared__ float wsh[KF_W][48];
    __shared__ float zmsh[KF_W][48];
    __shared__ float cdfsh[KF_W][47];
    __shared__ float bmn[KF_W], bmx[KF_W];
    if (blockIdx.x == 0 && threadIdx.x == 0) g_ctr1 = MODEL_WARPS;
    int lane = threadIdx.x & 31, wrp = threadIdx.x >> 5;
    int ray = blockIdx.x * KF_W + wrp;
    float* z   = zsh[wrp];
    float* sg  = ssh[wrp];
    float* w   = wsh[wrp];
    float* zm  = zmsh[wrp];
    float* cdf = cdfsh[wrp];

    for (int i = lane; i < 48; i += 32) {
        z[i]  = g_depth_c[ray * 48 + i];
        sg[i] = g_sig_c[ray * 48 + i];
    }
    __syncwarp();

    float a0, t0, a1 = 0.0f, t1 = 1.0f;
    {
        int i = lane;
        float dens = softplusf(0.5f * (sg[i] + sg[i + 1]) - 1.0f);
        a0 = 1.0f - expf(-dens * (z[i + 1] - z[i]));
        t0 = 1.0f - a0 + 1e-10f;
        zm[i] = 0.5f * (z[i] + z[i + 1]);
    }
    if (lane < 15) {
        int i = 32 + lane;
        float dens = softplusf(0.5f * (sg[i] + sg[i + 1]) - 1.0f);
        a1 = 1.0f - expf(-dens * (z[i + 1] - z[i]));
        t1 = 1.0f - a1 + 1e-10f;
        zm[i] = 0.5f * (z[i] + z[i + 1]);
    }
    float p0 = t0;
#pragma unroll
    for (int off = 1; off < 32; off <<= 1) {
        float v = __shfl_up_sync(0xffffffffu, p0, off);
        if (lane >= off) p0 *= v;
    }
    float tot0 = __shfl_sync(0xffffffffu, p0, 31);
    float p0prev = __shfl_up_sync(0xffffffffu, p0, 1);
    float P0 = (lane == 0) ? 1.0f : p0prev;
    float p1 = t1;
#pragma unroll
    for (int off = 1; off < 32; off <<= 1) {
        float v = __shfl_up_sync(0xffffffffu, p1, off);
        if (lane >= off) p1 *= v;
    }
    float p1prev = __shfl_up_sync(0xffffffffu, p1, 1);
    float P1 = tot0 * ((lane == 0) ? 1.0f : p1prev);

    w[lane] = a0 * P0;
    if (lane < 15) w[32 + lane] = a1 * P1;
    __syncwarp();

    if (lane == 0) { bmn[wrp] = z[0]; bmx[wrp] = z[47]; }
    __syncthreads();
    if (threadIdx.x == 0) {
        float mn = bmn[0], mx = bmx[0];
#pragma unroll
        for (int i = 1; i < KF_W; i++) { mn = fminf(mn, bmn[i]); mx = fmaxf(mx, bmx[i]); }
        atomicMin(&g_dmin_bits, __float_as_int(mn));
        atomicMax(&g_dmax_bits, __float_as_int(mx));
    }

    float s0 = 0.0f, s1 = 0.0f;
    {
        int j = lane;
        if (j < 45)
            s0 = 0.5f * (fmaxf(w[j], w[j + 1]) + fmaxf(w[j + 1], w[j + 2])) + 0.01f + 1e-5f;
    }
    if (lane < 13) {
        int j = 32 + lane;
        s1 = 0.5f * (fmaxf(w[j], w[j + 1]) + fmaxf(w[j + 1], w[j + 2])) + 0.01f + 1e-5f;
    }
    float q0 = s0;
#pragma unroll
    for (int off = 1; off < 32; off <<= 1) {
        float v = __shfl_up_sync(0xffffffffu, q0, off);
        if (lane >= off) q0 += v;
    }
    float tot0s = __shfl_sync(0xffffffffu, q0, 31);
    float q1 = s1;
#pragma unroll
    for (int off = 1; off < 32; off <<= 1) {
        float v = __shfl_up_sync(0xffffffffu, q1, off);
        if (lane >= off) q1 += v;
    }
    float sum = tot0s + __shfl_sync(0xffffffffu, q1, 31);
    if (lane == 0) cdf[0] = 0.0f;
    if (lane < 45) cdf[lane + 1] = q0 / sum;
    if (lane < 13) cdf[33 + lane] = (tot0s + q1) / sum;
    __syncwarp();

    uint32_t ka, kb; derive_key(1u, ka, kb);
#pragma unroll
    for (int half = 0; half < 2; half++) {
        int j = half * 32 + lane;
        if (j < 48) {
            float u = tf_uniform(ka, kb, (uint32_t)(ray * 48 + j));
            int pos = 0;
#pragma unroll
            for (int step = 32; step; step >>= 1) {
                int np = pos + step;
                if (np <= 46 && cdf[np - 1] <= u) pos = np;
            }
            int ind = pos;
            int below = ind - 1; if (below < 0) below = 0;
            int above = ind;     if (above > 45) above = 45;
            float c0 = cdf[below], c1 = cdf[above];
            float b0 = zm[below],  b1v = zm[above];
            float denom = c1 - c0;
            if (denom < 1e-5f) denom = 1.0f;
            g_depth_f[ray * 48 + j] = b0 + (u - c0) / denom * (b1v - b0);
        }
    }
}

// ---------------- kernel 4: unify + final march, warp per ray, PARALLEL (scan) ----------------
#define KL_W 8
__global__ void __launch_bounds__(KL_W*32) k_final(
    const float* __restrict__ ro, const float* __restrict__ rd,
    float* __restrict__ out)
{
    __shared__ __align__(16) float sd[KL_W][96];
    __shared__ __align__(16) float ssg[KL_W][96];
    __shared__ __align__(16) float wbuf[KL_W][96];
    __shared__ __align__(16) int   sidx[KL_W][96];
    int lane = threadIdx.x & 31, wrp = threadIdx.x >> 5;
    int ray = blockIdx.x * KL_W + wrp;

    for (int i = lane; i < 48; i += 32) {
        sd[wrp][i]       = g_depth_c[ray * 48 + i];
        sd[wrp][48 + i]  = g_depth_f[ray * 48 + i];
        ssg[wrp][i]      = g_sig_c[ray * 48 + i];
        ssg[wrp][48 + i] = g_sig_f[ray * 48 + i];
    }
    __syncwarp();
    // stable rank sort
#pragma unroll
    for (int t = 0; t < 3; t++) {
        int e = lane + t * 32;
        float de = sd[wrp][e];
        int rank = 0;
        for (int j = 0; j < 96; j++) {
            float dj = sd[wrp][j];
            rank += (dj < de || (dj == de && j < e)) ? 1 : 0;
        }
        sidx[wrp][rank] = e;
    }
    __syncwarp();

    // ---- phase 1: 95 intervals, 3 per lane; weights via product scans ----
    float av[3], tv[3], dm[3];
#pragma unroll
    for (int c = 0; c < 3; c++) {
        int k = c * 32 + lane;
        av[c] = 0.0f; tv[c] = 1.0f; dm[c] = 0.0f;
        if (k < 95) {
            int i0 = sidx[wrp][k], i1 = sidx[wrp][k + 1];
            float d0 = sd[wrp][i0], d1 = sd[wrp][i1];
            float s0 = ssg[wrp][i0], s1 = ssg[wrp][i1];
            float dens = softplus_fast(0.5f * (s0 + s1) - 1.0f);
            float alpha = 1.0f - __expf(-dens * (d1 - d0));
            av[c] = alpha;
            tv[c] = 1.0f - alpha + 1e-10f;
            dm[c] = 0.5f * (d0 + d1);
        }
    }
    float carry = 1.0f;
    float accW = 0.0f, accWD = 0.0f;
#pragma unroll
    for (int c = 0; c < 3; c++) {
        float p = tv[c];
#pragma unroll
        for (int off = 1; off < 32; off <<= 1) {
            float v = __shfl_up_sync(0xffffffffu, p, off);
            if (lane >= off) p *= v;
        }
        float pprev = __shfl_up_sync(0xffffffffu, p, 1);
        float P = carry * ((lane == 0) ? 1.0f : pprev);
        float wk = av[c] * P;
        int k = c * 32 + lane;
        wbuf[wrp][k] = (k < 95) ? wk : 0.0f;
        if (k < 95) { accW += wk; accWD += wk * dm[c]; }
        carry *= __shfl_sync(0xffffffffu, p, 31);
    }
    if (lane == 31) wbuf[wrp][95] = 0.0f;  // padding (k=95 slot)
    // warp reductions
#pragma unroll
    for (int off = 16; off; off >>= 1) {
        accW  += __shfl_xor_sync(0xffffffffu, accW, off);
        accWD += __shfl_xor_sync(0xffffffffu, accWD, off);
    }
    __syncwarp();

    // ---- phase 2: color composite, lane = channel, independent loads ----
    const float* colc = g_col_c + (size_t)ray * 48 * 32 + lane;
    const float* colf = g_col_f + (size_t)ray * 48 * 32 + lane;
    float accC = 0.0f;
#pragma unroll 8
    for (int j = 0; j < 96; j++) {
        float wj  = (j < 95) ? wbuf[wrp][j] : 0.0f;
        float wjm = (j > 0)  ? wbuf[wrp][j - 1] : 0.0f;
        float coef = 0.5f * (wj + wjm);
        int i = sidx[wrp][j];
        const float* cb = (i < 48) ? colc : colf;
        float cc = cb[(size_t)(i < 48 ? i : i - 48) * 32];
        accC = fmaf(coef, cc, accC);
    }

    out[OUT_RGB + (size_t)ray * 32 + lane] = accC * 2.0f - 1.0f;
    if (lane == 0) {
        float wt = accW;
        float dep = accWD / wt;
        if (isnan(dep)) dep = __int_as_float(0x7f800000);
        float dmin = __int_as_float(g_dmin_bits);
        float dmax = __int_as_float(g_dmax_bits);
        dep = fminf(fmaxf(dep, dmin), dmax);
        out[OUT_DEPTH + ray] = dep;
        out[OUT_WT + ray] = wt;
    }
    if (lane < 3) {
        float o_ = ro[ray * 3 + lane], d_ = rd[ray * 3 + lane];
        out[OUT_XYZ + (size_t)ray * 3 + lane] = 2.0f * (o_ * accW + d_ * accWD) - 1.0f;
    }
}

// ---------------- launcher ----------------
extern "C" void kernel_launch(void* const* d_in, const int* in_sizes, int n_in,
                              void* d_out, int out_size) {
    const float* front  = (const float*)d_in[0];
    const float* back   = (const float*)d_in[1];
    const float* ro     = (const float*)d_in[2];
    const float* rd     = (const float*)d_in[3];
    const float* weight = (const float*)d_in[4];
    const float* w1     = (const float*)d_in[5];
    const float* b1     = (const float*)d_in[6];
    const float* w2     = (const float*)d_in[7];
    const float* b2     = (const float*)d_in[8];
    float* out = (float*)d_out;

    cudaFuncSetAttribute(k_model, cudaFuncAttributeMaxDynamicSharedMemorySize, SM_TOTAL_BYTES);

    k_transpose<<<dim3(8, 256, 6), dim3(32, 8)>>>(front, back);
    k_model<<<MODEL_BLOCKS, 512, SM_TOTAL_BYTES>>>(ro, rd, weight, w1, b1, w2, b2, 0);
    k_fine<<<NRAY / KF_W, KF_W * 32>>>();
    k_model<<<MODEL_BLOCKS, 512, SM_TOTAL_BYTES>>>(ro, rd, weight, w1, b1, w2, b2, 1);
    k_final<<<NRAY / KL_W, KL_W * 32>>>(ro, rd, out);
    (void)in_sizes; (void)n_in; (void)out_size;
}